// round 1
// baseline (speedup 1.0000x reference)
#include <cuda_runtime.h>
#include <math.h>

#define S_DIM 1024
#define N_DIM 512
#define CM 64
#define CC 8
#define CZ 128
#define HH 8
#define HIDDEN 256
#define NROWS (S_DIM*N_DIM)        // 524288
#define PDIM (S_DIM*CC)            // 8192

// ---- scratch (device globals: allocation-free rule) ----
__device__ float g_G [(size_t)NROWS*CM];                 // gate, [s][i][hc]    128MB
__device__ float g_Vt[(size_t)HH*N_DIM*S_DIM*CC];        // v^T,  [h][j][s][c]  128MB
__device__ float g_WV[(size_t)HH*N_DIM*S_DIM*CC];        // wv,   [h][i][s][c]  128MB
__device__ float g_Wsm[(size_t)HH*N_DIM*N_DIM];          // softmax w [h][i][j]   8MB

// ============================================================
// K1: LN(m) -> v (transposed) and g (sigmoid). 4 rows per 64-thread group.
// ============================================================
__global__ void __launch_bounds__(256) k1_ln_vg(
    const float* __restrict__ m, const float* __restrict__ lng, const float* __restrict__ lnb,
    const float* __restrict__ Wmv, const float* __restrict__ Wmg)
{
    __shared__ float sWv[CM*CM];
    __shared__ float sWg[CM*CM];
    __shared__ float smn[16][CM];
    __shared__ float2 sred[8][4];
    int tid = threadIdx.x;
    for (int idx = tid; idx < CM*CM; idx += 256) { sWv[idx] = Wmv[idx]; sWg[idx] = Wmg[idx]; }
    int grp = tid >> 6, ln = tid & 63, warp = tid >> 5;
    float gg = lng[ln], bb = lnb[ln];
    __syncthreads();

    for (int r0 = blockIdx.x*16; r0 < NROWS; r0 += gridDim.x*16) {
        int rbase = r0 + grp*4;
        float x[4]; float2 p[4];
        #pragma unroll
        for (int rr = 0; rr < 4; rr++) {
            x[rr] = m[(size_t)(rbase+rr)*CM + ln];
            float s = x[rr], q = x[rr]*x[rr];
            #pragma unroll
            for (int o = 16; o > 0; o >>= 1) {
                s += __shfl_xor_sync(0xffffffffu, s, o);
                q += __shfl_xor_sync(0xffffffffu, q, o);
            }
            p[rr] = make_float2(s, q);
        }
        if ((tid & 31) == 0) {
            #pragma unroll
            for (int rr = 0; rr < 4; rr++) sred[warp][rr] = p[rr];
        }
        __syncthreads();
        #pragma unroll
        for (int rr = 0; rr < 4; rr++) {
            float2 pa = sred[grp*2][rr], pb = sred[grp*2+1][rr];
            float mean = (pa.x+pb.x) * (1.0f/64.0f);
            float var  = (pa.y+pb.y) * (1.0f/64.0f) - mean*mean;
            float rs = rsqrtf(var + 1e-5f);
            smn[grp*4+rr][ln] = (x[rr]-mean)*rs*gg + bb;
        }
        __syncthreads();

        float av[4] = {0,0,0,0}, ag[4] = {0,0,0,0};
        #pragma unroll 4
        for (int k = 0; k < 64; k += 4) {
            float wv0 = sWv[(k+0)*64+ln], wv1 = sWv[(k+1)*64+ln];
            float wv2 = sWv[(k+2)*64+ln], wv3 = sWv[(k+3)*64+ln];
            float wg0 = sWg[(k+0)*64+ln], wg1 = sWg[(k+1)*64+ln];
            float wg2 = sWg[(k+2)*64+ln], wg3 = sWg[(k+3)*64+ln];
            #pragma unroll
            for (int rr = 0; rr < 4; rr++) {
                float4 mn4 = *(const float4*)&smn[grp*4+rr][k];
                av[rr] += mn4.x*wv0 + mn4.y*wv1 + mn4.z*wv2 + mn4.w*wv3;
                ag[rr] += mn4.x*wg0 + mn4.y*wg1 + mn4.z*wg2 + mn4.w*wg3;
            }
        }
        #pragma unroll
        for (int rr = 0; rr < 4; rr++) {
            int r = rbase + rr;
            int ss = r >> 9, ii = r & 511;
            float gval = __fdividef(1.0f, 1.0f + __expf(-ag[rr]));
            g_G[(size_t)r*64 + ln] = gval;
            g_Vt[(((size_t)(ln>>3)*N_DIM + ii)*S_DIM + ss)*CC + (ln&7)] = av[rr];
        }
        __syncthreads();
    }
}

// ============================================================
// K2a: bias[h][i][j] = LN(z[i,j,:]) @ W_z   (one warp per (i,j))
// ============================================================
__global__ void __launch_bounds__(256) k2a_bias(
    const float* __restrict__ z, const float* __restrict__ lng, const float* __restrict__ lnb,
    const float* __restrict__ Wz)
{
    int w = (blockIdx.x * 256 + threadIdx.x) >> 5;
    int lane = threadIdx.x & 31;
    if (w >= N_DIM*N_DIM) return;
    int i = w >> 9, j = w & 511;
    const float* zp = z + ((size_t)i*N_DIM + j)*CZ;
    float x0 = zp[lane], x1 = zp[lane+32], x2 = zp[lane+64], x3 = zp[lane+96];
    float s = x0+x1+x2+x3;
    float q = x0*x0 + x1*x1 + x2*x2 + x3*x3;
    #pragma unroll
    for (int o = 16; o > 0; o >>= 1) {
        s += __shfl_xor_sync(0xffffffffu, s, o);
        q += __shfl_xor_sync(0xffffffffu, q, o);
    }
    float mean = s * (1.0f/128.0f);
    float var  = q * (1.0f/128.0f) - mean*mean;
    float rs = rsqrtf(var + 1e-5f);
    float n0 = (x0-mean)*rs*lng[lane]    + lnb[lane];
    float n1 = (x1-mean)*rs*lng[lane+32] + lnb[lane+32];
    float n2 = (x2-mean)*rs*lng[lane+64] + lnb[lane+64];
    float n3 = (x3-mean)*rs*lng[lane+96] + lnb[lane+96];
    float ph[8];
    #pragma unroll
    for (int h = 0; h < 8; h++) {
        float pp = n0*Wz[lane*8+h] + n1*Wz[(lane+32)*8+h]
                 + n2*Wz[(lane+64)*8+h] + n3*Wz[(lane+96)*8+h];
        #pragma unroll
        for (int o = 16; o > 0; o >>= 1) pp += __shfl_xor_sync(0xffffffffu, pp, o);
        ph[h] = pp;
    }
    if (lane == 0) {
        #pragma unroll
        for (int h = 0; h < 8; h++)
            g_Wsm[(size_t)h*N_DIM*N_DIM + (size_t)i*N_DIM + j] = ph[h];
    }
}

// ============================================================
// K2b: softmax over j (last dim of g_Wsm rows). one block per (h,i)
// ============================================================
__global__ void __launch_bounds__(256) k2b_softmax()
{
    float* p = g_Wsm + (size_t)blockIdx.x * N_DIM;
    __shared__ float red[256];
    int t = threadIdx.x;
    float v0 = p[t], v1 = p[t+256];
    red[t] = fmaxf(v0, v1);
    __syncthreads();
    for (int s2 = 128; s2 > 0; s2 >>= 1) {
        if (t < s2) red[t] = fmaxf(red[t], red[t+s2]);
        __syncthreads();
    }
    float mx = red[0];
    __syncthreads();
    float e0 = __expf(v0-mx), e1 = __expf(v1-mx);
    red[t] = e0+e1;
    __syncthreads();
    for (int s2 = 128; s2 > 0; s2 >>= 1) {
        if (t < s2) red[t] += red[t+s2];
        __syncthreads();
    }
    float inv = __fdividef(1.0f, red[0]);
    p[t] = e0*inv; p[t+256] = e1*inv;
}

// ============================================================
// K3: batched GEMM  WV[h] = Wsm[h] (512x512)  @  Vt[h] (512x8192)
//     64x64x16 tiles, 256 thr, 4x4 microtile
// ============================================================
__global__ void __launch_bounds__(256) k3_gemm()
{
    int h  = blockIdx.z;
    int i0 = blockIdx.y * 64;
    int p0 = blockIdx.x * 64;
    const float* A = g_Wsm + (size_t)h*N_DIM*N_DIM;
    const float* B = g_Vt  + (size_t)h*N_DIM*PDIM;
    float*       Cm = g_WV + (size_t)h*N_DIM*PDIM;
    __shared__ float As[16][64];
    __shared__ float Bs[16][64];
    int tid = threadIdx.x;
    int a_i = tid >> 2, a_k = (tid & 3) << 2;
    int b_k = tid >> 4, b_p = (tid & 15) << 2;
    int tr = (tid >> 4) << 2;
    int tc = (tid & 15) << 2;
    float acc[4][4] = {};
    for (int k0 = 0; k0 < N_DIM; k0 += 16) {
        float4 av = *(const float4*)&A[(size_t)(i0 + a_i)*N_DIM + k0 + a_k];
        As[a_k+0][a_i] = av.x; As[a_k+1][a_i] = av.y;
        As[a_k+2][a_i] = av.z; As[a_k+3][a_i] = av.w;
        *(float4*)&Bs[b_k][b_p] = *(const float4*)&B[(size_t)(k0 + b_k)*PDIM + p0 + b_p];
        __syncthreads();
        #pragma unroll
        for (int k = 0; k < 16; k++) {
            float4 a4 = *(const float4*)&As[k][tr];
            float4 b4 = *(const float4*)&Bs[k][tc];
            acc[0][0] += a4.x*b4.x; acc[0][1] += a4.x*b4.y; acc[0][2] += a4.x*b4.z; acc[0][3] += a4.x*b4.w;
            acc[1][0] += a4.y*b4.x; acc[1][1] += a4.y*b4.y; acc[1][2] += a4.y*b4.z; acc[1][3] += a4.y*b4.w;
            acc[2][0] += a4.z*b4.x; acc[2][1] += a4.z*b4.y; acc[2][2] += a4.z*b4.z; acc[2][3] += a4.z*b4.w;
            acc[3][0] += a4.w*b4.x; acc[3][1] += a4.w*b4.y; acc[3][2] += a4.w*b4.z; acc[3][3] += a4.w*b4.w;
        }
        __syncthreads();
    }
    #pragma unroll
    for (int r = 0; r < 4; r++) {
        float4 o4 = make_float4(acc[r][0], acc[r][1], acc[r][2], acc[r][3]);
        *(float4*)&Cm[(size_t)(i0 + tr + r)*PDIM + p0 + tc] = o4;
    }
}

// ============================================================
// K4: o = g*wv ; out = m + o @ W_out   (residual)
// ============================================================
__global__ void __launch_bounds__(256) k4_gate_out(
    const float* __restrict__ m, const float* __restrict__ Wout, float* __restrict__ out)
{
    __shared__ float sW[64*64];
    __shared__ float so[16][64];
    int tid = threadIdx.x;
    for (int idx = tid; idx < 4096; idx += 256) sW[idx] = Wout[idx];
    int grp = tid >> 6, ln = tid & 63;
    __syncthreads();
    for (int r0 = blockIdx.x*16; r0 < NROWS; r0 += gridDim.x*16) {
        int rbase = r0 + grp*4;
        #pragma unroll
        for (int rr = 0; rr < 4; rr++) {
            int r = rbase + rr;
            int ss = r >> 9, ii = r & 511;
            so[grp*4+rr][ln] = g_G[(size_t)r*64 + ln] *
                g_WV[(((size_t)(ln>>3)*N_DIM + ii)*S_DIM + ss)*CC + (ln&7)];
        }
        __syncthreads();
        float acc[4];
        #pragma unroll
        for (int rr = 0; rr < 4; rr++) acc[rr] = m[(size_t)(rbase+rr)*64 + ln];
        #pragma unroll 4
        for (int k = 0; k < 64; k += 4) {
            float w0 = sW[(k+0)*64+ln], w1 = sW[(k+1)*64+ln];
            float w2 = sW[(k+2)*64+ln], w3 = sW[(k+3)*64+ln];
            #pragma unroll
            for (int rr = 0; rr < 4; rr++) {
                float4 o4 = *(const float4*)&so[grp*4+rr][k];
                acc[rr] += o4.x*w0 + o4.y*w1 + o4.z*w2 + o4.w*w3;
            }
        }
        #pragma unroll
        for (int rr = 0; rr < 4; rr++)
            out[(size_t)(rbase+rr)*64 + ln] = acc[rr];
        __syncthreads();
    }
}

// ============================================================
// K5: SwiGLU transition, fused. out = out + (silu(t@Wa)*(t@Wb))@Wo, t=LN(out)
// 256 thr = 4 groups x 64; each group 4 rows. All weights in smem (218 KB).
// ============================================================
__global__ void __launch_bounds__(256) k5_transition(
    float* __restrict__ out, const float* __restrict__ lng, const float* __restrict__ lnb,
    const float* __restrict__ Wa, const float* __restrict__ Wb, const float* __restrict__ Wo)
{
    extern __shared__ float sh[];
    float* sWa  = sh;                   // 16384
    float* sWb  = sWa + 16384;          // 16384
    float* sWoT = sWb + 16384;          // [c][k] padded: 64*260 = 16640
    float* st   = sWoT + 16640;         // 16*64
    float* shh  = st + 1024;            // 16*256
    float2* sred = (float2*)(shh + 4096); // 8 warps * 4 rows

    int tid = threadIdx.x;
    for (int idx = tid; idx < 16384; idx += 256) { sWa[idx] = Wa[idx]; sWb[idx] = Wb[idx]; }
    for (int idx = tid; idx < 16384; idx += 256) {
        int k = idx >> 6, c = idx & 63;
        sWoT[c*260 + k] = Wo[idx];
    }
    int grp = tid >> 6, ln = tid & 63, warp = tid >> 5;
    float gg = lng[ln], bb = lnb[ln];
    __syncthreads();

    for (int r0 = blockIdx.x*16; r0 < NROWS; r0 += gridDim.x*16) {
        int rbase = r0 + grp*4;
        float x[4]; float2 p[4];
        #pragma unroll
        for (int rr = 0; rr < 4; rr++) {
            x[rr] = out[(size_t)(rbase+rr)*64 + ln];
            float s = x[rr], q = x[rr]*x[rr];
            #pragma unroll
            for (int o = 16; o > 0; o >>= 1) {
                s += __shfl_xor_sync(0xffffffffu, s, o);
                q += __shfl_xor_sync(0xffffffffu, q, o);
            }
            p[rr] = make_float2(s, q);
        }
        if ((tid & 31) == 0) {
            #pragma unroll
            for (int rr = 0; rr < 4; rr++) sred[warp*4+rr] = p[rr];
        }
        __syncthreads();
        #pragma unroll
        for (int rr = 0; rr < 4; rr++) {
            float2 pa = sred[(grp*2)*4+rr], pb = sred[(grp*2+1)*4+rr];
            float mean = (pa.x+pb.x)*(1.0f/64.0f);
            float var  = (pa.y+pb.y)*(1.0f/64.0f) - mean*mean;
            float rs = rsqrtf(var + 1e-5f);
            st[(grp*4+rr)*64 + ln] = (x[rr]-mean)*rs*gg + bb;
        }
        __syncthreads();

        // stage1: hidden cols 4*ln..4*ln+3 for 4 rows
        float aa[4][4] = {}, ab[4][4] = {};
        #pragma unroll 4
        for (int k = 0; k < 64; k++) {
            float4 wa4 = *(const float4*)&sWa[k*256 + 4*ln];
            float4 wb4 = *(const float4*)&sWb[k*256 + 4*ln];
            #pragma unroll
            for (int rr = 0; rr < 4; rr++) {
                float tv = st[(grp*4+rr)*64 + k];
                aa[rr][0] += tv*wa4.x; aa[rr][1] += tv*wa4.y;
                aa[rr][2] += tv*wa4.z; aa[rr][3] += tv*wa4.w;
                ab[rr][0] += tv*wb4.x; ab[rr][1] += tv*wb4.y;
                ab[rr][2] += tv*wb4.z; ab[rr][3] += tv*wb4.w;
            }
        }
        #pragma unroll
        for (int rr = 0; rr < 4; rr++) {
            float4 hv;
            hv.x = aa[rr][0]*__fdividef(1.0f, 1.0f+__expf(-aa[rr][0]))*ab[rr][0];
            hv.y = aa[rr][1]*__fdividef(1.0f, 1.0f+__expf(-aa[rr][1]))*ab[rr][1];
            hv.z = aa[rr][2]*__fdividef(1.0f, 1.0f+__expf(-aa[rr][2]))*ab[rr][2];
            hv.w = aa[rr][3]*__fdividef(1.0f, 1.0f+__expf(-aa[rr][3]))*ab[rr][3];
            *(float4*)&shh[(grp*4+rr)*256 + 4*ln] = hv;
        }
        __syncthreads();

        // stage2: out col = ln for 4 rows, k-vectorized with transposed Wo
        float acc[4] = {x[0], x[1], x[2], x[3]};
        #pragma unroll 8
        for (int k = 0; k < 256; k += 4) {
            float4 wo4 = *(const float4*)&sWoT[ln*260 + k];
            #pragma unroll
            for (int rr = 0; rr < 4; rr++) {
                float4 h4 = *(const float4*)&shh[(grp*4+rr)*256 + k];
                acc[rr] += h4.x*wo4.x + h4.y*wo4.y + h4.z*wo4.z + h4.w*wo4.w;
            }
        }
        #pragma unroll
        for (int rr = 0; rr < 4; rr++)
            out[(size_t)(rbase+rr)*64 + ln] = acc[rr];
        __syncthreads();
    }
}

// ============================================================
extern "C" void kernel_launch(void* const* d_in, const int* in_sizes, int n_in,
                              void* d_out, int out_size) {
    const float* m    = (const float*)d_in[0];
    const float* z    = (const float*)d_in[1];
    const float* lnmg = (const float*)d_in[2];
    const float* lnmb = (const float*)d_in[3];
    const float* Wmv  = (const float*)d_in[4];
    const float* lnzg = (const float*)d_in[5];
    const float* lnzb = (const float*)d_in[6];
    const float* Wz   = (const float*)d_in[7];
    const float* Wmg  = (const float*)d_in[8];
    const float* Wout = (const float*)d_in[9];
    const float* lntg = (const float*)d_in[10];
    const float* lntb = (const float*)d_in[11];
    const float* Wa   = (const float*)d_in[12];
    const float* Wb   = (const float*)d_in[13];
    const float* Wo   = (const float*)d_in[14];
    float* out = (float*)d_out;

    k1_ln_vg<<<1184, 256>>>(m, lnmg, lnmb, Wmv, Wmg);
    k2a_bias<<<(N_DIM*N_DIM)/8, 256>>>(z, lnzg, lnzb, Wz);
    k2b_softmax<<<HH*N_DIM, 256>>>();
    k3_gemm<<<dim3(PDIM/64, N_DIM/64, HH), 256>>>();
    k4_gate_out<<<1184, 256>>>(m, Wout, out);

    static const int k5_smem = (16384*3 + 256 + 1024 + 4096) * 4 + 256; // 218368 B
    cudaFuncSetAttribute(k5_transition, cudaFuncAttributeMaxDynamicSharedMemorySize, 232448);
    k5_transition<<<296, 256, 218368>>>(out, lntg, lntb, Wa, Wb, Wo);
    (void)k5_smem; (void)in_sizes; (void)n_in; (void)out_size;
}

// round 2
// speedup vs baseline: 1.2622x; 1.2622x over previous
#include <cuda_runtime.h>
#include <math.h>

#define S_DIM 1024
#define N_DIM 512
#define CM 64
#define CC 8
#define CZ 128
#define HH 8
#define NROWS (S_DIM*N_DIM)        // 524288
#define PDIM (S_DIM*CC)            // 8192

// ---- scratch ----
__device__ float g_G [(size_t)NROWS*CM];                 // gate, [s][i][hc]
__device__ float g_Vt[(size_t)HH*N_DIM*S_DIM*CC];        // v^T,  [h][j][s][c]
__device__ float g_WV[(size_t)HH*N_DIM*S_DIM*CC];        // wv,   [h][i][s][c]
__device__ float g_Wsm[(size_t)HH*N_DIM*N_DIM];          // softmax w [h][i][j]

// ============================================================
// K1: LN(m) -> v (transposed) and g (sigmoid).
// ============================================================
__global__ void __launch_bounds__(256) k1_ln_vg(
    const float* __restrict__ m, const float* __restrict__ lng, const float* __restrict__ lnb,
    const float* __restrict__ Wmv, const float* __restrict__ Wmg)
{
    __shared__ float sWv[CM*CM];
    __shared__ float sWg[CM*CM];
    __shared__ float smn[16][CM];
    __shared__ float2 sred[8][4];
    int tid = threadIdx.x;
    for (int idx = tid; idx < CM*CM; idx += 256) { sWv[idx] = Wmv[idx]; sWg[idx] = Wmg[idx]; }
    int grp = tid >> 6, ln = tid & 63, warp = tid >> 5;
    float gg = lng[ln], bb = lnb[ln];
    __syncthreads();

    for (int r0 = blockIdx.x*16; r0 < NROWS; r0 += gridDim.x*16) {
        int rbase = r0 + grp*4;
        float x[4]; float2 p[4];
        #pragma unroll
        for (int rr = 0; rr < 4; rr++) {
            x[rr] = m[(size_t)(rbase+rr)*CM + ln];
            float s = x[rr], q = x[rr]*x[rr];
            #pragma unroll
            for (int o = 16; o > 0; o >>= 1) {
                s += __shfl_xor_sync(0xffffffffu, s, o);
                q += __shfl_xor_sync(0xffffffffu, q, o);
            }
            p[rr] = make_float2(s, q);
        }
        if ((tid & 31) == 0) {
            #pragma unroll
            for (int rr = 0; rr < 4; rr++) sred[warp][rr] = p[rr];
        }
        __syncthreads();
        #pragma unroll
        for (int rr = 0; rr < 4; rr++) {
            float2 pa = sred[grp*2][rr], pb = sred[grp*2+1][rr];
            float mean = (pa.x+pb.x) * (1.0f/64.0f);
            float var  = (pa.y+pb.y) * (1.0f/64.0f) - mean*mean;
            float rs = rsqrtf(var + 1e-5f);
            smn[grp*4+rr][ln] = (x[rr]-mean)*rs*gg + bb;
        }
        __syncthreads();

        float av[4] = {0,0,0,0}, ag[4] = {0,0,0,0};
        #pragma unroll 4
        for (int k = 0; k < 64; k += 4) {
            float wv0 = sWv[(k+0)*64+ln], wv1 = sWv[(k+1)*64+ln];
            float wv2 = sWv[(k+2)*64+ln], wv3 = sWv[(k+3)*64+ln];
            float wg0 = sWg[(k+0)*64+ln], wg1 = sWg[(k+1)*64+ln];
            float wg2 = sWg[(k+2)*64+ln], wg3 = sWg[(k+3)*64+ln];
            #pragma unroll
            for (int rr = 0; rr < 4; rr++) {
                float4 mn4 = *(const float4*)&smn[grp*4+rr][k];
                av[rr] += mn4.x*wv0 + mn4.y*wv1 + mn4.z*wv2 + mn4.w*wv3;
                ag[rr] += mn4.x*wg0 + mn4.y*wg1 + mn4.z*wg2 + mn4.w*wg3;
            }
        }
        #pragma unroll
        for (int rr = 0; rr < 4; rr++) {
            int r = rbase + rr;
            int ss = r >> 9, ii = r & 511;
            float gval = __fdividef(1.0f, 1.0f + __expf(-ag[rr]));
            g_G[(size_t)r*64 + ln] = gval;
            g_Vt[(((size_t)(ln>>3)*N_DIM + ii)*S_DIM + ss)*CC + (ln&7)] = av[rr];
        }
        __syncthreads();
    }
}

// ============================================================
// K2a: bias[h][i][j] = LN(z[i,j,:]) @ W_z
// ============================================================
__global__ void __launch_bounds__(256) k2a_bias(
    const float* __restrict__ z, const float* __restrict__ lng, const float* __restrict__ lnb,
    const float* __restrict__ Wz)
{
    int w = (blockIdx.x * 256 + threadIdx.x) >> 5;
    int lane = threadIdx.x & 31;
    if (w >= N_DIM*N_DIM) return;
    int i = w >> 9, j = w & 511;
    const float* zp = z + ((size_t)i*N_DIM + j)*CZ;
    float x0 = zp[lane], x1 = zp[lane+32], x2 = zp[lane+64], x3 = zp[lane+96];
    float s = x0+x1+x2+x3;
    float q = x0*x0 + x1*x1 + x2*x2 + x3*x3;
    #pragma unroll
    for (int o = 16; o > 0; o >>= 1) {
        s += __shfl_xor_sync(0xffffffffu, s, o);
        q += __shfl_xor_sync(0xffffffffu, q, o);
    }
    float mean = s * (1.0f/128.0f);
    float var  = q * (1.0f/128.0f) - mean*mean;
    float rs = rsqrtf(var + 1e-5f);
    float n0 = (x0-mean)*rs*lng[lane]    + lnb[lane];
    float n1 = (x1-mean)*rs*lng[lane+32] + lnb[lane+32];
    float n2 = (x2-mean)*rs*lng[lane+64] + lnb[lane+64];
    float n3 = (x3-mean)*rs*lng[lane+96] + lnb[lane+96];
    float ph[8];
    #pragma unroll
    for (int h = 0; h < 8; h++) {
        float pp = n0*Wz[lane*8+h] + n1*Wz[(lane+32)*8+h]
                 + n2*Wz[(lane+64)*8+h] + n3*Wz[(lane+96)*8+h];
        #pragma unroll
        for (int o = 16; o > 0; o >>= 1) pp += __shfl_xor_sync(0xffffffffu, pp, o);
        ph[h] = pp;
    }
    if (lane == 0) {
        #pragma unroll
        for (int h = 0; h < 8; h++)
            g_Wsm[(size_t)h*N_DIM*N_DIM + (size_t)i*N_DIM + j] = ph[h];
    }
}

// ============================================================
// K2b: softmax over j
// ============================================================
__global__ void __launch_bounds__(256) k2b_softmax()
{
    float* p = g_Wsm + (size_t)blockIdx.x * N_DIM;
    __shared__ float red[256];
    int t = threadIdx.x;
    float v0 = p[t], v1 = p[t+256];
    red[t] = fmaxf(v0, v1);
    __syncthreads();
    for (int s2 = 128; s2 > 0; s2 >>= 1) {
        if (t < s2) red[t] = fmaxf(red[t], red[t+s2]);
        __syncthreads();
    }
    float mx = red[0];
    __syncthreads();
    float e0 = __expf(v0-mx), e1 = __expf(v1-mx);
    red[t] = e0+e1;
    __syncthreads();
    for (int s2 = 128; s2 > 0; s2 >>= 1) {
        if (t < s2) red[t] += red[t+s2];
        __syncthreads();
    }
    float inv = __fdividef(1.0f, red[0]);
    p[t] = e0*inv; p[t+256] = e1*inv;
}

// ============================================================
// K3: batched GEMM  WV[h] = Wsm[h] (512x512) @ Vt[h] (512x8192)
//     128x128 tile, 8x8 microtile, double-buffered smem.
// ============================================================
__global__ void __launch_bounds__(256) k3_gemm()
{
    int h  = blockIdx.z;
    int i0 = blockIdx.y * 128;
    int p0 = blockIdx.x * 128;
    const float* A = g_Wsm + (size_t)h*N_DIM*N_DIM;
    const float* B = g_Vt  + (size_t)h*N_DIM*PDIM;
    float*       Cm = g_WV + (size_t)h*N_DIM*PDIM;
    __shared__ float As[2][16][132];
    __shared__ float Bs[2][16][128];
    int tid = threadIdx.x;
    int ra = tid >> 2, kq = (tid & 3) * 4;         // A loader: 2 rows (ra, ra+64), 4 k
    int kb = tid >> 4, pb = (tid & 15) * 8;        // B loader
    int tr = (tid >> 4) << 3, tc = (tid & 15) << 3;

    float4 a0, a1, b0, b1;
    a0 = *(const float4*)&A[(size_t)(i0+ra)*N_DIM + kq];
    a1 = *(const float4*)&A[(size_t)(i0+ra+64)*N_DIM + kq];
    b0 = *(const float4*)&B[(size_t)kb*PDIM + p0 + pb];
    b1 = *(const float4*)&B[(size_t)kb*PDIM + p0 + pb + 4];
    As[0][kq+0][ra] = a0.x; As[0][kq+1][ra] = a0.y; As[0][kq+2][ra] = a0.z; As[0][kq+3][ra] = a0.w;
    As[0][kq+0][ra+64] = a1.x; As[0][kq+1][ra+64] = a1.y; As[0][kq+2][ra+64] = a1.z; As[0][kq+3][ra+64] = a1.w;
    *(float4*)&Bs[0][kb][pb]   = b0;
    *(float4*)&Bs[0][kb][pb+4] = b1;
    __syncthreads();

    float acc[8][8] = {};
    int buf = 0;
    for (int k0 = 16; k0 <= N_DIM; k0 += 16) {
        if (k0 < N_DIM) {
            a0 = *(const float4*)&A[(size_t)(i0+ra)*N_DIM + k0 + kq];
            a1 = *(const float4*)&A[(size_t)(i0+ra+64)*N_DIM + k0 + kq];
            b0 = *(const float4*)&B[(size_t)(k0+kb)*PDIM + p0 + pb];
            b1 = *(const float4*)&B[(size_t)(k0+kb)*PDIM + p0 + pb + 4];
        }
        #pragma unroll
        for (int k = 0; k < 16; k++) {
            float4 x0 = *(const float4*)&As[buf][k][tr];
            float4 x1 = *(const float4*)&As[buf][k][tr+4];
            float4 y0 = *(const float4*)&Bs[buf][k][tc];
            float4 y1 = *(const float4*)&Bs[buf][k][tc+4];
            float xa[8] = {x0.x,x0.y,x0.z,x0.w,x1.x,x1.y,x1.z,x1.w};
            float yb[8] = {y0.x,y0.y,y0.z,y0.w,y1.x,y1.y,y1.z,y1.w};
            #pragma unroll
            for (int i = 0; i < 8; i++)
                #pragma unroll
                for (int j = 0; j < 8; j++)
                    acc[i][j] += xa[i]*yb[j];
        }
        int nb = buf ^ 1;
        if (k0 < N_DIM) {
            As[nb][kq+0][ra] = a0.x; As[nb][kq+1][ra] = a0.y; As[nb][kq+2][ra] = a0.z; As[nb][kq+3][ra] = a0.w;
            As[nb][kq+0][ra+64] = a1.x; As[nb][kq+1][ra+64] = a1.y; As[nb][kq+2][ra+64] = a1.z; As[nb][kq+3][ra+64] = a1.w;
            *(float4*)&Bs[nb][kb][pb]   = b0;
            *(float4*)&Bs[nb][kb][pb+4] = b1;
        }
        __syncthreads();
        buf = nb;
    }
    #pragma unroll
    for (int i = 0; i < 8; i++) {
        *(float4*)&Cm[(size_t)(i0+tr+i)*PDIM + p0 + tc]     = make_float4(acc[i][0],acc[i][1],acc[i][2],acc[i][3]);
        *(float4*)&Cm[(size_t)(i0+tr+i)*PDIM + p0 + tc + 4] = make_float4(acc[i][4],acc[i][5],acc[i][6],acc[i][7]);
    }
}

// ============================================================
// K4: o = g*wv ; out = m + o @ W_out. 256 rows/iter, 8x8 microtile.
// ============================================================
__global__ void __launch_bounds__(256) k4_gate_out(
    const float* __restrict__ m, const float* __restrict__ Wout, float* __restrict__ out)
{
    extern __shared__ float dyn4[];
    float* sW = dyn4;            // [64][68]
    float* so = sW + 64*68;      // [256][68]
    int tid = threadIdx.x;
    for (int idx = tid; idx < 4096; idx += 256) {
        int k = idx >> 6, c = idx & 63;
        sW[k*68 + c] = Wout[idx];
    }
    int rg = tid >> 3, cg = tid & 7;
    int r0t = rg*8, c0 = cg*8;
    __syncthreads();

    for (int rbase = blockIdx.x*256; rbase < NROWS; rbase += gridDim.x*256) {
        // phase A: gate product, coalesced
        #pragma unroll
        for (int i = 0; i < 16; i++) {
            int flat4 = i*256 + tid;
            int row = flat4 >> 4, c4 = flat4 & 15;
            int r = rbase + row; int ss = r >> 9, ii = r & 511;
            int k0 = c4*4; int hh = k0 >> 3, cc = k0 & 7;
            float4 g4 = *(const float4*)&g_G[(size_t)r*64 + k0];
            float4 w4 = *(const float4*)&g_WV[(((size_t)hh*N_DIM+ii)*S_DIM+ss)*CC + cc];
            float4 s4 = make_float4(g4.x*w4.x, g4.y*w4.y, g4.z*w4.z, g4.w*w4.w);
            *(float4*)&so[row*68 + k0] = s4;
        }
        __syncthreads();

        float acc[8][8] = {};
        #pragma unroll 8
        for (int k = 0; k < 64; k++) {
            float tv[8];
            #pragma unroll
            for (int i = 0; i < 8; i++) tv[i] = so[(r0t+i)*68 + k];
            float4 w0 = *(const float4*)&sW[k*68 + c0];
            float4 w1 = *(const float4*)&sW[k*68 + c0 + 4];
            float wb8[8] = {w0.x,w0.y,w0.z,w0.w,w1.x,w1.y,w1.z,w1.w};
            #pragma unroll
            for (int i = 0; i < 8; i++)
                #pragma unroll
                for (int j = 0; j < 8; j++)
                    acc[i][j] += tv[i]*wb8[j];
        }
        #pragma unroll
        for (int i = 0; i < 8; i++) {
            size_t rowoff = (size_t)(rbase + r0t + i)*64;
            float4 m0 = *(const float4*)&m[rowoff + c0];
            float4 m1 = *(const float4*)&m[rowoff + c0 + 4];
            *(float4*)&out[rowoff + c0]     = make_float4(m0.x+acc[i][0], m0.y+acc[i][1], m0.z+acc[i][2], m0.w+acc[i][3]);
            *(float4*)&out[rowoff + c0 + 4] = make_float4(m1.x+acc[i][4], m1.y+acc[i][5], m1.z+acc[i][6], m1.w+acc[i][7]);
        }
        __syncthreads();
    }
}

// ============================================================
// K5: SwiGLU transition. 256 rows/iter; hidden in 4 chunks of 64;
// weights streamed per chunk; all stages 8-row microtiles.
// ============================================================
__global__ void __launch_bounds__(256, 1) k5_transition(
    float* __restrict__ out, const float* __restrict__ lng, const float* __restrict__ lnb,
    const float* __restrict__ Wa, const float* __restrict__ Wb, const float* __restrict__ Wo)
{
    extern __shared__ float dyn5[];
    float* st  = dyn5;               // [256][68] LN'd activations
    float* shd = st  + 256*68;       // [256][68] hidden chunk
    float* sWa = shd + 256*68;       // [64][68]
    float* sWb = sWa + 64*68;        // [64][68]
    float* sWo = sWb + 64*68;        // [64][68]

    int tid = threadIdx.x;
    int lane = tid & 31, wid = tid >> 5;
    float gm0 = lng[lane], gm1 = lng[lane+32];
    float bt0 = lnb[lane], bt1 = lnb[lane+32];

    int rg1 = tid >> 4, hg = tid & 15;           // stage1: 16 rgrp x 16 hgrp
    int h0 = hg*4;
    int rg2 = tid >> 3, cg = tid & 7;            // stage2: 32 rgrp x 8 cgrp
    int r0b = rg2*8, c0 = cg*8;
    int wkk = tid >> 2, wq = (tid & 3)*16;       // weight loader

    for (int rbase = blockIdx.x*256; rbase < NROWS; rbase += gridDim.x*256) {
        // ---- load rows (coalesced) into st ----
        #pragma unroll
        for (int i = 0; i < 16; i++) {
            int flat4 = i*256 + tid;
            int row = flat4 >> 4, c4 = flat4 & 15;
            float4 v = *(const float4*)&out[(size_t)(rbase+row)*64 + c4*4];
            *(float4*)&st[row*68 + c4*4] = v;
        }
        __syncthreads();
        // ---- LN in place (warp per 32 rows, 4-way ILP) ----
        for (int rr = 0; rr < 32; rr += 4) {
            float xs0[4], xs1[4], s[4], q[4];
            #pragma unroll
            for (int u = 0; u < 4; u++) {
                int row = wid*32 + rr + u;
                xs0[u] = st[row*68 + lane];
                xs1[u] = st[row*68 + 32 + lane];
                s[u] = xs0[u] + xs1[u];
                q[u] = xs0[u]*xs0[u] + xs1[u]*xs1[u];
            }
            #pragma unroll
            for (int o = 16; o > 0; o >>= 1) {
                #pragma unroll
                for (int u = 0; u < 4; u++) {
                    s[u] += __shfl_xor_sync(0xffffffffu, s[u], o);
                    q[u] += __shfl_xor_sync(0xffffffffu, q[u], o);
                }
            }
            #pragma unroll
            for (int u = 0; u < 4; u++) {
                int row = wid*32 + rr + u;
                float mean = s[u]*(1.0f/64.0f);
                float var  = q[u]*(1.0f/64.0f) - mean*mean;
                float rs = rsqrtf(var + 1e-5f);
                st[row*68 + lane]      = (xs0[u]-mean)*rs*gm0 + bt0;
                st[row*68 + 32 + lane] = (xs1[u]-mean)*rs*gm1 + bt1;
            }
        }

        float acc[8][8] = {};
        #pragma unroll 1
        for (int hc = 0; hc < 4; hc++) {
            __syncthreads();   // prev stage2 done with shd / weights
            // ---- stream weight chunks ----
            #pragma unroll
            for (int u = 0; u < 4; u++) {
                *(float4*)&sWa[wkk*68 + wq + u*4] = *(const float4*)&Wa[(size_t)wkk*256 + hc*64 + wq + u*4];
                *(float4*)&sWb[wkk*68 + wq + u*4] = *(const float4*)&Wb[(size_t)wkk*256 + hc*64 + wq + u*4];
                *(float4*)&sWo[wkk*68 + wq + u*4] = *(const float4*)&Wo[(size_t)(hc*64+wkk)*64 + wq + u*4];
            }
            __syncthreads();
            // ---- stage1: h chunk for 256 rows ----
            #pragma unroll 1
            for (int rh = 0; rh < 2; rh++) {
                int r0 = rh*128 + rg1*8;
                float aa[8][4] = {}, ab[8][4] = {};
                #pragma unroll 8
                for (int kk = 0; kk < 64; kk++) {
                    float tv[8];
                    #pragma unroll
                    for (int i = 0; i < 8; i++) tv[i] = st[(r0+i)*68 + kk];
                    float4 wa = *(const float4*)&sWa[kk*68 + h0];
                    float4 wb = *(const float4*)&sWb[kk*68 + h0];
                    #pragma unroll
                    for (int i = 0; i < 8; i++) {
                        aa[i][0] += tv[i]*wa.x; aa[i][1] += tv[i]*wa.y;
                        aa[i][2] += tv[i]*wa.z; aa[i][3] += tv[i]*wa.w;
                        ab[i][0] += tv[i]*wb.x; ab[i][1] += tv[i]*wb.y;
                        ab[i][2] += tv[i]*wb.z; ab[i][3] += tv[i]*wb.w;
                    }
                }
                #pragma unroll
                for (int i = 0; i < 8; i++) {
                    float4 hv;
                    hv.x = aa[i][0]*__fdividef(1.0f, 1.0f+__expf(-aa[i][0]))*ab[i][0];
                    hv.y = aa[i][1]*__fdividef(1.0f, 1.0f+__expf(-aa[i][1]))*ab[i][1];
                    hv.z = aa[i][2]*__fdividef(1.0f, 1.0f+__expf(-aa[i][2]))*ab[i][2];
                    hv.w = aa[i][3]*__fdividef(1.0f, 1.0f+__expf(-aa[i][3]))*ab[i][3];
                    *(float4*)&shd[(r0+i)*68 + h0] = hv;
                }
            }
            __syncthreads();
            // ---- stage2: accumulate out tile ----
            #pragma unroll 8
            for (int kk = 0; kk < 64; kk++) {
                float hv[8];
                #pragma unroll
                for (int i = 0; i < 8; i++) hv[i] = shd[(r0b+i)*68 + kk];
                float4 w0 = *(const float4*)&sWo[kk*68 + c0];
                float4 w1 = *(const float4*)&sWo[kk*68 + c0 + 4];
                float wb8[8] = {w0.x,w0.y,w0.z,w0.w,w1.x,w1.y,w1.z,w1.w};
                #pragma unroll
                for (int i = 0; i < 8; i++)
                    #pragma unroll
                    for (int j = 0; j < 8; j++)
                        acc[i][j] += hv[i]*wb8[j];
            }
        }
        // ---- residual + store ----
        #pragma unroll
        for (int i = 0; i < 8; i++) {
            size_t rowoff = (size_t)(rbase + r0b + i)*64;
            float4 x0 = *(const float4*)&out[rowoff + c0];
            float4 x1 = *(const float4*)&out[rowoff + c0 + 4];
            *(float4*)&out[rowoff + c0]     = make_float4(x0.x+acc[0 ? 0 : i][0], x0.y+acc[i][1], x0.z+acc[i][2], x0.w+acc[i][3]);
            *(float4*)&out[rowoff + c0 + 4] = make_float4(x1.x+acc[i][4], x1.y+acc[i][5], x1.z+acc[i][6], x1.w+acc[i][7]);
        }
        __syncthreads();   // before next iter overwrites st
    }
}

// ============================================================
extern "C" void kernel_launch(void* const* d_in, const int* in_sizes, int n_in,
                              void* d_out, int out_size) {
    const float* m    = (const float*)d_in[0];
    const float* z    = (const float*)d_in[1];
    const float* lnmg = (const float*)d_in[2];
    const float* lnmb = (const float*)d_in[3];
    const float* Wmv  = (const float*)d_in[4];
    const float* lnzg = (const float*)d_in[5];
    const float* lnzb = (const float*)d_in[6];
    const float* Wz   = (const float*)d_in[7];
    const float* Wmg  = (const float*)d_in[8];
    const float* Wout = (const float*)d_in[9];
    const float* lntg = (const float*)d_in[10];
    const float* lntb = (const float*)d_in[11];
    const float* Wa   = (const float*)d_in[12];
    const float* Wb   = (const float*)d_in[13];
    const float* Wo   = (const float*)d_in[14];
    float* out = (float*)d_out;

    k1_ln_vg<<<1184, 256>>>(m, lnmg, lnmb, Wmv, Wmg);
    k2a_bias<<<(N_DIM*N_DIM)/8, 256>>>(z, lnzg, lnzb, Wz);
    k2b_softmax<<<HH*N_DIM, 256>>>();
    k3_gemm<<<dim3(PDIM/128, N_DIM/128, HH), 256>>>();

    const int k4_smem = (64*68 + 256*68) * 4;       // 87,040 B
    cudaFuncSetAttribute(k4_gate_out, cudaFuncAttributeMaxDynamicSharedMemorySize, k4_smem);
    k4_gate_out<<<296, 256, k4_smem>>>(m, Wout, out);

    const int k5_smem = (256*68*2 + 64*68*3) * 4;   // 191,488 B
    cudaFuncSetAttribute(k5_transition, cudaFuncAttributeMaxDynamicSharedMemorySize, k5_smem);
    k5_transition<<<148, 256, k5_smem>>>(out, lntg, lntb, Wa, Wb, Wo);
    (void)in_sizes; (void)n_in; (void)out_size;
}

// round 4
// speedup vs baseline: 1.5592x; 1.2354x over previous
#include <cuda_runtime.h>
#include <math.h>
#include <stdint.h>

#define S_DIM 1024
#define N_DIM 512
#define CM 64
#define CC 8
#define CZ 128
#define HH 8
#define NROWS (S_DIM*N_DIM)        // 524288
#define PDIM (S_DIM*CC)            // 8192

// ---- scratch ----
__device__ float g_G [(size_t)NROWS*CM];                 // gate, [s*N+i][hc]
__device__ float g_Vt[(size_t)HH*N_DIM*PDIM];            // v^T,  [h][j][p=s*8+c]  (tf32-rounded)
__device__ float g_WV[(size_t)HH*N_DIM*PDIM];            // wv,   [h][i][p]
__device__ float g_Wsm[(size_t)HH*N_DIM*N_DIM];          // softmax w [h][i][j] (tf32-rounded)

__device__ __forceinline__ float tf32r(float x){
    uint32_t u; asm("cvt.rna.tf32.f32 %0, %1;" : "=r"(u) : "f"(x)); return __uint_as_float(u);
}
__device__ __forceinline__ void mma16n8k8(float* c, const uint32_t* a, const uint32_t* b){
    asm volatile("mma.sync.aligned.m16n8k8.row.col.f32.tf32.tf32.f32 "
        "{%0,%1,%2,%3}, {%4,%5,%6,%7}, {%8,%9}, {%0,%1,%2,%3};"
        : "+f"(c[0]), "+f"(c[1]), "+f"(c[2]), "+f"(c[3])
        : "r"(a[0]), "r"(a[1]), "r"(a[2]), "r"(a[3]), "r"(b[0]), "r"(b[1]));
}

// ============================================================
// K1: LN(m) -> v (tf32, to g_Vt [h][j][p]) and g (sigmoid).
// ============================================================
__global__ void __launch_bounds__(256) k1_ln_vg(
    const float* __restrict__ m, const float* __restrict__ lng, const float* __restrict__ lnb,
    const float* __restrict__ Wmv, const float* __restrict__ Wmg)
{
    __shared__ float sWv[CM*CM];
    __shared__ float sWg[CM*CM];
    __shared__ float smn[16][CM];
    __shared__ float2 sred[8][4];
    int tid = threadIdx.x;
    for (int idx = tid; idx < CM*CM; idx += 256) { sWv[idx] = Wmv[idx]; sWg[idx] = Wmg[idx]; }
    int grp = tid >> 6, ln = tid & 63, warp = tid >> 5;
    float gg = lng[ln], bb = lnb[ln];
    __syncthreads();

    for (int r0 = blockIdx.x*16; r0 < NROWS; r0 += gridDim.x*16) {
        int rbase = r0 + grp*4;
        float x[4]; float2 p[4];
        #pragma unroll
        for (int rr = 0; rr < 4; rr++) {
            x[rr] = m[(size_t)(rbase+rr)*CM + ln];
            float s = x[rr], q = x[rr]*x[rr];
            #pragma unroll
            for (int o = 16; o > 0; o >>= 1) {
                s += __shfl_xor_sync(0xffffffffu, s, o);
                q += __shfl_xor_sync(0xffffffffu, q, o);
            }
            p[rr] = make_float2(s, q);
        }
        if ((tid & 31) == 0) {
            #pragma unroll
            for (int rr = 0; rr < 4; rr++) sred[warp][rr] = p[rr];
        }
        __syncthreads();
        #pragma unroll
        for (int rr = 0; rr < 4; rr++) {
            float2 pa = sred[grp*2][rr], pb = sred[grp*2+1][rr];
            float mean = (pa.x+pb.x) * (1.0f/64.0f);
            float var  = (pa.y+pb.y) * (1.0f/64.0f) - mean*mean;
            float rs = rsqrtf(var + 1e-5f);
            smn[grp*4+rr][ln] = (x[rr]-mean)*rs*gg + bb;
        }
        __syncthreads();

        float av[4] = {0,0,0,0}, ag[4] = {0,0,0,0};
        #pragma unroll 4
        for (int k = 0; k < 64; k += 4) {
            float wv0 = sWv[(k+0)*64+ln], wv1 = sWv[(k+1)*64+ln];
            float wv2 = sWv[(k+2)*64+ln], wv3 = sWv[(k+3)*64+ln];
            float wg0 = sWg[(k+0)*64+ln], wg1 = sWg[(k+1)*64+ln];
            float wg2 = sWg[(k+2)*64+ln], wg3 = sWg[(k+3)*64+ln];
            #pragma unroll
            for (int rr = 0; rr < 4; rr++) {
                float4 mn4 = *(const float4*)&smn[grp*4+rr][k];
                av[rr] += mn4.x*wv0 + mn4.y*wv1 + mn4.z*wv2 + mn4.w*wv3;
                ag[rr] += mn4.x*wg0 + mn4.y*wg1 + mn4.z*wg2 + mn4.w*wg3;
            }
        }
        #pragma unroll
        for (int rr = 0; rr < 4; rr++) {
            int r = rbase + rr;
            int ss = r >> 9, ii = r & 511;
            float gval = __fdividef(1.0f, 1.0f + __expf(-ag[rr]));
            g_G[(size_t)r*64 + ln] = gval;
            g_Vt[(((size_t)(ln>>3)*N_DIM + ii)*S_DIM + ss)*CC + (ln&7)] = tf32r(av[rr]);
        }
        __syncthreads();
    }
}

// ============================================================
// K2a: bias[h][i][j] = LN(z[i,j,:]) @ W_z
// ============================================================
__global__ void __launch_bounds__(256) k2a_bias(
    const float* __restrict__ z, const float* __restrict__ lng, const float* __restrict__ lnb,
    const float* __restrict__ Wz)
{
    int w = (blockIdx.x * 256 + threadIdx.x) >> 5;
    int lane = threadIdx.x & 31;
    if (w >= N_DIM*N_DIM) return;
    int i = w >> 9, j = w & 511;
    const float* zp = z + ((size_t)i*N_DIM + j)*CZ;
    float x0 = zp[lane], x1 = zp[lane+32], x2 = zp[lane+64], x3 = zp[lane+96];
    float s = x0+x1+x2+x3;
    float q = x0*x0 + x1*x1 + x2*x2 + x3*x3;
    #pragma unroll
    for (int o = 16; o > 0; o >>= 1) {
        s += __shfl_xor_sync(0xffffffffu, s, o);
        q += __shfl_xor_sync(0xffffffffu, q, o);
    }
    float mean = s * (1.0f/128.0f);
    float var  = q * (1.0f/128.0f) - mean*mean;
    float rs = rsqrtf(var + 1e-5f);
    float n0 = (x0-mean)*rs*lng[lane]    + lnb[lane];
    float n1 = (x1-mean)*rs*lng[lane+32] + lnb[lane+32];
    float n2 = (x2-mean)*rs*lng[lane+64] + lnb[lane+64];
    float n3 = (x3-mean)*rs*lng[lane+96] + lnb[lane+96];
    float ph[8];
    #pragma unroll
    for (int h = 0; h < 8; h++) {
        float pp = n0*Wz[lane*8+h] + n1*Wz[(lane+32)*8+h]
                 + n2*Wz[(lane+64)*8+h] + n3*Wz[(lane+96)*8+h];
        #pragma unroll
        for (int o = 16; o > 0; o >>= 1) pp += __shfl_xor_sync(0xffffffffu, pp, o);
        ph[h] = pp;
    }
    if (lane == 0) {
        #pragma unroll
        for (int h = 0; h < 8; h++)
            g_Wsm[(size_t)h*N_DIM*N_DIM + (size_t)i*N_DIM + j] = ph[h];
    }
}

// ============================================================
// K2b: softmax over j, tf32-rounded output
// ============================================================
__global__ void __launch_bounds__(256) k2b_softmax()
{
    float* p = g_Wsm + (size_t)blockIdx.x * N_DIM;
    __shared__ float red[256];
    int t = threadIdx.x;
    float v0 = p[t], v1 = p[t+256];
    red[t] = fmaxf(v0, v1);
    __syncthreads();
    for (int s2 = 128; s2 > 0; s2 >>= 1) {
        if (t < s2) red[t] = fmaxf(red[t], red[t+s2]);
        __syncthreads();
    }
    float mx = red[0];
    __syncthreads();
    float e0 = __expf(v0-mx), e1 = __expf(v1-mx);
    red[t] = e0+e1;
    __syncthreads();
    for (int s2 = 128; s2 > 0; s2 >>= 1) {
        if (t < s2) red[t] += red[t+s2];
        __syncthreads();
    }
    float inv = __fdividef(1.0f, red[0]);
    p[t] = tf32r(e0*inv); p[t+256] = tf32r(e1*inv);
}

// ============================================================
// K3: mma.sync tf32 GEMM per head:
//   WV[h] (512x8192) = Wsm[h] (512x512) @ Vt[h] (512x8192)
// 128x128 block tile, 8 warps (2x4), warp tile 64x32, BK=32, double buffered.
// ============================================================
__global__ void __launch_bounds__(256,1) k3_mma()
{
    extern __shared__ float sh3[];
    float* sAs = sh3;                 // 2 x [128][36]
    float* sBs = sh3 + 2*128*36;      // 2 x [32][132]

    int tid = threadIdx.x, wid = tid >> 5, lane = tid & 31;
    int group = lane >> 2, tg = lane & 3;
    int wm = wid >> 2, wn = wid & 3;
    int h  = blockIdx.z;
    int i0 = blockIdx.y * 128;
    int p0 = blockIdx.x * 128;
    const float* A = g_Wsm + (size_t)h*N_DIM*N_DIM;
    const float* B = g_Vt  + (size_t)h*N_DIM*PDIM;
    float*       C = g_WV  + (size_t)h*N_DIM*PDIM;

    int lr = tid >> 3, lc = (tid & 7)*4;

    float4 pa[4], pb[4];
    #pragma unroll
    for (int u = 0; u < 4; u++) {
        pa[u] = *(const float4*)&A[(size_t)(i0 + lr + u*32)*N_DIM + lc];
        pb[u] = *(const float4*)&B[(size_t)(lr)*PDIM + p0 + lc + u*32];
    }
    #pragma unroll
    for (int u = 0; u < 4; u++) {
        *(float4*)&sAs[(lr + u*32)*36 + lc] = pa[u];
        *(float4*)&sBs[lr*132 + lc + u*32] = pb[u];
    }
    __syncthreads();

    float acc[4][4][4] = {};
    for (int it = 1; it <= 16; it++) {
        int buf = (it-1) & 1, nbuf = it & 1;
        if (it < 16) {
            int k0 = it*32;
            #pragma unroll
            for (int u = 0; u < 4; u++) {
                pa[u] = *(const float4*)&A[(size_t)(i0 + lr + u*32)*N_DIM + k0 + lc];
                pb[u] = *(const float4*)&B[(size_t)(k0 + lr)*PDIM + p0 + lc + u*32];
            }
        }
        const float* as = sAs + buf*4608;
        const float* bs = sBs + buf*4224;
        #pragma unroll
        for (int ks = 0; ks < 4; ks++) {
            uint32_t af[4][4], bf[4][2];
            #pragma unroll
            for (int mt = 0; mt < 4; mt++) {
                const float* ap = as + (wm*64 + mt*16 + group)*36 + ks*8 + tg;
                af[mt][0] = __float_as_uint(ap[0]);
                af[mt][1] = __float_as_uint(ap[8*36]);
                af[mt][2] = __float_as_uint(ap[4]);
                af[mt][3] = __float_as_uint(ap[8*36 + 4]);
            }
            #pragma unroll
            for (int nt = 0; nt < 4; nt++) {
                const float* bp = bs + (ks*8 + tg)*132 + wn*32 + nt*8 + group;
                bf[nt][0] = __float_as_uint(bp[0]);
                bf[nt][1] = __float_as_uint(bp[4*132]);
            }
            #pragma unroll
            for (int mt = 0; mt < 4; mt++)
                #pragma unroll
                for (int nt = 0; nt < 4; nt++)
                    mma16n8k8(acc[mt][nt], af[mt], bf[nt]);
        }
        if (it < 16) {
            #pragma unroll
            for (int u = 0; u < 4; u++) {
                *(float4*)&sAs[nbuf*4608 + (lr + u*32)*36 + lc] = pa[u];
                *(float4*)&sBs[nbuf*4224 + lr*132 + lc + u*32] = pb[u];
            }
        }
        __syncthreads();
    }

    #pragma unroll
    for (int mt = 0; mt < 4; mt++) {
        int row = i0 + wm*64 + mt*16 + group;
        #pragma unroll
        for (int nt = 0; nt < 4; nt++) {
            int col = p0 + wn*32 + nt*8 + tg*2;
            *(float2*)&C[(size_t)row*PDIM + col]     = make_float2(acc[mt][nt][0], acc[mt][nt][1]);
            *(float2*)&C[(size_t)(row+8)*PDIM + col] = make_float2(acc[mt][nt][2], acc[mt][nt][3]);
        }
    }
}

// ============================================================
// K4: o = g*wv ; out = m + o @ W_out. 256 rows/iter, 8x8 microtile.
// ============================================================
__global__ void __launch_bounds__(256) k4_gate_out(
    const float* __restrict__ m, const float* __restrict__ Wout, float* __restrict__ out)
{
    extern __shared__ float dyn4[];
    float* sW = dyn4;            // [64][68]
    float* so = sW + 64*68;      // [256][68]
    int tid = threadIdx.x;
    for (int idx = tid; idx < 4096; idx += 256) {
        int k = idx >> 6, c = idx & 63;
        sW[k*68 + c] = Wout[idx];
    }
    int rg = tid >> 3, cg = tid & 7;
    int r0t = rg*8, c0 = cg*8;
    __syncthreads();

    for (int rbase = blockIdx.x*256; rbase < NROWS; rbase += gridDim.x*256) {
        #pragma unroll
        for (int i = 0; i < 16; i++) {
            int flat4 = i*256 + tid;
            int row = flat4 >> 4, c4 = flat4 & 15;
            int r = rbase + row; int ss = r >> 9, ii = r & 511;
            int k0 = c4*4; int hh = k0 >> 3, cc = k0 & 7;
            float4 g4 = *(const float4*)&g_G[(size_t)r*64 + k0];
            float4 w4 = *(const float4*)&g_WV[(((size_t)hh*N_DIM+ii)*S_DIM+ss)*CC + cc];
            float4 s4 = make_float4(g4.x*w4.x, g4.y*w4.y, g4.z*w4.z, g4.w*w4.w);
            *(float4*)&so[row*68 + k0] = s4;
        }
        __syncthreads();

        float acc[8][8] = {};
        #pragma unroll 8
        for (int k = 0; k < 64; k++) {
            float tv[8];
            #pragma unroll
            for (int i = 0; i < 8; i++) tv[i] = so[(r0t+i)*68 + k];
            float4 w0 = *(const float4*)&sW[k*68 + c0];
            float4 w1 = *(const float4*)&sW[k*68 + c0 + 4];
            float wb8[8] = {w0.x,w0.y,w0.z,w0.w,w1.x,w1.y,w1.z,w1.w};
            #pragma unroll
            for (int i = 0; i < 8; i++)
                #pragma unroll
                for (int j = 0; j < 8; j++)
                    acc[i][j] += tv[i]*wb8[j];
        }
        #pragma unroll
        for (int i = 0; i < 8; i++) {
            size_t rowoff = (size_t)(rbase + r0t + i)*64;
            float4 m0 = *(const float4*)&m[rowoff + c0];
            float4 m1 = *(const float4*)&m[rowoff + c0 + 4];
            *(float4*)&out[rowoff + c0]     = make_float4(m0.x+acc[i][0], m0.y+acc[i][1], m0.z+acc[i][2], m0.w+acc[i][3]);
            *(float4*)&out[rowoff + c0 + 4] = make_float4(m1.x+acc[i][4], m1.y+acc[i][5], m1.z+acc[i][6], m1.w+acc[i][7]);
        }
        __syncthreads();
    }
}

// ============================================================
// K5: SwiGLU transition.
// ============================================================
__global__ void __launch_bounds__(256, 1) k5_transition(
    float* __restrict__ out, const float* __restrict__ lng, const float* __restrict__ lnb,
    const float* __restrict__ Wa, const float* __restrict__ Wb, const float* __restrict__ Wo)
{
    extern __shared__ float dyn5[];
    float* st  = dyn5;               // [256][68]
    float* shd = st  + 256*68;       // [256][68]
    float* sWa = shd + 256*68;       // [64][68]
    float* sWb = sWa + 64*68;
    float* sWo = sWb + 64*68;

    int tid = threadIdx.x;
    int lane = tid & 31, wid = tid >> 5;
    float gm0 = lng[lane], gm1 = lng[lane+32];
    float bt0 = lnb[lane], bt1 = lnb[lane+32];

    int rg1 = tid >> 4, hg = tid & 15;
    int h0 = hg*4;
    int rg2 = tid >> 3, cg = tid & 7;
    int r0b = rg2*8, c0 = cg*8;
    int wkk = tid >> 2, wq = (tid & 3)*16;

    for (int rbase = blockIdx.x*256; rbase < NROWS; rbase += gridDim.x*256) {
        #pragma unroll
        for (int i = 0; i < 16; i++) {
            int flat4 = i*256 + tid;
            int row = flat4 >> 4, c4 = flat4 & 15;
            float4 v = *(const float4*)&out[(size_t)(rbase+row)*64 + c4*4];
            *(float4*)&st[row*68 + c4*4] = v;
        }
        __syncthreads();
        for (int rr = 0; rr < 32; rr += 4) {
            float xs0[4], xs1[4], s[4], q[4];
            #pragma unroll
            for (int u = 0; u < 4; u++) {
                int row = wid*32 + rr + u;
                xs0[u] = st[row*68 + lane];
                xs1[u] = st[row*68 + 32 + lane];
                s[u] = xs0[u] + xs1[u];
                q[u] = xs0[u]*xs0[u] + xs1[u]*xs1[u];
            }
            #pragma unroll
            for (int o = 16; o > 0; o >>= 1) {
                #pragma unroll
                for (int u = 0; u < 4; u++) {
                    s[u] += __shfl_xor_sync(0xffffffffu, s[u], o);
                    q[u] += __shfl_xor_sync(0xffffffffu, q[u], o);
                }
            }
            #pragma unroll
            for (int u = 0; u < 4; u++) {
                int row = wid*32 + rr + u;
                float mean = s[u]*(1.0f/64.0f);
                float var  = q[u]*(1.0f/64.0f) - mean*mean;
                float rs = rsqrtf(var + 1e-5f);
                st[row*68 + lane]      = (xs0[u]-mean)*rs*gm0 + bt0;
                st[row*68 + 32 + lane] = (xs1[u]-mean)*rs*gm1 + bt1;
            }
        }

        float acc[8][8] = {};
        #pragma unroll 1
        for (int hc = 0; hc < 4; hc++) {
            __syncthreads();
            #pragma unroll
            for (int u = 0; u < 4; u++) {
                *(float4*)&sWa[wkk*68 + wq + u*4] = *(const float4*)&Wa[(size_t)wkk*256 + hc*64 + wq + u*4];
                *(float4*)&sWb[wkk*68 + wq + u*4] = *(const float4*)&Wb[(size_t)wkk*256 + hc*64 + wq + u*4];
                *(float4*)&sWo[wkk*68 + wq + u*4] = *(const float4*)&Wo[(size_t)(hc*64+wkk)*64 + wq + u*4];
            }
            __syncthreads();
            #pragma unroll 1
            for (int rh = 0; rh < 2; rh++) {
                int r0 = rh*128 + rg1*8;
                float aa[8][4] = {}, ab[8][4] = {};
                #pragma unroll 8
                for (int kk = 0; kk < 64; kk++) {
                    float tv[8];
                    #pragma unroll
                    for (int i = 0; i < 8; i++) tv[i] = st[(r0+i)*68 + kk];
                    float4 wa = *(const float4*)&sWa[kk*68 + h0];
                    float4 wb = *(const float4*)&sWb[kk*68 + h0];
                    #pragma unroll
                    for (int i = 0; i < 8; i++) {
                        aa[i][0] += tv[i]*wa.x; aa[i][1] += tv[i]*wa.y;
                        aa[i][2] += tv[i]*wa.z; aa[i][3] += tv[i]*wa.w;
                        ab[i][0] += tv[i]*wb.x; ab[i][1] += tv[i]*wb.y;
                        ab[i][2] += tv[i]*wb.z; ab[i][3] += tv[i]*wb.w;
                    }
                }
                #pragma unroll
                for (int i = 0; i < 8; i++) {
                    float4 hv;
                    hv.x = aa[i][0]*__fdividef(1.0f, 1.0f+__expf(-aa[i][0]))*ab[i][0];
                    hv.y = aa[i][1]*__fdividef(1.0f, 1.0f+__expf(-aa[i][1]))*ab[i][1];
                    hv.z = aa[i][2]*__fdividef(1.0f, 1.0f+__expf(-aa[i][2]))*ab[i][2];
                    hv.w = aa[i][3]*__fdividef(1.0f, 1.0f+__expf(-aa[i][3]))*ab[i][3];
                    *(float4*)&shd[(r0+i)*68 + h0] = hv;
                }
            }
            __syncthreads();
            #pragma unroll 8
            for (int kk = 0; kk < 64; kk++) {
                float hv[8];
                #pragma unroll
                for (int i = 0; i < 8; i++) hv[i] = shd[(r0b+i)*68 + kk];
                float4 w0 = *(const float4*)&sWo[kk*68 + c0];
                float4 w1 = *(const float4*)&sWo[kk*68 + c0 + 4];
                float wb8[8] = {w0.x,w0.y,w0.z,w0.w,w1.x,w1.y,w1.z,w1.w};
                #pragma unroll
                for (int i = 0; i < 8; i++)
                    #pragma unroll
                    for (int j = 0; j < 8; j++)
                        acc[i][j] += hv[i]*wb8[j];
            }
        }
        #pragma unroll
        for (int i = 0; i < 8; i++) {
            size_t rowoff = (size_t)(rbase + r0b + i)*64;
            float4 x0 = *(const float4*)&out[rowoff + c0];
            float4 x1 = *(const float4*)&out[rowoff + c0 + 4];
            *(float4*)&out[rowoff + c0]     = make_float4(x0.x+acc[i][0], x0.y+acc[i][1], x0.z+acc[i][2], x0.w+acc[i][3]);
            *(float4*)&out[rowoff + c0 + 4] = make_float4(x1.x+acc[i][4], x1.y+acc[i][5], x1.z+acc[i][6], x1.w+acc[i][7]);
        }
        __syncthreads();
    }
}

// ============================================================
extern "C" void kernel_launch(void* const* d_in, const int* in_sizes, int n_in,
                              void* d_out, int out_size) {
    const float* m    = (const float*)d_in[0];
    const float* z    = (const float*)d_in[1];
    const float* lnmg = (const float*)d_in[2];
    const float* lnmb = (const float*)d_in[3];
    const float* Wmv  = (const float*)d_in[4];
    const float* lnzg = (const float*)d_in[5];
    const float* lnzb = (const float*)d_in[6];
    const float* Wz   = (const float*)d_in[7];
    const float* Wmg  = (const float*)d_in[8];
    const float* Wout = (const float*)d_in[9];
    const float* lntg = (const float*)d_in[10];
    const float* lntb = (const float*)d_in[11];
    const float* Wa   = (const float*)d_in[12];
    const float* Wb   = (const float*)d_in[13];
    const float* Wo   = (const float*)d_in[14];
    float* out = (float*)d_out;

    k1_ln_vg<<<1184, 256>>>(m, lnmg, lnmb, Wmv, Wmg);
    k2a_bias<<<(N_DIM*N_DIM)/8, 256>>>(z, lnzg, lnzb, Wz);
    k2b_softmax<<<HH*N_DIM, 256>>>();

    const int k3_smem = (2*128*36 + 2*32*132) * 4;   // 70,656 B
    cudaFuncSetAttribute(k3_mma, cudaFuncAttributeMaxDynamicSharedMemorySize, k3_smem);
    k3_mma<<<dim3(PDIM/128, N_DIM/128, HH), 256, k3_smem>>>();

    const int k4_smem = (64*68 + 256*68) * 4;        // 87,040 B
    cudaFuncSetAttribute(k4_gate_out, cudaFuncAttributeMaxDynamicSharedMemorySize, k4_smem);
    k4_gate_out<<<296, 256, k4_smem>>>(m, Wout, out);

    const int k5_smem = (256*68*2 + 64*68*3) * 4;    // 191,488 B
    cudaFuncSetAttribute(k5_transition, cudaFuncAttributeMaxDynamicSharedMemorySize, k5_smem);
    k5_transition<<<148, 256, k5_smem>>>(out, lntg, lntb, Wa, Wb, Wo);
    (void)in_sizes; (void)n_in; (void)out_size;
}

// round 6
// speedup vs baseline: 1.9798x; 1.2697x over previous
#include <cuda_runtime.h>
#include <math.h>
#include <stdint.h>

// R6 = R5 resubmit: R5 bench died with "GB300 container failed twice"
// (infra flake, same signature as Round 0 with the empty stub). No code change.

#define S_DIM 1024
#define N_DIM 512
#define CM 64
#define CC 8
#define CZ 128
#define HH 8
#define NROWS (S_DIM*N_DIM)        // 524288
#define PDIM (S_DIM*CC)            // 8192

// ---- scratch ----
__device__ float g_G [(size_t)NROWS*CM];                 // gate, [s*N+i][hc]
__device__ float g_Vt[(size_t)HH*N_DIM*PDIM];            // v^T,  [h][j][p=s*8+c]  (tf32-rounded)
__device__ float g_WV[(size_t)HH*N_DIM*PDIM];            // wv,   [h][i][p]
__device__ float g_Wsm[(size_t)HH*N_DIM*N_DIM];          // softmax w [h][i][j] (tf32-rounded)

__device__ __forceinline__ float tf32r(float x){
    uint32_t u; asm("cvt.rna.tf32.f32 %0, %1;" : "=r"(u) : "f"(x)); return __uint_as_float(u);
}
__device__ __forceinline__ void mma16n8k8(float* c, const uint32_t* a, const uint32_t* b){
    asm volatile("mma.sync.aligned.m16n8k8.row.col.f32.tf32.tf32.f32 "
        "{%0,%1,%2,%3}, {%4,%5,%6,%7}, {%8,%9}, {%0,%1,%2,%3};"
        : "+f"(c[0]), "+f"(c[1]), "+f"(c[2]), "+f"(c[3])
        : "r"(a[0]), "r"(a[1]), "r"(a[2]), "r"(a[3]), "r"(b[0]), "r"(b[1]));
}

// ============================================================
// K1: LN(m) -> v (tf32, to g_Vt [h][j][p]) and g (sigmoid).
// ============================================================
__global__ void __launch_bounds__(256) k1_ln_vg(
    const float* __restrict__ m, const float* __restrict__ lng, const float* __restrict__ lnb,
    const float* __restrict__ Wmv, const float* __restrict__ Wmg)
{
    __shared__ float sWv[CM*CM];
    __shared__ float sWg[CM*CM];
    __shared__ float smn[16][CM];
    __shared__ float2 sred[8][4];
    int tid = threadIdx.x;
    for (int idx = tid; idx < CM*CM; idx += 256) { sWv[idx] = Wmv[idx]; sWg[idx] = Wmg[idx]; }
    int grp = tid >> 6, ln = tid & 63, warp = tid >> 5;
    float gg = lng[ln], bb = lnb[ln];
    __syncthreads();

    for (int r0 = blockIdx.x*16; r0 < NROWS; r0 += gridDim.x*16) {
        int rbase = r0 + grp*4;
        float x[4]; float2 p[4];
        #pragma unroll
        for (int rr = 0; rr < 4; rr++) {
            x[rr] = m[(size_t)(rbase+rr)*CM + ln];
            float s = x[rr], q = x[rr]*x[rr];
            #pragma unroll
            for (int o = 16; o > 0; o >>= 1) {
                s += __shfl_xor_sync(0xffffffffu, s, o);
                q += __shfl_xor_sync(0xffffffffu, q, o);
            }
            p[rr] = make_float2(s, q);
        }
        if ((tid & 31) == 0) {
            #pragma unroll
            for (int rr = 0; rr < 4; rr++) sred[warp][rr] = p[rr];
        }
        __syncthreads();
        #pragma unroll
        for (int rr = 0; rr < 4; rr++) {
            float2 pa = sred[grp*2][rr], pb = sred[grp*2+1][rr];
            float mean = (pa.x+pb.x) * (1.0f/64.0f);
            float var  = (pa.y+pb.y) * (1.0f/64.0f) - mean*mean;
            float rs = rsqrtf(var + 1e-5f);
            smn[grp*4+rr][ln] = (x[rr]-mean)*rs*gg + bb;
        }
        __syncthreads();

        float av[4] = {0,0,0,0}, ag[4] = {0,0,0,0};
        #pragma unroll 4
        for (int k = 0; k < 64; k += 4) {
            float wv0 = sWv[(k+0)*64+ln], wv1 = sWv[(k+1)*64+ln];
            float wv2 = sWv[(k+2)*64+ln], wv3 = sWv[(k+3)*64+ln];
            float wg0 = sWg[(k+0)*64+ln], wg1 = sWg[(k+1)*64+ln];
            float wg2 = sWg[(k+2)*64+ln], wg3 = sWg[(k+3)*64+ln];
            #pragma unroll
            for (int rr = 0; rr < 4; rr++) {
                float4 mn4 = *(const float4*)&smn[grp*4+rr][k];
                av[rr] += mn4.x*wv0 + mn4.y*wv1 + mn4.z*wv2 + mn4.w*wv3;
                ag[rr] += mn4.x*wg0 + mn4.y*wg1 + mn4.z*wg2 + mn4.w*wg3;
            }
        }
        #pragma unroll
        for (int rr = 0; rr < 4; rr++) {
            int r = rbase + rr;
            int ss = r >> 9, ii = r & 511;
            float gval = __fdividef(1.0f, 1.0f + __expf(-ag[rr]));
            g_G[(size_t)r*64 + ln] = gval;
            g_Vt[(((size_t)(ln>>3)*N_DIM + ii)*S_DIM + ss)*CC + (ln&7)] = tf32r(av[rr]);
        }
        __syncthreads();
    }
}

// ============================================================
// K2a: bias[h][i][j] = LN(z[i,j,:]) @ W_z
// ============================================================
__global__ void __launch_bounds__(256) k2a_bias(
    const float* __restrict__ z, const float* __restrict__ lng, const float* __restrict__ lnb,
    const float* __restrict__ Wz)
{
    int w = (blockIdx.x * 256 + threadIdx.x) >> 5;
    int lane = threadIdx.x & 31;
    if (w >= N_DIM*N_DIM) return;
    int i = w >> 9, j = w & 511;
    const float* zp = z + ((size_t)i*N_DIM + j)*CZ;
    float x0 = zp[lane], x1 = zp[lane+32], x2 = zp[lane+64], x3 = zp[lane+96];
    float s = x0+x1+x2+x3;
    float q = x0*x0 + x1*x1 + x2*x2 + x3*x3;
    #pragma unroll
    for (int o = 16; o > 0; o >>= 1) {
        s += __shfl_xor_sync(0xffffffffu, s, o);
        q += __shfl_xor_sync(0xffffffffu, q, o);
    }
    float mean = s * (1.0f/128.0f);
    float var  = q * (1.0f/128.0f) - mean*mean;
    float rs = rsqrtf(var + 1e-5f);
    float n0 = (x0-mean)*rs*lng[lane]    + lnb[lane];
    float n1 = (x1-mean)*rs*lng[lane+32] + lnb[lane+32];
    float n2 = (x2-mean)*rs*lng[lane+64] + lnb[lane+64];
    float n3 = (x3-mean)*rs*lng[lane+96] + lnb[lane+96];
    float ph[8];
    #pragma unroll
    for (int h = 0; h < 8; h++) {
        float pp = n0*Wz[lane*8+h] + n1*Wz[(lane+32)*8+h]
                 + n2*Wz[(lane+64)*8+h] + n3*Wz[(lane+96)*8+h];
        #pragma unroll
        for (int o = 16; o > 0; o >>= 1) pp += __shfl_xor_sync(0xffffffffu, pp, o);
        ph[h] = pp;
    }
    if (lane == 0) {
        #pragma unroll
        for (int h = 0; h < 8; h++)
            g_Wsm[(size_t)h*N_DIM*N_DIM + (size_t)i*N_DIM + j] = ph[h];
    }
}

// ============================================================
// K2b: softmax over j, tf32-rounded output
// ============================================================
__global__ void __launch_bounds__(256) k2b_softmax()
{
    float* p = g_Wsm + (size_t)blockIdx.x * N_DIM;
    __shared__ float red[256];
    int t = threadIdx.x;
    float v0 = p[t], v1 = p[t+256];
    red[t] = fmaxf(v0, v1);
    __syncthreads();
    for (int s2 = 128; s2 > 0; s2 >>= 1) {
        if (t < s2) red[t] = fmaxf(red[t], red[t+s2]);
        __syncthreads();
    }
    float mx = red[0];
    __syncthreads();
    float e0 = __expf(v0-mx), e1 = __expf(v1-mx);
    red[t] = e0+e1;
    __syncthreads();
    for (int s2 = 128; s2 > 0; s2 >>= 1) {
        if (t < s2) red[t] += red[t+s2];
        __syncthreads();
    }
    float inv = __fdividef(1.0f, red[0]);
    p[t] = tf32r(e0*inv); p[t+256] = tf32r(e1*inv);
}

// ============================================================
// K3: mma.sync tf32 GEMM per head (unchanged, passing).
// ============================================================
__global__ void __launch_bounds__(256,1) k3_mma()
{
    extern __shared__ float sh3[];
    float* sAs = sh3;                 // 2 x [128][36]
    float* sBs = sh3 + 2*128*36;      // 2 x [32][132]

    int tid = threadIdx.x, wid = tid >> 5, lane = tid & 31;
    int group = lane >> 2, tg = lane & 3;
    int wm = wid >> 2, wn = wid & 3;
    int h  = blockIdx.z;
    int i0 = blockIdx.y * 128;
    int p0 = blockIdx.x * 128;
    const float* A = g_Wsm + (size_t)h*N_DIM*N_DIM;
    const float* B = g_Vt  + (size_t)h*N_DIM*PDIM;
    float*       C = g_WV  + (size_t)h*N_DIM*PDIM;

    int lr = tid >> 3, lc = (tid & 7)*4;

    float4 pa[4], pb[4];
    #pragma unroll
    for (int u = 0; u < 4; u++) {
        pa[u] = *(const float4*)&A[(size_t)(i0 + lr + u*32)*N_DIM + lc];
        pb[u] = *(const float4*)&B[(size_t)(lr)*PDIM + p0 + lc + u*32];
    }
    #pragma unroll
    for (int u = 0; u < 4; u++) {
        *(float4*)&sAs[(lr + u*32)*36 + lc] = pa[u];
        *(float4*)&sBs[lr*132 + lc + u*32] = pb[u];
    }
    __syncthreads();

    float acc[4][4][4] = {};
    for (int it = 1; it <= 16; it++) {
        int buf = (it-1) & 1, nbuf = it & 1;
        if (it < 16) {
            int k0 = it*32;
            #pragma unroll
            for (int u = 0; u < 4; u++) {
                pa[u] = *(const float4*)&A[(size_t)(i0 + lr + u*32)*N_DIM + k0 + lc];
                pb[u] = *(const float4*)&B[(size_t)(k0 + lr)*PDIM + p0 + lc + u*32];
            }
        }
        const float* as = sAs + buf*4608;
        const float* bs = sBs + buf*4224;
        #pragma unroll
        for (int ks = 0; ks < 4; ks++) {
            uint32_t af[4][4], bf[4][2];
            #pragma unroll
            for (int mt = 0; mt < 4; mt++) {
                const float* ap = as + (wm*64 + mt*16 + group)*36 + ks*8 + tg;
                af[mt][0] = __float_as_uint(ap[0]);
                af[mt][1] = __float_as_uint(ap[8*36]);
                af[mt][2] = __float_as_uint(ap[4]);
                af[mt][3] = __float_as_uint(ap[8*36 + 4]);
            }
            #pragma unroll
            for (int nt = 0; nt < 4; nt++) {
                const float* bp = bs + (ks*8 + tg)*132 + wn*32 + nt*8 + group;
                bf[nt][0] = __float_as_uint(bp[0]);
                bf[nt][1] = __float_as_uint(bp[4*132]);
            }
            #pragma unroll
            for (int mt = 0; mt < 4; mt++)
                #pragma unroll
                for (int nt = 0; nt < 4; nt++)
                    mma16n8k8(acc[mt][nt], af[mt], bf[nt]);
        }
        if (it < 16) {
            #pragma unroll
            for (int u = 0; u < 4; u++) {
                *(float4*)&sAs[nbuf*4608 + (lr + u*32)*36 + lc] = pa[u];
                *(float4*)&sBs[nbuf*4224 + lr*132 + lc + u*32] = pb[u];
            }
        }
        __syncthreads();
    }

    #pragma unroll
    for (int mt = 0; mt < 4; mt++) {
        int row = i0 + wm*64 + mt*16 + group;
        #pragma unroll
        for (int nt = 0; nt < 4; nt++) {
            int col = p0 + wn*32 + nt*8 + tg*2;
            *(float2*)&C[(size_t)row*PDIM + col]     = make_float2(acc[mt][nt][0], acc[mt][nt][1]);
            *(float2*)&C[(size_t)(row+8)*PDIM + col] = make_float2(acc[mt][nt][2], acc[mt][nt][3]);
        }
    }
}

// ============================================================
// K4: o = g*wv ; out = m + o @ W_out. (unchanged, passing)
// ============================================================
__global__ void __launch_bounds__(256) k4_gate_out(
    const float* __restrict__ m, const float* __restrict__ Wout, float* __restrict__ out)
{
    extern __shared__ float dyn4[];
    float* sW = dyn4;            // [64][68]
    float* so = sW + 64*68;      // [256][68]
    int tid = threadIdx.x;
    for (int idx = tid; idx < 4096; idx += 256) {
        int k = idx >> 6, c = idx & 63;
        sW[k*68 + c] = Wout[idx];
    }
    int rg = tid >> 3, cg = tid & 7;
    int r0t = rg*8, c0 = cg*8;
    __syncthreads();

    for (int rbase = blockIdx.x*256; rbase < NROWS; rbase += gridDim.x*256) {
        #pragma unroll
        for (int i = 0; i < 16; i++) {
            int flat4 = i*256 + tid;
            int row = flat4 >> 4, c4 = flat4 & 15;
            int r = rbase + row; int ss = r >> 9, ii = r & 511;
            int k0 = c4*4; int hh = k0 >> 3, cc = k0 & 7;
            float4 g4 = *(const float4*)&g_G[(size_t)r*64 + k0];
            float4 w4 = *(const float4*)&g_WV[(((size_t)hh*N_DIM+ii)*S_DIM+ss)*CC + cc];
            float4 s4 = make_float4(g4.x*w4.x, g4.y*w4.y, g4.z*w4.z, g4.w*w4.w);
            *(float4*)&so[row*68 + k0] = s4;
        }
        __syncthreads();

        float acc[8][8] = {};
        #pragma unroll 8
        for (int k = 0; k < 64; k++) {
            float tv[8];
            #pragma unroll
            for (int i = 0; i < 8; i++) tv[i] = so[(r0t+i)*68 + k];
            float4 w0 = *(const float4*)&sW[k*68 + c0];
            float4 w1 = *(const float4*)&sW[k*68 + c0 + 4];
            float wb8[8] = {w0.x,w0.y,w0.z,w0.w,w1.x,w1.y,w1.z,w1.w};
            #pragma unroll
            for (int i = 0; i < 8; i++)
                #pragma unroll
                for (int j = 0; j < 8; j++)
                    acc[i][j] += tv[i]*wb8[j];
        }
        #pragma unroll
        for (int i = 0; i < 8; i++) {
            size_t rowoff = (size_t)(rbase + r0t + i)*64;
            float4 m0 = *(const float4*)&m[rowoff + c0];
            float4 m1 = *(const float4*)&m[rowoff + c0 + 4];
            *(float4*)&out[rowoff + c0]     = make_float4(m0.x+acc[i][0], m0.y+acc[i][1], m0.z+acc[i][2], m0.w+acc[i][3]);
            *(float4*)&out[rowoff + c0 + 4] = make_float4(m1.x+acc[i][4], m1.y+acc[i][5], m1.z+acc[i][6], m1.w+acc[i][7]);
        }
        __syncthreads();
    }
}

// ============================================================
// K5: SwiGLU transition via mma.sync tf32.
// 128-row tiles. Wa/Wb column-interleaved -> SiLU pairs land in c0/c1.
// ============================================================
__global__ void __launch_bounds__(256,1) k5_mma(
    float* __restrict__ out, const float* __restrict__ lng, const float* __restrict__ lnb,
    const float* __restrict__ Wa, const float* __restrict__ Wb, const float* __restrict__ Wo)
{
    extern __shared__ float sh5[];
    float* st   = sh5;               // [128][68] LN'd rows (tf32)
    float* shh  = st  + 128*68;      // [128][68] hidden chunk (tf32)
    float* swab = shh + 128*68;      // [64 k][132] interleaved Wa|Wb chunk
    float* swo  = swab + 64*132;     // [64 k][68]  Wo chunk

    int tid = threadIdx.x, wid = tid >> 5, lane = tid & 31;
    int group = lane >> 2, tg = lane & 3;
    int wm = wid >> 2, wn = wid & 3;       // GEMM1: 2(M) x 4(N)
    int wm2 = wid >> 1, wn2 = wid & 1;     // GEMM2: 4(M) x 2(N)
    float gm0 = lng[lane], gm1 = lng[lane+32];
    float bt0 = lnb[lane], bt1 = lnb[lane+32];
    int wk = tid >> 2, wq = tid & 3;       // weight loader

    for (int tile = blockIdx.x; tile < NROWS/128; tile += gridDim.x) {
        int rbase = tile*128;
        // ---- load + LN -> st (each warp owns 16 rows) ----
        #pragma unroll 1
        for (int rr = 0; rr < 16; rr += 4) {
            float xs0[4], xs1[4], s[4], q[4];
            #pragma unroll
            for (int u = 0; u < 4; u++) {
                int row = wid*16 + rr + u;
                xs0[u] = out[(size_t)(rbase+row)*64 + lane];
                xs1[u] = out[(size_t)(rbase+row)*64 + 32 + lane];
                s[u] = xs0[u] + xs1[u];
                q[u] = xs0[u]*xs0[u] + xs1[u]*xs1[u];
            }
            #pragma unroll
            for (int o = 16; o > 0; o >>= 1) {
                #pragma unroll
                for (int u = 0; u < 4; u++) {
                    s[u] += __shfl_xor_sync(0xffffffffu, s[u], o);
                    q[u] += __shfl_xor_sync(0xffffffffu, q[u], o);
                }
            }
            #pragma unroll
            for (int u = 0; u < 4; u++) {
                int row = wid*16 + rr + u;
                float mean = s[u]*(1.0f/64.0f);
                float var  = q[u]*(1.0f/64.0f) - mean*mean;
                float rs = rsqrtf(var + 1e-5f);
                st[row*68 + lane]      = tf32r((xs0[u]-mean)*rs*gm0 + bt0);
                st[row*68 + 32 + lane] = tf32r((xs1[u]-mean)*rs*gm1 + bt1);
            }
        }

        float acc2[2][4][4] = {};
        #pragma unroll 1
        for (int hc = 0; hc < 4; hc++) {
            __syncthreads();  // st ready / prev GEMM2 done with shh+weights
            // ---- stream weight chunk: Wa|Wb interleaved, Wo rows ----
            #pragma unroll
            for (int u = 0; u < 4; u++) {
                float4 a4 = *(const float4*)&Wa[(size_t)wk*256 + hc*64 + wq*16 + u*4];
                float4 b4 = *(const float4*)&Wb[(size_t)wk*256 + hc*64 + wq*16 + u*4];
                int base = wk*132 + 2*(wq*16 + u*4);
                swab[base+0] = tf32r(a4.x); swab[base+1] = tf32r(b4.x);
                swab[base+2] = tf32r(a4.y); swab[base+3] = tf32r(b4.y);
                swab[base+4] = tf32r(a4.z); swab[base+5] = tf32r(b4.z);
                swab[base+6] = tf32r(a4.w); swab[base+7] = tf32r(b4.w);
                float4 o4 = *(const float4*)&Wo[(size_t)(hc*64 + wk)*64 + wq*16 + u*4];
                *(float4*)&swo[wk*68 + wq*16 + u*4] =
                    make_float4(tf32r(o4.x), tf32r(o4.y), tf32r(o4.z), tf32r(o4.w));
            }
            __syncthreads();
            // ---- GEMM1: st[128x64] @ wab[64x128] ----
            float acc1[4][4][4] = {};
            #pragma unroll
            for (int ks = 0; ks < 8; ks++) {
                uint32_t af[4][4], bf[4][2];
                #pragma unroll
                for (int mt = 0; mt < 4; mt++) {
                    const float* ap = st + (wm*64 + mt*16 + group)*68 + ks*8 + tg;
                    af[mt][0] = __float_as_uint(ap[0]);
                    af[mt][1] = __float_as_uint(ap[8*68]);
                    af[mt][2] = __float_as_uint(ap[4]);
                    af[mt][3] = __float_as_uint(ap[8*68 + 4]);
                }
                #pragma unroll
                for (int nt = 0; nt < 4; nt++) {
                    const float* bp = swab + (ks*8 + tg)*132 + wn*32 + nt*8 + group;
                    bf[nt][0] = __float_as_uint(bp[0]);
                    bf[nt][1] = __float_as_uint(bp[4*132]);
                }
                #pragma unroll
                for (int mt = 0; mt < 4; mt++)
                    #pragma unroll
                    for (int nt = 0; nt < 4; nt++)
                        mma16n8k8(acc1[mt][nt], af[mt], bf[nt]);
            }
            // ---- SiLU(a)*b in-register (c0=A, c1=B), h -> smem ----
            #pragma unroll
            for (int mt = 0; mt < 4; mt++) {
                int r1 = wm*64 + mt*16 + group;
                #pragma unroll
                for (int nt = 0; nt < 4; nt++) {
                    int hcol = wn*16 + nt*4 + tg;
                    float a0 = acc1[mt][nt][0], b0v = acc1[mt][nt][1];
                    float a1 = acc1[mt][nt][2], b1v = acc1[mt][nt][3];
                    float h0 = __fdividef(a0, 1.0f + __expf(-a0)) * b0v;
                    float h1 = __fdividef(a1, 1.0f + __expf(-a1)) * b1v;
                    shh[r1*68 + hcol]      = tf32r(h0);
                    shh[(r1+8)*68 + hcol]  = tf32r(h1);
                }
            }
            __syncthreads();
            // ---- GEMM2: shh[128x64] @ swo[64x64], accumulate ----
            #pragma unroll
            for (int ks = 0; ks < 8; ks++) {
                uint32_t af[2][4], bf[4][2];
                #pragma unroll
                for (int mt = 0; mt < 2; mt++) {
                    const float* ap = shh + (wm2*32 + mt*16 + group)*68 + ks*8 + tg;
                    af[mt][0] = __float_as_uint(ap[0]);
                    af[mt][1] = __float_as_uint(ap[8*68]);
                    af[mt][2] = __float_as_uint(ap[4]);
                    af[mt][3] = __float_as_uint(ap[8*68 + 4]);
                }
                #pragma unroll
                for (int nt = 0; nt < 4; nt++) {
                    const float* bp = swo + (ks*8 + tg)*68 + wn2*32 + nt*8 + group;
                    bf[nt][0] = __float_as_uint(bp[0]);
                    bf[nt][1] = __float_as_uint(bp[4*68]);
                }
                #pragma unroll
                for (int mt = 0; mt < 2; mt++)
                    #pragma unroll
                    for (int nt = 0; nt < 4; nt++)
                        mma16n8k8(acc2[mt][nt], af[mt], bf[nt]);
            }
        }
        // ---- residual add + store ----
        #pragma unroll
        for (int mt = 0; mt < 2; mt++) {
            int row = rbase + wm2*32 + mt*16 + group;
            #pragma unroll
            for (int nt = 0; nt < 4; nt++) {
                int col = wn2*32 + nt*8 + tg*2;
                float2 o0 = *(float2*)&out[(size_t)row*64 + col];
                o0.x += acc2[mt][nt][0]; o0.y += acc2[mt][nt][1];
                *(float2*)&out[(size_t)row*64 + col] = o0;
                float2 o1 = *(float2*)&out[(size_t)(row+8)*64 + col];
                o1.x += acc2[mt][nt][2]; o1.y += acc2[mt][nt][3];
                *(float2*)&out[(size_t)(row+8)*64 + col] = o1;
            }
        }
        __syncthreads();  // before st overwrite next tile
    }
}

// ============================================================
extern "C" void kernel_launch(void* const* d_in, const int* in_sizes, int n_in,
                              void* d_out, int out_size) {
    const float* m    = (const float*)d_in[0];
    const float* z    = (const float*)d_in[1];
    const float* lnmg = (const float*)d_in[2];
    const float* lnmb = (const float*)d_in[3];
    const float* Wmv  = (const float*)d_in[4];
    const float* lnzg = (const float*)d_in[5];
    const float* lnzb = (const float*)d_in[6];
    const float* Wz   = (const float*)d_in[7];
    const float* Wmg  = (const float*)d_in[8];
    const float* Wout = (const float*)d_in[9];
    const float* lntg = (const float*)d_in[10];
    const float* lntb = (const float*)d_in[11];
    const float* Wa   = (const float*)d_in[12];
    const float* Wb   = (const float*)d_in[13];
    const float* Wo   = (const float*)d_in[14];
    float* out = (float*)d_out;

    k1_ln_vg<<<1184, 256>>>(m, lnmg, lnmb, Wmv, Wmg);
    k2a_bias<<<(N_DIM*N_DIM)/8, 256>>>(z, lnzg, lnzb, Wz);
    k2b_softmax<<<HH*N_DIM, 256>>>();

    const int k3_smem = (2*128*36 + 2*32*132) * 4;   // 70,656 B
    cudaFuncSetAttribute(k3_mma, cudaFuncAttributeMaxDynamicSharedMemorySize, k3_smem);
    k3_mma<<<dim3(PDIM/128, N_DIM/128, HH), 256, k3_smem>>>();

    const int k4_smem = (64*68 + 256*68) * 4;        // 87,040 B
    cudaFuncSetAttribute(k4_gate_out, cudaFuncAttributeMaxDynamicSharedMemorySize, k4_smem);
    k4_gate_out<<<296, 256, k4_smem>>>(m, Wout, out);

    const int k5_smem = (128*68*2 + 64*132 + 64*68) * 4;   // 120,832 B
    cudaFuncSetAttribute(k5_mma, cudaFuncAttributeMaxDynamicSharedMemorySize, k5_smem);
    k5_mma<<<148, 256, k5_smem>>>(out, lntg, lntb, Wa, Wb, Wo);
    (void)in_sizes; (void)n_in; (void)out_size;
}

// round 8
// speedup vs baseline: 2.1744x; 1.0983x over previous
#include <cuda_runtime.h>
#include <math.h>
#include <stdint.h>

// R8 = R7 resubmit (byte-identical kernels): R7 bench died with
// "GB300 container failed twice" — same infra-flake signature as R0/R5.
// R5/R6 proved identical code flakes then passes; no code change here.

#define S_DIM 1024
#define N_DIM 512
#define CM 64
#define CC 8
#define CZ 128
#define HH 8
#define NROWS (S_DIM*N_DIM)        // 524288
#define PDIM (S_DIM*CC)            // 8192

// ---- scratch ----
__device__ float g_G [(size_t)NROWS*CM];                 // gate, [s*N+i][hc]
__device__ float g_Vt[(size_t)HH*N_DIM*PDIM];            // v^T,  [h][j][p=s*8+c]  (tf32-rounded)
__device__ float g_WV[(size_t)HH*N_DIM*PDIM];            // wv,   [h][i][p]
__device__ float g_Wsm[(size_t)HH*N_DIM*N_DIM];          // softmax w [h][i][j] (tf32-rounded)

__device__ __forceinline__ float tf32r(float x){
    uint32_t u; asm("cvt.rna.tf32.f32 %0, %1;" : "=r"(u) : "f"(x)); return __uint_as_float(u);
}
__device__ __forceinline__ void mma16n8k8(float* c, const uint32_t* a, const uint32_t* b){
    asm volatile("mma.sync.aligned.m16n8k8.row.col.f32.tf32.tf32.f32 "
        "{%0,%1,%2,%3}, {%4,%5,%6,%7}, {%8,%9}, {%0,%1,%2,%3};"
        : "+f"(c[0]), "+f"(c[1]), "+f"(c[2]), "+f"(c[3])
        : "r"(a[0]), "r"(a[1]), "r"(a[2]), "r"(a[3]), "r"(b[0]), "r"(b[1]));
}
__device__ __forceinline__ uint32_t smem_u32(const void* p){
    uint32_t a; asm("{ .reg .u64 t; cvta.to.shared.u64 t, %1; cvt.u32.u64 %0, t; }" : "=r"(a) : "l"(p)); return a;
}
__device__ __forceinline__ void cpasync16(uint32_t saddr, const void* g){
    asm volatile("cp.async.ca.shared.global [%0], [%1], 16;" :: "r"(saddr), "l"(g));
}

// ============================================================
// K1: per 128-row tile: LN -> st; GEMM st @ [Wmv|Wmg] (mma tf32);
//     sigmoid on gate half -> g_G; v half tf32 -> g_Vt [h][j][p].
// ============================================================
__global__ void __launch_bounds__(256,1) k1_mma(
    const float* __restrict__ m, const float* __restrict__ lng, const float* __restrict__ lnb,
    const float* __restrict__ Wmv, const float* __restrict__ Wmg)
{
    extern __shared__ float sh1[];
    float* st   = sh1;               // [128][68] LN'd rows (tf32)
    float* sW   = st + 128*68;       // [64][132] combined [Wmv|Wmg] (tf32)
    float* sout = sW + 64*132;       // [128][132] GEMM output

    int tid = threadIdx.x, wid = tid >> 5, lane = tid & 31;
    int group = lane >> 2, tg = lane & 3;
    int wm = wid >> 2, wn = wid & 3;
    float gm0 = lng[lane], gm1 = lng[lane+32];
    float bt0 = lnb[lane], bt1 = lnb[lane+32];

    int rbase = blockIdx.x*128;
    int ss = rbase >> 9, ii0 = rbase & 511;

    // ---- weights -> smem (tf32) ----
    {
        int wk = tid >> 2, wq = tid & 3;
        float4 a4 = *(const float4*)&Wmv[(size_t)wk*64 + wq*16];
        float4 b4 = *(const float4*)&Wmg[(size_t)wk*64 + wq*16];
        float4 a5 = *(const float4*)&Wmv[(size_t)wk*64 + wq*16 + 4];
        float4 b5 = *(const float4*)&Wmg[(size_t)wk*64 + wq*16 + 4];
        float4 a6 = *(const float4*)&Wmv[(size_t)wk*64 + wq*16 + 8];
        float4 b6 = *(const float4*)&Wmg[(size_t)wk*64 + wq*16 + 8];
        float4 a7 = *(const float4*)&Wmv[(size_t)wk*64 + wq*16 + 12];
        float4 b7 = *(const float4*)&Wmg[(size_t)wk*64 + wq*16 + 12];
        *(float4*)&sW[wk*132 + wq*16]      = make_float4(tf32r(a4.x),tf32r(a4.y),tf32r(a4.z),tf32r(a4.w));
        *(float4*)&sW[wk*132 + wq*16 + 4]  = make_float4(tf32r(a5.x),tf32r(a5.y),tf32r(a5.z),tf32r(a5.w));
        *(float4*)&sW[wk*132 + wq*16 + 8]  = make_float4(tf32r(a6.x),tf32r(a6.y),tf32r(a6.z),tf32r(a6.w));
        *(float4*)&sW[wk*132 + wq*16 + 12] = make_float4(tf32r(a7.x),tf32r(a7.y),tf32r(a7.z),tf32r(a7.w));
        *(float4*)&sW[wk*132 + 64 + wq*16]      = make_float4(tf32r(b4.x),tf32r(b4.y),tf32r(b4.z),tf32r(b4.w));
        *(float4*)&sW[wk*132 + 64 + wq*16 + 4]  = make_float4(tf32r(b5.x),tf32r(b5.y),tf32r(b5.z),tf32r(b5.w));
        *(float4*)&sW[wk*132 + 64 + wq*16 + 8]  = make_float4(tf32r(b6.x),tf32r(b6.y),tf32r(b6.z),tf32r(b6.w));
        *(float4*)&sW[wk*132 + 64 + wq*16 + 12] = make_float4(tf32r(b7.x),tf32r(b7.y),tf32r(b7.z),tf32r(b7.w));
    }
    // ---- load m rows + LN -> st (each warp owns 16 rows) ----
    #pragma unroll 1
    for (int rr = 0; rr < 16; rr += 4) {
        float xs0[4], xs1[4], s[4], q[4];
        #pragma unroll
        for (int u = 0; u < 4; u++) {
            int row = wid*16 + rr + u;
            xs0[u] = m[(size_t)(rbase+row)*64 + lane];
            xs1[u] = m[(size_t)(rbase+row)*64 + 32 + lane];
            s[u] = xs0[u] + xs1[u];
            q[u] = xs0[u]*xs0[u] + xs1[u]*xs1[u];
        }
        #pragma unroll
        for (int o = 16; o > 0; o >>= 1) {
            #pragma unroll
            for (int u = 0; u < 4; u++) {
                s[u] += __shfl_xor_sync(0xffffffffu, s[u], o);
                q[u] += __shfl_xor_sync(0xffffffffu, q[u], o);
            }
        }
        #pragma unroll
        for (int u = 0; u < 4; u++) {
            int row = wid*16 + rr + u;
            float mean = s[u]*(1.0f/64.0f);
            float var  = q[u]*(1.0f/64.0f) - mean*mean;
            float rs = rsqrtf(var + 1e-5f);
            st[row*68 + lane]      = tf32r((xs0[u]-mean)*rs*gm0 + bt0);
            st[row*68 + 32 + lane] = tf32r((xs1[u]-mean)*rs*gm1 + bt1);
        }
    }
    __syncthreads();

    // ---- GEMM: st[128x64] @ sW[64x128] ----
    float acc[4][4][4] = {};
    #pragma unroll
    for (int ks = 0; ks < 8; ks++) {
        uint32_t af[4][4], bf[4][2];
        #pragma unroll
        for (int mt = 0; mt < 4; mt++) {
            const float* ap = st + (wm*64 + mt*16 + group)*68 + ks*8 + tg;
            af[mt][0] = __float_as_uint(ap[0]);
            af[mt][1] = __float_as_uint(ap[8*68]);
            af[mt][2] = __float_as_uint(ap[4]);
            af[mt][3] = __float_as_uint(ap[8*68 + 4]);
        }
        #pragma unroll
        for (int nt = 0; nt < 4; nt++) {
            const float* bp = sW + (ks*8 + tg)*132 + wn*32 + nt*8 + group;
            bf[nt][0] = __float_as_uint(bp[0]);
            bf[nt][1] = __float_as_uint(bp[4*132]);
        }
        #pragma unroll
        for (int mt = 0; mt < 4; mt++)
            #pragma unroll
            for (int nt = 0; nt < 4; nt++)
                mma16n8k8(acc[mt][nt], af[mt], bf[nt]);
    }
    // ---- stage output to smem ----
    #pragma unroll
    for (int mt = 0; mt < 4; mt++) {
        int r1 = wm*64 + mt*16 + group;
        #pragma unroll
        for (int nt = 0; nt < 4; nt++) {
            int col = wn*32 + nt*8 + tg*2;
            *(float2*)&sout[r1*132 + col]     = make_float2(acc[mt][nt][0], acc[mt][nt][1]);
            *(float2*)&sout[(r1+8)*132 + col] = make_float2(acc[mt][nt][2], acc[mt][nt][3]);
        }
    }
    __syncthreads();

    // ---- gate: sigmoid(cols 64..127) -> g_G (coalesced) ----
    #pragma unroll
    for (int u = 0; u < 8; u++) {
        int flat = u*256 + tid;
        int row = flat >> 4, c4 = (flat & 15)*4;
        float4 v = *(const float4*)&sout[row*132 + 64 + c4];
        float4 gv;
        gv.x = __fdividef(1.0f, 1.0f + __expf(-v.x));
        gv.y = __fdividef(1.0f, 1.0f + __expf(-v.y));
        gv.z = __fdividef(1.0f, 1.0f + __expf(-v.z));
        gv.w = __fdividef(1.0f, 1.0f + __expf(-v.w));
        *(float4*)&g_G[(size_t)(rbase+row)*64 + c4] = gv;
    }
    // ---- v: cols 0..63, tf32 -> g_Vt[h][ii0+row][ss*8..+7] (32B chunks) ----
    #pragma unroll
    for (int u = 0; u < 4; u++) {
        int pidx = u*256 + tid;
        int h = pidx >> 7, row = pidx & 127;
        float4 v0 = *(const float4*)&sout[row*132 + h*8];
        float4 v1 = *(const float4*)&sout[row*132 + h*8 + 4];
        size_t off = ((size_t)h*N_DIM + ii0 + row)*PDIM + ss*8;
        *(float4*)&g_Vt[off]     = make_float4(tf32r(v0.x),tf32r(v0.y),tf32r(v0.z),tf32r(v0.w));
        *(float4*)&g_Vt[off + 4] = make_float4(tf32r(v1.x),tf32r(v1.y),tf32r(v1.z),tf32r(v1.w));
    }
}

// ============================================================
// K2a: bias[h][i][j] = LN(z[i,j,:]) @ W_z
// ============================================================
__global__ void __launch_bounds__(256) k2a_bias(
    const float* __restrict__ z, const float* __restrict__ lng, const float* __restrict__ lnb,
    const float* __restrict__ Wz)
{
    int w = (blockIdx.x * 256 + threadIdx.x) >> 5;
    int lane = threadIdx.x & 31;
    if (w >= N_DIM*N_DIM) return;
    int i = w >> 9, j = w & 511;
    const float* zp = z + ((size_t)i*N_DIM + j)*CZ;
    float x0 = zp[lane], x1 = zp[lane+32], x2 = zp[lane+64], x3 = zp[lane+96];
    float s = x0+x1+x2+x3;
    float q = x0*x0 + x1*x1 + x2*x2 + x3*x3;
    #pragma unroll
    for (int o = 16; o > 0; o >>= 1) {
        s += __shfl_xor_sync(0xffffffffu, s, o);
        q += __shfl_xor_sync(0xffffffffu, q, o);
    }
    float mean = s * (1.0f/128.0f);
    float var  = q * (1.0f/128.0f) - mean*mean;
    float rs = rsqrtf(var + 1e-5f);
    float n0 = (x0-mean)*rs*lng[lane]    + lnb[lane];
    float n1 = (x1-mean)*rs*lng[lane+32] + lnb[lane+32];
    float n2 = (x2-mean)*rs*lng[lane+64] + lnb[lane+64];
    float n3 = (x3-mean)*rs*lng[lane+96] + lnb[lane+96];
    float ph[8];
    #pragma unroll
    for (int h = 0; h < 8; h++) {
        float pp = n0*Wz[lane*8+h] + n1*Wz[(lane+32)*8+h]
                 + n2*Wz[(lane+64)*8+h] + n3*Wz[(lane+96)*8+h];
        #pragma unroll
        for (int o = 16; o > 0; o >>= 1) pp += __shfl_xor_sync(0xffffffffu, pp, o);
        ph[h] = pp;
    }
    if (lane == 0) {
        #pragma unroll
        for (int h = 0; h < 8; h++)
            g_Wsm[(size_t)h*N_DIM*N_DIM + (size_t)i*N_DIM + j] = ph[h];
    }
}

// ============================================================
// K2b: softmax over j, tf32-rounded output
// ============================================================
__global__ void __launch_bounds__(256) k2b_softmax()
{
    float* p = g_Wsm + (size_t)blockIdx.x * N_DIM;
    __shared__ float red[256];
    int t = threadIdx.x;
    float v0 = p[t], v1 = p[t+256];
    red[t] = fmaxf(v0, v1);
    __syncthreads();
    for (int s2 = 128; s2 > 0; s2 >>= 1) {
        if (t < s2) red[t] = fmaxf(red[t], red[t+s2]);
        __syncthreads();
    }
    float mx = red[0];
    __syncthreads();
    float e0 = __expf(v0-mx), e1 = __expf(v1-mx);
    red[t] = e0+e1;
    __syncthreads();
    for (int s2 = 128; s2 > 0; s2 >>= 1) {
        if (t < s2) red[t] += red[t+s2];
        __syncthreads();
    }
    float inv = __fdividef(1.0f, red[0]);
    p[t] = tf32r(e0*inv); p[t+256] = tf32r(e1*inv);
}

// ============================================================
// K3: mma.sync tf32 GEMM per head; cp.async staging, 2 CTAs/SM.
// ============================================================
__global__ void __launch_bounds__(256,2) k3_mma()
{
    extern __shared__ float sh3[];
    float* sAs = sh3;                 // 2 x [128][36]
    float* sBs = sh3 + 2*128*36;      // 2 x [32][132]
    uint32_t aS = smem_u32(sAs), bS = smem_u32(sBs);

    int tid = threadIdx.x, wid = tid >> 5, lane = tid & 31;
    int group = lane >> 2, tg = lane & 3;
    int wm = wid >> 2, wn = wid & 3;
    int h  = blockIdx.z;
    int i0 = blockIdx.y * 128;
    int p0 = blockIdx.x * 128;
    const float* A = g_Wsm + (size_t)h*N_DIM*N_DIM;
    const float* B = g_Vt  + (size_t)h*N_DIM*PDIM;
    float*       C = g_WV  + (size_t)h*N_DIM*PDIM;

    int lr = tid >> 3, lc = (tid & 7)*4;

    // prologue: buf0
    #pragma unroll
    for (int u = 0; u < 4; u++)
        cpasync16(aS + (uint32_t)((lr + u*32)*36 + lc)*4, &A[(size_t)(i0+lr+u*32)*N_DIM + lc]);
    #pragma unroll
    for (int u = 0; u < 4; u++)
        cpasync16(bS + (uint32_t)(lr*132 + lc + u*32)*4, &B[(size_t)lr*PDIM + p0 + lc + u*32]);
    asm volatile("cp.async.commit_group;");

    float acc[4][4][4] = {};
    for (int it = 0; it < 16; it++) {
        if (it < 15) {
            int k0 = (it+1)*32;
            uint32_t ao = aS + (uint32_t)(((it+1)&1)*4608*4);
            uint32_t bo = bS + (uint32_t)(((it+1)&1)*4224*4);
            #pragma unroll
            for (int u = 0; u < 4; u++)
                cpasync16(ao + (uint32_t)((lr + u*32)*36 + lc)*4, &A[(size_t)(i0+lr+u*32)*N_DIM + k0 + lc]);
            #pragma unroll
            for (int u = 0; u < 4; u++)
                cpasync16(bo + (uint32_t)(lr*132 + lc + u*32)*4, &B[(size_t)(k0+lr)*PDIM + p0 + lc + u*32]);
            asm volatile("cp.async.commit_group;");
            asm volatile("cp.async.wait_group 1;");
        } else {
            asm volatile("cp.async.wait_group 0;");
        }
        __syncthreads();
        const float* as = sAs + (it&1)*4608;
        const float* bs = sBs + (it&1)*4224;
        #pragma unroll
        for (int ks = 0; ks < 4; ks++) {
            uint32_t af[4][4], bf[4][2];
            #pragma unroll
            for (int mt = 0; mt < 4; mt++) {
                const float* ap = as + (wm*64 + mt*16 + group)*36 + ks*8 + tg;
                af[mt][0] = __float_as_uint(ap[0]);
                af[mt][1] = __float_as_uint(ap[8*36]);
                af[mt][2] = __float_as_uint(ap[4]);
                af[mt][3] = __float_as_uint(ap[8*36 + 4]);
            }
            #pragma unroll
            for (int nt = 0; nt < 4; nt++) {
                const float* bp = bs + (ks*8 + tg)*132 + wn*32 + nt*8 + group;
                bf[nt][0] = __float_as_uint(bp[0]);
                bf[nt][1] = __float_as_uint(bp[4*132]);
            }
            #pragma unroll
            for (int mt = 0; mt < 4; mt++)
                #pragma unroll
                for (int nt = 0; nt < 4; nt++)
                    mma16n8k8(acc[mt][nt], af[mt], bf[nt]);
        }
        __syncthreads();
    }

    #pragma unroll
    for (int mt = 0; mt < 4; mt++) {
        int row = i0 + wm*64 + mt*16 + group;
        #pragma unroll
        for (int nt = 0; nt < 4; nt++) {
            int col = p0 + wn*32 + nt*8 + tg*2;
            *(float2*)&C[(size_t)row*PDIM + col]     = make_float2(acc[mt][nt][0], acc[mt][nt][1]);
            *(float2*)&C[(size_t)(row+8)*PDIM + col] = make_float2(acc[mt][nt][2], acc[mt][nt][3]);
        }
    }
}

// ============================================================
// K4: o = g*wv ; out = m + o @ W_out. (unchanged, passing)
// ============================================================
__global__ void __launch_bounds__(256) k4_gate_out(
    const float* __restrict__ m, const float* __restrict__ Wout, float* __restrict__ out)
{
    extern __shared__ float dyn4[];
    float* sW = dyn4;            // [64][68]
    float* so = sW + 64*68;      // [256][68]
    int tid = threadIdx.x;
    for (int idx = tid; idx < 4096; idx += 256) {
        int k = idx >> 6, c = idx & 63;
        sW[k*68 + c] = Wout[idx];
    }
    int rg = tid >> 3, cg = tid & 7;
    int r0t = rg*8, c0 = cg*8;
    __syncthreads();

    for (int rbase = blockIdx.x*256; rbase < NROWS; rbase += gridDim.x*256) {
        #pragma unroll
        for (int i = 0; i < 16; i++) {
            int flat4 = i*256 + tid;
            int row = flat4 >> 4, c4 = flat4 & 15;
            int r = rbase + row; int ss = r >> 9, ii = r & 511;
            int k0 = c4*4; int hh = k0 >> 3, cc = k0 & 7;
            float4 g4 = *(const float4*)&g_G[(size_t)r*64 + k0];
            float4 w4 = *(const float4*)&g_WV[(((size_t)hh*N_DIM+ii)*S_DIM+ss)*CC + cc];
            float4 s4 = make_float4(g4.x*w4.x, g4.y*w4.y, g4.z*w4.z, g4.w*w4.w);
            *(float4*)&so[row*68 + k0] = s4;
        }
        __syncthreads();

        float acc[8][8] = {};
        #pragma unroll 8
        for (int k = 0; k < 64; k++) {
            float tv[8];
            #pragma unroll
            for (int i = 0; i < 8; i++) tv[i] = so[(r0t+i)*68 + k];
            float4 w0 = *(const float4*)&sW[k*68 + c0];
            float4 w1 = *(const float4*)&sW[k*68 + c0 + 4];
            float wb8[8] = {w0.x,w0.y,w0.z,w0.w,w1.x,w1.y,w1.z,w1.w};
            #pragma unroll
            for (int i = 0; i < 8; i++)
                #pragma unroll
                for (int j = 0; j < 8; j++)
                    acc[i][j] += tv[i]*wb8[j];
        }
        #pragma unroll
        for (int i = 0; i < 8; i++) {
            size_t rowoff = (size_t)(rbase + r0t + i)*64;
            float4 m0 = *(const float4*)&m[rowoff + c0];
            float4 m1 = *(const float4*)&m[rowoff + c0 + 4];
            *(float4*)&out[rowoff + c0]     = make_float4(m0.x+acc[i][0], m0.y+acc[i][1], m0.z+acc[i][2], m0.w+acc[i][3]);
            *(float4*)&out[rowoff + c0 + 4] = make_float4(m1.x+acc[i][4], m1.y+acc[i][5], m1.z+acc[i][6], m1.w+acc[i][7]);
        }
        __syncthreads();
    }
}

// ============================================================
// K5: SwiGLU transition via mma.sync tf32. (unchanged, passing)
// ============================================================
__global__ void __launch_bounds__(256,1) k5_mma(
    float* __restrict__ out, const float* __restrict__ lng, const float* __restrict__ lnb,
    const float* __restrict__ Wa, const float* __restrict__ Wb, const float* __restrict__ Wo)
{
    extern __shared__ float sh5[];
    float* st   = sh5;               // [128][68]
    float* shh  = st  + 128*68;      // [128][68]
    float* swab = shh + 128*68;      // [64][132]
    float* swo  = swab + 64*132;     // [64][68]

    int tid = threadIdx.x, wid = tid >> 5, lane = tid & 31;
    int group = lane >> 2, tg = lane & 3;
    int wm = wid >> 2, wn = wid & 3;
    int wm2 = wid >> 1, wn2 = wid & 1;
    float gm0 = lng[lane], gm1 = lng[lane+32];
    float bt0 = lnb[lane], bt1 = lnb[lane+32];
    int wk = tid >> 2, wq = tid & 3;

    for (int tile = blockIdx.x; tile < NROWS/128; tile += gridDim.x) {
        int rbase = tile*128;
        #pragma unroll 1
        for (int rr = 0; rr < 16; rr += 4) {
            float xs0[4], xs1[4], s[4], q[4];
            #pragma unroll
            for (int u = 0; u < 4; u++) {
                int row = wid*16 + rr + u;
                xs0[u] = out[(size_t)(rbase+row)*64 + lane];
                xs1[u] = out[(size_t)(rbase+row)*64 + 32 + lane];
                s[u] = xs0[u] + xs1[u];
                q[u] = xs0[u]*xs0[u] + xs1[u]*xs1[u];
            }
            #pragma unroll
            for (int o = 16; o > 0; o >>= 1) {
                #pragma unroll
                for (int u = 0; u < 4; u++) {
                    s[u] += __shfl_xor_sync(0xffffffffu, s[u], o);
                    q[u] += __shfl_xor_sync(0xffffffffu, q[u], o);
                }
            }
            #pragma unroll
            for (int u = 0; u < 4; u++) {
                int row = wid*16 + rr + u;
                float mean = s[u]*(1.0f/64.0f);
                float var  = q[u]*(1.0f/64.0f) - mean*mean;
                float rs = rsqrtf(var + 1e-5f);
                st[row*68 + lane]      = tf32r((xs0[u]-mean)*rs*gm0 + bt0);
                st[row*68 + 32 + lane] = tf32r((xs1[u]-mean)*rs*gm1 + bt1);
            }
        }

        float acc2[2][4][4] = {};
        #pragma unroll 1
        for (int hc = 0; hc < 4; hc++) {
            __syncthreads();
            #pragma unroll
            for (int u = 0; u < 4; u++) {
                float4 a4 = *(const float4*)&Wa[(size_t)wk*256 + hc*64 + wq*16 + u*4];
                float4 b4 = *(const float4*)&Wb[(size_t)wk*256 + hc*64 + wq*16 + u*4];
                int base = wk*132 + 2*(wq*16 + u*4);
                swab[base+0] = tf32r(a4.x); swab[base+1] = tf32r(b4.x);
                swab[base+2] = tf32r(a4.y); swab[base+3] = tf32r(b4.y);
                swab[base+4] = tf32r(a4.z); swab[base+5] = tf32r(b4.z);
                swab[base+6] = tf32r(a4.w); swab[base+7] = tf32r(b4.w);
                float4 o4 = *(const float4*)&Wo[(size_t)(hc*64 + wk)*64 + wq*16 + u*4];
                *(float4*)&swo[wk*68 + wq*16 + u*4] =
                    make_float4(tf32r(o4.x), tf32r(o4.y), tf32r(o4.z), tf32r(o4.w));
            }
            __syncthreads();
            float acc1[4][4][4] = {};
            #pragma unroll
            for (int ks = 0; ks < 8; ks++) {
                uint32_t af[4][4], bf[4][2];
                #pragma unroll
                for (int mt = 0; mt < 4; mt++) {
                    const float* ap = st + (wm*64 + mt*16 + group)*68 + ks*8 + tg;
                    af[mt][0] = __float_as_uint(ap[0]);
                    af[mt][1] = __float_as_uint(ap[8*68]);
                    af[mt][2] = __float_as_uint(ap[4]);
                    af[mt][3] = __float_as_uint(ap[8*68 + 4]);
                }
                #pragma unroll
                for (int nt = 0; nt < 4; nt++) {
                    const float* bp = swab + (ks*8 + tg)*132 + wn*32 + nt*8 + group;
                    bf[nt][0] = __float_as_uint(bp[0]);
                    bf[nt][1] = __float_as_uint(bp[4*132]);
                }
                #pragma unroll
                for (int mt = 0; mt < 4; mt++)
                    #pragma unroll
                    for (int nt = 0; nt < 4; nt++)
                        mma16n8k8(acc1[mt][nt], af[mt], bf[nt]);
            }
            #pragma unroll
            for (int mt = 0; mt < 4; mt++) {
                int r1 = wm*64 + mt*16 + group;
                #pragma unroll
                for (int nt = 0; nt < 4; nt++) {
                    int hcol = wn*16 + nt*4 + tg;
                    float a0 = acc1[mt][nt][0], b0v = acc1[mt][nt][1];
                    float a1 = acc1[mt][nt][2], b1v = acc1[mt][nt][3];
                    float h0 = __fdividef(a0, 1.0f + __expf(-a0)) * b0v;
                    float h1 = __fdividef(a1, 1.0f + __expf(-a1)) * b1v;
                    shh[r1*68 + hcol]      = tf32r(h0);
                    shh[(r1+8)*68 + hcol]  = tf32r(h1);
                }
            }
            __syncthreads();
            #pragma unroll
            for (int ks = 0; ks < 8; ks++) {
                uint32_t af[2][4], bf[4][2];
                #pragma unroll
                for (int mt = 0; mt < 2; mt++) {
                    const float* ap = shh + (wm2*32 + mt*16 + group)*68 + ks*8 + tg;
                    af[mt][0] = __float_as_uint(ap[0]);
                    af[mt][1] = __float_as_uint(ap[8*68]);
                    af[mt][2] = __float_as_uint(ap[4]);
                    af[mt][3] = __float_as_uint(ap[8*68 + 4]);
                }
                #pragma unroll
                for (int nt = 0; nt < 4; nt++) {
                    const float* bp = swo + (ks*8 + tg)*68 + wn2*32 + nt*8 + group;
                    bf[nt][0] = __float_as_uint(bp[0]);
                    bf[nt][1] = __float_as_uint(bp[4*68]);
                }
                #pragma unroll
                for (int mt = 0; mt < 2; mt++)
                    #pragma unroll
                    for (int nt = 0; nt < 4; nt++)
                        mma16n8k8(acc2[mt][nt], af[mt], bf[nt]);
            }
        }
        #pragma unroll
        for (int mt = 0; mt < 2; mt++) {
            int row = rbase + wm2*32 + mt*16 + group;
            #pragma unroll
            for (int nt = 0; nt < 4; nt++) {
                int col = wn2*32 + nt*8 + tg*2;
                float2 o0 = *(float2*)&out[(size_t)row*64 + col];
                o0.x += acc2[mt][nt][0]; o0.y += acc2[mt][nt][1];
                *(float2*)&out[(size_t)row*64 + col] = o0;
                float2 o1 = *(float2*)&out[(size_t)(row+8)*64 + col];
                o1.x += acc2[mt][nt][2]; o1.y += acc2[mt][nt][3];
                *(float2*)&out[(size_t)(row+8)*64 + col] = o1;
            }
        }
        __syncthreads();
    }
}

// ============================================================
extern "C" void kernel_launch(void* const* d_in, const int* in_sizes, int n_in,
                              void* d_out, int out_size) {
    const float* m    = (const float*)d_in[0];
    const float* z    = (const float*)d_in[1];
    const float* lnmg = (const float*)d_in[2];
    const float* lnmb = (const float*)d_in[3];
    const float* Wmv  = (const float*)d_in[4];
    const float* lnzg = (const float*)d_in[5];
    const float* lnzb = (const float*)d_in[6];
    const float* Wz   = (const float*)d_in[7];
    const float* Wmg  = (const float*)d_in[8];
    const float* Wout = (const float*)d_in[9];
    const float* lntg = (const float*)d_in[10];
    const float* lntb = (const float*)d_in[11];
    const float* Wa   = (const float*)d_in[12];
    const float* Wb   = (const float*)d_in[13];
    const float* Wo   = (const float*)d_in[14];
    float* out = (float*)d_out;

    const int k1_smem = (128*68 + 64*132 + 128*132) * 4;   // 136,192 B
    cudaFuncSetAttribute(k1_mma, cudaFuncAttributeMaxDynamicSharedMemorySize, k1_smem);
    k1_mma<<<NROWS/128, 256, k1_smem>>>(m, lnmg, lnmb, Wmv, Wmg);

    k2a_bias<<<(N_DIM*N_DIM)/8, 256>>>(z, lnzg, lnzb, Wz);
    k2b_softmax<<<HH*N_DIM, 256>>>();

    const int k3_smem = (2*128*36 + 2*32*132) * 4;   // 70,656 B
    cudaFuncSetAttribute(k3_mma, cudaFuncAttributeMaxDynamicSharedMemorySize, k3_smem);
    k3_mma<<<dim3(PDIM/128, N_DIM/128, HH), 256, k3_smem>>>();

    const int k4_smem = (64*68 + 256*68) * 4;        // 87,040 B
    cudaFuncSetAttribute(k4_gate_out, cudaFuncAttributeMaxDynamicSharedMemorySize, k4_smem);
    k4_gate_out<<<296, 256, k4_smem>>>(m, Wout, out);

    const int k5_smem = (128*68*2 + 64*132 + 64*68) * 4;   // 120,832 B
    cudaFuncSetAttribute(k5_mma, cudaFuncAttributeMaxDynamicSharedMemorySize, k5_smem);
    k5_mma<<<148, 256, k5_smem>>>(out, lntg, lntb, Wa, Wb, Wo);
    (void)in_sizes; (void)n_in; (void)out_size;
}

// round 10
// speedup vs baseline: 2.3458x; 1.0788x over previous
#include <cuda_runtime.h>
#include <math.h>
#include <stdint.h>

#define S_DIM 1024
#define N_DIM 512
#define CM 64
#define CC 8
#define CZ 128
#define HH 8
#define NROWS (S_DIM*N_DIM)        // 524288
#define PDIM (S_DIM*CC)            // 8192

// ---- scratch ----
__device__ float g_G [(size_t)NROWS*CM];                 // gate, [s*N+i][hc]
__device__ float g_Vt[(size_t)HH*N_DIM*PDIM];            // v^T,  [h][j][p=s*8+c]  (tf32-rounded)
__device__ float g_WV[(size_t)HH*N_DIM*PDIM];            // wv,   [h][i][p]
__device__ float g_Wsm[(size_t)HH*N_DIM*N_DIM];          // softmax w [h][i][j] (tf32-rounded)

__device__ __forceinline__ float tf32r(float x){
    uint32_t u; asm("cvt.rna.tf32.f32 %0, %1;" : "=r"(u) : "f"(x)); return __uint_as_float(u);
}
__device__ __forceinline__ void mma16n8k8(float* c, const uint32_t* a, const uint32_t* b){
    asm volatile("mma.sync.aligned.m16n8k8.row.col.f32.tf32.tf32.f32 "
        "{%0,%1,%2,%3}, {%4,%5,%6,%7}, {%8,%9}, {%0,%1,%2,%3};"
        : "+f"(c[0]), "+f"(c[1]), "+f"(c[2]), "+f"(c[3])
        : "r"(a[0]), "r"(a[1]), "r"(a[2]), "r"(a[3]), "r"(b[0]), "r"(b[1]));
}
__device__ __forceinline__ uint32_t smem_u32(const void* p){
    uint32_t a; asm("{ .reg .u64 t; cvta.to.shared.u64 t, %1; cvt.u32.u64 %0, t; }" : "=r"(a) : "l"(p)); return a;
}
__device__ __forceinline__ void cpasync16(uint32_t saddr, const void* g){
    asm volatile("cp.async.ca.shared.global [%0], [%1], 16;" :: "r"(saddr), "l"(g));
}

// ============================================================
// K1: per 128-row tile: LN -> st; GEMM st @ [Wmv|Wmg] (mma tf32);
//     sigmoid gate -> g_G; v half tf32 -> g_Vt [h][j][p].
// A stride 68 (64 data cols, ==4 mod 32); B stride 136 (==8 mod 32).
// ============================================================
__global__ void __launch_bounds__(256,1) k1_mma(
    const float* __restrict__ m, const float* __restrict__ lng, const float* __restrict__ lnb,
    const float* __restrict__ Wmv, const float* __restrict__ Wmg)
{
    extern __shared__ float sh1[];
    float* st   = sh1;               // [128][68] LN'd rows (tf32)
    float* sW   = st + 128*68;       // [64][136] combined [Wmv|Wmg] (tf32)
    float* sout = sW + 64*136;       // [128][132] GEMM output

    int tid = threadIdx.x, wid = tid >> 5, lane = tid & 31;
    int group = lane >> 2, tg = lane & 3;
    int wm = wid >> 2, wn = wid & 3;
    float gm0 = lng[lane], gm1 = lng[lane+32];
    float bt0 = lnb[lane], bt1 = lnb[lane+32];

    int rbase = blockIdx.x*128;
    int ss = rbase >> 9, ii0 = rbase & 511;

    // ---- weights -> smem (tf32) ----
    {
        int wk = tid >> 2, wq = tid & 3;
        #pragma unroll
        for (int u = 0; u < 4; u++) {
            float4 a4 = *(const float4*)&Wmv[(size_t)wk*64 + wq*16 + u*4];
            float4 b4 = *(const float4*)&Wmg[(size_t)wk*64 + wq*16 + u*4];
            *(float4*)&sW[wk*136 + wq*16 + u*4] =
                make_float4(tf32r(a4.x),tf32r(a4.y),tf32r(a4.z),tf32r(a4.w));
            *(float4*)&sW[wk*136 + 64 + wq*16 + u*4] =
                make_float4(tf32r(b4.x),tf32r(b4.y),tf32r(b4.z),tf32r(b4.w));
        }
    }
    // ---- load m rows + LN -> st ----
    #pragma unroll 1
    for (int rr = 0; rr < 16; rr += 4) {
        float xs0[4], xs1[4], s[4], q[4];
        #pragma unroll
        for (int u = 0; u < 4; u++) {
            int row = wid*16 + rr + u;
            xs0[u] = m[(size_t)(rbase+row)*64 + lane];
            xs1[u] = m[(size_t)(rbase+row)*64 + 32 + lane];
            s[u] = xs0[u] + xs1[u];
            q[u] = xs0[u]*xs0[u] + xs1[u]*xs1[u];
        }
        #pragma unroll
        for (int o = 16; o > 0; o >>= 1) {
            #pragma unroll
            for (int u = 0; u < 4; u++) {
                s[u] += __shfl_xor_sync(0xffffffffu, s[u], o);
                q[u] += __shfl_xor_sync(0xffffffffu, q[u], o);
            }
        }
        #pragma unroll
        for (int u = 0; u < 4; u++) {
            int row = wid*16 + rr + u;
            float mean = s[u]*(1.0f/64.0f);
            float var  = q[u]*(1.0f/64.0f) - mean*mean;
            float rs = rsqrtf(var + 1e-5f);
            st[row*68 + lane]      = tf32r((xs0[u]-mean)*rs*gm0 + bt0);
            st[row*68 + 32 + lane] = tf32r((xs1[u]-mean)*rs*gm1 + bt1);
        }
    }
    __syncthreads();

    // ---- GEMM: st[128x64] @ sW[64x128] ----
    float acc[4][4][4] = {};
    #pragma unroll
    for (int ks = 0; ks < 8; ks++) {
        uint32_t af[4][4], bf[4][2];
        #pragma unroll
        for (int mt = 0; mt < 4; mt++) {
            const float* ap = st + (wm*64 + mt*16 + group)*68 + ks*8 + tg;
            af[mt][0] = __float_as_uint(ap[0]);
            af[mt][1] = __float_as_uint(ap[8*68]);
            af[mt][2] = __float_as_uint(ap[4]);
            af[mt][3] = __float_as_uint(ap[8*68 + 4]);
        }
        #pragma unroll
        for (int nt = 0; nt < 4; nt++) {
            const float* bp = sW + (ks*8 + tg)*136 + wn*32 + nt*8 + group;
            bf[nt][0] = __float_as_uint(bp[0]);
            bf[nt][1] = __float_as_uint(bp[4*136]);
        }
        #pragma unroll
        for (int mt = 0; mt < 4; mt++)
            #pragma unroll
            for (int nt = 0; nt < 4; nt++)
                mma16n8k8(acc[mt][nt], af[mt], bf[nt]);
    }
    // ---- stage output to smem ----
    #pragma unroll
    for (int mt = 0; mt < 4; mt++) {
        int r1 = wm*64 + mt*16 + group;
        #pragma unroll
        for (int nt = 0; nt < 4; nt++) {
            int col = wn*32 + nt*8 + tg*2;
            *(float2*)&sout[r1*132 + col]     = make_float2(acc[mt][nt][0], acc[mt][nt][1]);
            *(float2*)&sout[(r1+8)*132 + col] = make_float2(acc[mt][nt][2], acc[mt][nt][3]);
        }
    }
    __syncthreads();

    // ---- gate: sigmoid(cols 64..127) -> g_G ----
    #pragma unroll
    for (int u = 0; u < 8; u++) {
        int flat = u*256 + tid;
        int row = flat >> 4, c4 = (flat & 15)*4;
        float4 v = *(const float4*)&sout[row*132 + 64 + c4];
        float4 gv;
        gv.x = __fdividef(1.0f, 1.0f + __expf(-v.x));
        gv.y = __fdividef(1.0f, 1.0f + __expf(-v.y));
        gv.z = __fdividef(1.0f, 1.0f + __expf(-v.z));
        gv.w = __fdividef(1.0f, 1.0f + __expf(-v.w));
        *(float4*)&g_G[(size_t)(rbase+row)*64 + c4] = gv;
    }
    // ---- v: cols 0..63, tf32 -> g_Vt[h][ii0+row][ss*8..+7] ----
    #pragma unroll
    for (int u = 0; u < 4; u++) {
        int pidx = u*256 + tid;
        int h = pidx >> 7, row = pidx & 127;
        float4 v0 = *(const float4*)&sout[row*132 + h*8];
        float4 v1 = *(const float4*)&sout[row*132 + h*8 + 4];
        size_t off = ((size_t)h*N_DIM + ii0 + row)*PDIM + ss*8;
        *(float4*)&g_Vt[off]     = make_float4(tf32r(v0.x),tf32r(v0.y),tf32r(v0.z),tf32r(v0.w));
        *(float4*)&g_Vt[off + 4] = make_float4(tf32r(v1.x),tf32r(v1.y),tf32r(v1.z),tf32r(v1.w));
    }
}

// ============================================================
// K2a: bias[h][i][j] = LN(z[i,j,:]) @ W_z
// ============================================================
__global__ void __launch_bounds__(256) k2a_bias(
    const float* __restrict__ z, const float* __restrict__ lng, const float* __restrict__ lnb,
    const float* __restrict__ Wz)
{
    int w = (blockIdx.x * 256 + threadIdx.x) >> 5;
    int lane = threadIdx.x & 31;
    if (w >= N_DIM*N_DIM) return;
    int i = w >> 9, j = w & 511;
    const float* zp = z + ((size_t)i*N_DIM + j)*CZ;
    float x0 = zp[lane], x1 = zp[lane+32], x2 = zp[lane+64], x3 = zp[lane+96];
    float s = x0+x1+x2+x3;
    float q = x0*x0 + x1*x1 + x2*x2 + x3*x3;
    #pragma unroll
    for (int o = 16; o > 0; o >>= 1) {
        s += __shfl_xor_sync(0xffffffffu, s, o);
        q += __shfl_xor_sync(0xffffffffu, q, o);
    }
    float mean = s * (1.0f/128.0f);
    float var  = q * (1.0f/128.0f) - mean*mean;
    float rs = rsqrtf(var + 1e-5f);
    float n0 = (x0-mean)*rs*lng[lane]    + lnb[lane];
    float n1 = (x1-mean)*rs*lng[lane+32] + lnb[lane+32];
    float n2 = (x2-mean)*rs*lng[lane+64] + lnb[lane+64];
    float n3 = (x3-mean)*rs*lng[lane+96] + lnb[lane+96];
    float ph[8];
    #pragma unroll
    for (int h = 0; h < 8; h++) {
        float pp = n0*Wz[lane*8+h] + n1*Wz[(lane+32)*8+h]
                 + n2*Wz[(lane+64)*8+h] + n3*Wz[(lane+96)*8+h];
        #pragma unroll
        for (int o = 16; o > 0; o >>= 1) pp += __shfl_xor_sync(0xffffffffu, pp, o);
        ph[h] = pp;
    }
    if (lane == 0) {
        #pragma unroll
        for (int h = 0; h < 8; h++)
            g_Wsm[(size_t)h*N_DIM*N_DIM + (size_t)i*N_DIM + j] = ph[h];
    }
}

// ============================================================
// K2b: softmax over j, tf32-rounded output
// ============================================================
__global__ void __launch_bounds__(256) k2b_softmax()
{
    float* p = g_Wsm + (size_t)blockIdx.x * N_DIM;
    __shared__ float red[256];
    int t = threadIdx.x;
    float v0 = p[t], v1 = p[t+256];
    red[t] = fmaxf(v0, v1);
    __syncthreads();
    for (int s2 = 128; s2 > 0; s2 >>= 1) {
        if (t < s2) red[t] = fmaxf(red[t], red[t+s2]);
        __syncthreads();
    }
    float mx = red[0];
    __syncthreads();
    float e0 = __expf(v0-mx), e1 = __expf(v1-mx);
    red[t] = e0+e1;
    __syncthreads();
    for (int s2 = 128; s2 > 0; s2 >>= 1) {
        if (t < s2) red[t] += red[t+s2];
        __syncthreads();
    }
    float inv = __fdividef(1.0f, red[0]);
    p[t] = tf32r(e0*inv); p[t+256] = tf32r(e1*inv);
}

// ============================================================
// K3: mma.sync tf32 GEMM per head; cp.async, 2 CTAs/SM.
// A chunks 32-wide (stride 36 ok), B stride 136.
// ============================================================
__global__ void __launch_bounds__(256,2) k3_mma()
{
    extern __shared__ float sh3[];
    float* sAs = sh3;                 // 2 x [128][36]
    float* sBs = sh3 + 2*128*36;      // 2 x [32][136]
    uint32_t aS = smem_u32(sAs), bS = smem_u32(sBs);

    int tid = threadIdx.x, wid = tid >> 5, lane = tid & 31;
    int group = lane >> 2, tg = lane & 3;
    int wm = wid >> 2, wn = wid & 3;
    int h  = blockIdx.z;
    int i0 = blockIdx.y * 128;
    int p0 = blockIdx.x * 128;
    const float* A = g_Wsm + (size_t)h*N_DIM*N_DIM;
    const float* B = g_Vt  + (size_t)h*N_DIM*PDIM;
    float*       C = g_WV  + (size_t)h*N_DIM*PDIM;

    int lr = tid >> 3, lc = (tid & 7)*4;

    #pragma unroll
    for (int u = 0; u < 4; u++)
        cpasync16(aS + (uint32_t)((lr + u*32)*36 + lc)*4, &A[(size_t)(i0+lr+u*32)*N_DIM + lc]);
    #pragma unroll
    for (int u = 0; u < 4; u++)
        cpasync16(bS + (uint32_t)(lr*136 + lc + u*32)*4, &B[(size_t)lr*PDIM + p0 + lc + u*32]);
    asm volatile("cp.async.commit_group;");

    float acc[4][4][4] = {};
    for (int it = 0; it < 16; it++) {
        if (it < 15) {
            int k0 = (it+1)*32;
            uint32_t ao = aS + (uint32_t)(((it+1)&1)*4608*4);
            uint32_t bo = bS + (uint32_t)(((it+1)&1)*4352*4);
            #pragma unroll
            for (int u = 0; u < 4; u++)
                cpasync16(ao + (uint32_t)((lr + u*32)*36 + lc)*4, &A[(size_t)(i0+lr+u*32)*N_DIM + k0 + lc]);
            #pragma unroll
            for (int u = 0; u < 4; u++)
                cpasync16(bo + (uint32_t)(lr*136 + lc + u*32)*4, &B[(size_t)(k0+lr)*PDIM + p0 + lc + u*32]);
            asm volatile("cp.async.commit_group;");
            asm volatile("cp.async.wait_group 1;");
        } else {
            asm volatile("cp.async.wait_group 0;");
        }
        __syncthreads();
        const float* as = sAs + (it&1)*4608;
        const float* bs = sBs + (it&1)*4352;
        #pragma unroll
        for (int ks = 0; ks < 4; ks++) {
            uint32_t af[4][4], bf[4][2];
            #pragma unroll
            for (int mt = 0; mt < 4; mt++) {
                const float* ap = as + (wm*64 + mt*16 + group)*36 + ks*8 + tg;
                af[mt][0] = __float_as_uint(ap[0]);
                af[mt][1] = __float_as_uint(ap[8*36]);
                af[mt][2] = __float_as_uint(ap[4]);
                af[mt][3] = __float_as_uint(ap[8*36 + 4]);
            }
            #pragma unroll
            for (int nt = 0; nt < 4; nt++) {
                const float* bp = bs + (ks*8 + tg)*136 + wn*32 + nt*8 + group;
                bf[nt][0] = __float_as_uint(bp[0]);
                bf[nt][1] = __float_as_uint(bp[4*136]);
            }
            #pragma unroll
            for (int mt = 0; mt < 4; mt++)
                #pragma unroll
                for (int nt = 0; nt < 4; nt++)
                    mma16n8k8(acc[mt][nt], af[mt], bf[nt]);
        }
        __syncthreads();
    }

    #pragma unroll
    for (int mt = 0; mt < 4; mt++) {
        int row = i0 + wm*64 + mt*16 + group;
        #pragma unroll
        for (int nt = 0; nt < 4; nt++) {
            int col = p0 + wn*32 + nt*8 + tg*2;
            *(float2*)&C[(size_t)row*PDIM + col]     = make_float2(acc[mt][nt][0], acc[mt][nt][1]);
            *(float2*)&C[(size_t)(row+8)*PDIM + col] = make_float2(acc[mt][nt][2], acc[mt][nt][3]);
        }
    }
}

// ============================================================
// K4: mma.sync. Per 128-row tile: st = tf32(g*wv); out = m + st @ Wout.
// st stride 68 (64 data cols), Wout stride 72.
// ============================================================
__global__ void __launch_bounds__(256) k4_mma(
    const float* __restrict__ m, const float* __restrict__ Wout, float* __restrict__ out)
{
    extern __shared__ float sh4[];
    float* st = sh4;             // [128][68] gated product (tf32)
    float* sW = st + 128*68;     // [64][72]  Wout (tf32)

    int tid = threadIdx.x, wid = tid >> 5, lane = tid & 31;
    int group = lane >> 2, tg = lane & 3;
    int wm2 = wid >> 1, wn2 = wid & 1;
    int rbase = blockIdx.x*128;
    int ss = rbase >> 9, ii0 = rbase & 511;

    // ---- Wout -> sW (tf32) ----
    {
        int wk = tid >> 2, wq = tid & 3;
        #pragma unroll
        for (int u = 0; u < 4; u++) {
            float4 w4 = *(const float4*)&Wout[(size_t)wk*64 + wq*16 + u*4];
            *(float4*)&sW[wk*72 + wq*16 + u*4] =
                make_float4(tf32r(w4.x),tf32r(w4.y),tf32r(w4.z),tf32r(w4.w));
        }
    }
    // ---- o = g*wv -> st (tf32) ----
    #pragma unroll
    for (int i = 0; i < 8; i++) {
        int flat4 = i*256 + tid;
        int row = flat4 >> 4, c4 = flat4 & 15;
        int k0 = c4*4; int hh = k0 >> 3, cc = k0 & 7;
        float4 g4 = *(const float4*)&g_G[(size_t)(rbase+row)*64 + k0];
        float4 w4 = *(const float4*)&g_WV[((size_t)hh*N_DIM + ii0 + row)*PDIM + ss*8 + cc];
        *(float4*)&st[row*68 + k0] = make_float4(
            tf32r(g4.x*w4.x), tf32r(g4.y*w4.y), tf32r(g4.z*w4.z), tf32r(g4.w*w4.w));
    }
    __syncthreads();

    // ---- GEMM: st[128x64] @ sW[64x64] ----
    float acc[2][4][4] = {};
    #pragma unroll
    for (int ks = 0; ks < 8; ks++) {
        uint32_t af[2][4], bf[4][2];
        #pragma unroll
        for (int mt = 0; mt < 2; mt++) {
            const float* ap = st + (wm2*32 + mt*16 + group)*68 + ks*8 + tg;
            af[mt][0] = __float_as_uint(ap[0]);
            af[mt][1] = __float_as_uint(ap[8*68]);
            af[mt][2] = __float_as_uint(ap[4]);
            af[mt][3] = __float_as_uint(ap[8*68 + 4]);
        }
        #pragma unroll
        for (int nt = 0; nt < 4; nt++) {
            const float* bp = sW + (ks*8 + tg)*72 + wn2*32 + nt*8 + group;
            bf[nt][0] = __float_as_uint(bp[0]);
            bf[nt][1] = __float_as_uint(bp[4*72]);
        }
        #pragma unroll
        for (int mt = 0; mt < 2; mt++)
            #pragma unroll
            for (int nt = 0; nt < 4; nt++)
                mma16n8k8(acc[mt][nt], af[mt], bf[nt]);
    }
    // ---- residual + store ----
    #pragma unroll
    for (int mt = 0; mt < 2; mt++) {
        int row = rbase + wm2*32 + mt*16 + group;
        #pragma unroll
        for (int nt = 0; nt < 4; nt++) {
            int col = wn2*32 + nt*8 + tg*2;
            float2 m0 = *(const float2*)&m[(size_t)row*64 + col];
            *(float2*)&out[(size_t)row*64 + col] =
                make_float2(m0.x + acc[mt][nt][0], m0.y + acc[mt][nt][1]);
            float2 m1 = *(const float2*)&m[(size_t)(row+8)*64 + col];
            *(float2*)&out[(size_t)(row+8)*64 + col] =
                make_float2(m1.x + acc[mt][nt][2], m1.y + acc[mt][nt][3]);
        }
    }
}

// ============================================================
// K5: SwiGLU transition via mma.sync tf32 (R6/R8-proven structure;
// only B strides updated: swab 136, swo 72).
// ============================================================
__global__ void __launch_bounds__(256,1) k5_mma(
    float* __restrict__ out, const float* __restrict__ lng, const float* __restrict__ lnb,
    const float* __restrict__ Wa, const float* __restrict__ Wb, const float* __restrict__ Wo)
{
    extern __shared__ float sh5[];
    float* st   = sh5;               // [128][68]
    float* shh  = st  + 128*68;      // [128][68]
    float* swab = shh + 128*68;      // [64][136] interleaved Wa|Wb chunk
    float* swo  = swab + 64*136;     // [64][72]  Wo chunk

    int tid = threadIdx.x, wid = tid >> 5, lane = tid & 31;
    int group = lane >> 2, tg = lane & 3;
    int wm = wid >> 2, wn = wid & 3;       // GEMM1: 2(M) x 4(N)
    int wm2 = wid >> 1, wn2 = wid & 1;     // GEMM2: 4(M) x 2(N)
    float gm0 = lng[lane], gm1 = lng[lane+32];
    float bt0 = lnb[lane], bt1 = lnb[lane+32];
    int wk = tid >> 2, wq = tid & 3;

    for (int tile = blockIdx.x; tile < NROWS/128; tile += gridDim.x) {
        int rbase = tile*128;
        // ---- load + LN -> st ----
        #pragma unroll 1
        for (int rr = 0; rr < 16; rr += 4) {
            float xs0[4], xs1[4], s[4], q[4];
            #pragma unroll
            for (int u = 0; u < 4; u++) {
                int row = wid*16 + rr + u;
                xs0[u] = out[(size_t)(rbase+row)*64 + lane];
                xs1[u] = out[(size_t)(rbase+row)*64 + 32 + lane];
                s[u] = xs0[u] + xs1[u];
                q[u] = xs0[u]*xs0[u] + xs1[u]*xs1[u];
            }
            #pragma unroll
            for (int o = 16; o > 0; o >>= 1) {
                #pragma unroll
                for (int u = 0; u < 4; u++) {
                    s[u] += __shfl_xor_sync(0xffffffffu, s[u], o);
                    q[u] += __shfl_xor_sync(0xffffffffu, q[u], o);
                }
            }
            #pragma unroll
            for (int u = 0; u < 4; u++) {
                int row = wid*16 + rr + u;
                float mean = s[u]*(1.0f/64.0f);
                float var  = q[u]*(1.0f/64.0f) - mean*mean;
                float rs = rsqrtf(var + 1e-5f);
                st[row*68 + lane]      = tf32r((xs0[u]-mean)*rs*gm0 + bt0);
                st[row*68 + 32 + lane] = tf32r((xs1[u]-mean)*rs*gm1 + bt1);
            }
        }

        float acc2[2][4][4] = {};
        #pragma unroll 1
        for (int hc = 0; hc < 4; hc++) {
            __syncthreads();  // st ready / prev GEMM2 done with shh+weights
            // ---- stream weight chunk: Wa|Wb interleaved, Wo rows ----
            #pragma unroll
            for (int u = 0; u < 4; u++) {
                float4 a4 = *(const float4*)&Wa[(size_t)wk*256 + hc*64 + wq*16 + u*4];
                float4 b4 = *(const float4*)&Wb[(size_t)wk*256 + hc*64 + wq*16 + u*4];
                int base = wk*136 + 2*(wq*16 + u*4);
                swab[base+0] = tf32r(a4.x); swab[base+1] = tf32r(b4.x);
                swab[base+2] = tf32r(a4.y); swab[base+3] = tf32r(b4.y);
                swab[base+4] = tf32r(a4.z); swab[base+5] = tf32r(b4.z);
                swab[base+6] = tf32r(a4.w); swab[base+7] = tf32r(b4.w);
                float4 o4 = *(const float4*)&Wo[(size_t)(hc*64 + wk)*64 + wq*16 + u*4];
                *(float4*)&swo[wk*72 + wq*16 + u*4] =
                    make_float4(tf32r(o4.x), tf32r(o4.y), tf32r(o4.z), tf32r(o4.w));
            }
            __syncthreads();
            // ---- GEMM1: st[128x64] @ wab[64x128] ----
            float acc1[4][4][4] = {};
            #pragma unroll
            for (int ks = 0; ks < 8; ks++) {
                uint32_t af[4][4], bf[4][2];
                #pragma unroll
                for (int mt = 0; mt < 4; mt++) {
                    const float* ap = st + (wm*64 + mt*16 + group)*68 + ks*8 + tg;
                    af[mt][0] = __float_as_uint(ap[0]);
                    af[mt][1] = __float_as_uint(ap[8*68]);
                    af[mt][2] = __float_as_uint(ap[4]);
                    af[mt][3] = __float_as_uint(ap[8*68 + 4]);
                }
                #pragma unroll
                for (int nt = 0; nt < 4; nt++) {
                    const float* bp = swab + (ks*8 + tg)*136 + wn*32 + nt*8 + group;
                    bf[nt][0] = __float_as_uint(bp[0]);
                    bf[nt][1] = __float_as_uint(bp[4*136]);
                }
                #pragma unroll
                for (int mt = 0; mt < 4; mt++)
                    #pragma unroll
                    for (int nt = 0; nt < 4; nt++)
                        mma16n8k8(acc1[mt][nt], af[mt], bf[nt]);
            }
            // ---- SiLU(a)*b in-register (c0=A, c1=B), h -> shh ----
            #pragma unroll
            for (int mt = 0; mt < 4; mt++) {
                int r1 = wm*64 + mt*16 + group;
                #pragma unroll
                for (int nt = 0; nt < 4; nt++) {
                    int hcol = wn*16 + nt*4 + tg;
                    float a0 = acc1[mt][nt][0], b0v = acc1[mt][nt][1];
                    float a1 = acc1[mt][nt][2], b1v = acc1[mt][nt][3];
                    float h0 = __fdividef(a0, 1.0f + __expf(-a0)) * b0v;
                    float h1 = __fdividef(a1, 1.0f + __expf(-a1)) * b1v;
                    shh[r1*68 + hcol]      = tf32r(h0);
                    shh[(r1+8)*68 + hcol]  = tf32r(h1);
                }
            }
            __syncthreads();
            // ---- GEMM2: shh[128x64] @ swo[64x64], accumulate ----
            #pragma unroll
            for (int ks = 0; ks < 8; ks++) {
                uint32_t af[2][4], bf[4][2];
                #pragma unroll
                for (int mt = 0; mt < 2; mt++) {
                    const float* ap = shh + (wm2*32 + mt*16 + group)*68 + ks*8 + tg;
                    af[mt][0] = __float_as_uint(ap[0]);
                    af[mt][1] = __float_as_uint(ap[8*68]);
                    af[mt][2] = __float_as_uint(ap[4]);
                    af[mt][3] = __float_as_uint(ap[8*68 + 4]);
                }
                #pragma unroll
                for (int nt = 0; nt < 4; nt++) {
                    const float* bp = swo + (ks*8 + tg)*72 + wn2*32 + nt*8 + group;
                    bf[nt][0] = __float_as_uint(bp[0]);
                    bf[nt][1] = __float_as_uint(bp[4*72]);
                }
                #pragma unroll
                for (int mt = 0; mt < 2; mt++)
                    #pragma unroll
                    for (int nt = 0; nt < 4; nt++)
                        mma16n8k8(acc2[mt][nt], af[mt], bf[nt]);
            }
        }
        // ---- residual add + store ----
        #pragma unroll
        for (int mt = 0; mt < 2; mt++) {
            int row = rbase + wm2*32 + mt*16 + group;
            #pragma unroll
            for (int nt = 0; nt < 4; nt++) {
                int col = wn2*32 + nt*8 + tg*2;
                float2 o0 = *(float2*)&out[(size_t)row*64 + col];
                o0.x += acc2[mt][nt][0]; o0.y += acc2[mt][nt][1];
                *(float2*)&out[(size_t)row*64 + col] = o0;
                float2 o1 = *(float2*)&out[(size_t)(row+8)*64 + col];
                o1.x += acc2[mt][nt][2]; o1.y += acc2[mt][nt][3];
                *(float2*)&out[(size_t)(row+8)*64 + col] = o1;
            }
        }
        __syncthreads();
    }
}

// ============================================================
extern "C" void kernel_launch(void* const* d_in, const int* in_sizes, int n_in,
                              void* d_out, int out_size) {
    const float* m    = (const float*)d_in[0];
    const float* z    = (const float*)d_in[1];
    const float* lnmg = (const float*)d_in[2];
    const float* lnmb = (const float*)d_in[3];
    const float* Wmv  = (const float*)d_in[4];
    const float* lnzg = (const float*)d_in[5];
    const float* lnzb = (const float*)d_in[6];
    const float* Wz   = (const float*)d_in[7];
    const float* Wmg  = (const float*)d_in[8];
    const float* Wout = (const float*)d_in[9];
    const float* lntg = (const float*)d_in[10];
    const float* lntb = (const float*)d_in[11];
    const float* Wa   = (const float*)d_in[12];
    const float* Wb   = (const float*)d_in[13];
    const float* Wo   = (const float*)d_in[14];
    float* out = (float*)d_out;

    const int k1_smem = (128*68 + 64*136 + 128*132) * 4;   // 137,216 B
    cudaFuncSetAttribute(k1_mma, cudaFuncAttributeMaxDynamicSharedMemorySize, k1_smem);
    k1_mma<<<NROWS/128, 256, k1_smem>>>(m, lnmg, lnmb, Wmv, Wmg);

    k2a_bias<<<(N_DIM*N_DIM)/8, 256>>>(z, lnzg, lnzb, Wz);
    k2b_softmax<<<HH*N_DIM, 256>>>();

    const int k3_smem = (2*128*36 + 2*32*136) * 4;   // 71,680 B
    cudaFuncSetAttribute(k3_mma, cudaFuncAttributeMaxDynamicSharedMemorySize, k3_smem);
    k3_mma<<<dim3(PDIM/128, N_DIM/128, HH), 256, k3_smem>>>();

    const int k4_smem = (128*68 + 64*72) * 4;        // 53,248 B
    cudaFuncSetAttribute(k4_mma, cudaFuncAttributeMaxDynamicSharedMemorySize, k4_smem);
    k4_mma<<<NROWS/128, 256, k4_smem>>>(m, Wout, out);

    const int k5_smem = (128*68*2 + 64*136 + 64*72) * 4;   // 122,880 B
    cudaFuncSetAttribute(k5_mma, cudaFuncAttributeMaxDynamicSharedMemorySize, k5_smem);
    k5_mma<<<296, 256, k5_smem>>>(out, lntg, lntb, Wa, Wb, Wo);
    (void)in_sizes; (void)n_in; (void)out_size;
}

// round 11
// speedup vs baseline: 2.7678x; 1.1799x over previous
#include <cuda_runtime.h>
#include <math.h>
#include <stdint.h>

#define S_DIM 1024
#define N_DIM 512
#define CM 64
#define CC 8
#define CZ 128
#define HH 8
#define NROWS (S_DIM*N_DIM)        // 524288
#define PDIM (S_DIM*CC)            // 8192

// ---- scratch ----
__device__ float g_G [(size_t)NROWS*CM];                 // gate, [s*N+i][hc]
__device__ float g_Vt[(size_t)HH*N_DIM*PDIM];            // v^T,  [h][j][p=s*8+c]  (tf32-rounded)
__device__ float g_WV[(size_t)HH*N_DIM*PDIM];            // wv,   [h][i][p]
__device__ float g_Wsm[(size_t)HH*N_DIM*N_DIM];          // softmax w [h][i][j] (tf32-rounded)

__device__ __forceinline__ float tf32r(float x){
    uint32_t u; asm("cvt.rna.tf32.f32 %0, %1;" : "=r"(u) : "f"(x)); return __uint_as_float(u);
}
__device__ __forceinline__ void mma16n8k8(float* c, const uint32_t* a, const uint32_t* b){
    asm volatile("mma.sync.aligned.m16n8k8.row.col.f32.tf32.tf32.f32 "
        "{%0,%1,%2,%3}, {%4,%5,%6,%7}, {%8,%9}, {%0,%1,%2,%3};"
        : "+f"(c[0]), "+f"(c[1]), "+f"(c[2]), "+f"(c[3])
        : "r"(a[0]), "r"(a[1]), "r"(a[2]), "r"(a[3]), "r"(b[0]), "r"(b[1]));
}
__device__ __forceinline__ uint32_t smem_u32(const void* p){
    uint32_t a; asm("{ .reg .u64 t; cvta.to.shared.u64 t, %1; cvt.u32.u64 %0, t; }" : "=r"(a) : "l"(p)); return a;
}
__device__ __forceinline__ void cpasync16(uint32_t saddr, const void* g){
    asm volatile("cp.async.ca.shared.global [%0], [%1], 16;" :: "r"(saddr), "l"(g));
}

// ============================================================
// K1: per 128-row tile: LN -> st; GEMM st @ [Wmv|Wmg] (mma tf32);
//     sigmoid gate -> g_G; v half tf32 -> g_Vt [h][j][p].
// smem union: sout overlays st+sW (dead after GEMM) -> 69.6KB, 2 CTAs/SM.
// ============================================================
__global__ void __launch_bounds__(256,2) k1_mma(
    const float* __restrict__ m, const float* __restrict__ lng, const float* __restrict__ lnb,
    const float* __restrict__ Wmv, const float* __restrict__ Wmg)
{
    extern __shared__ float sh1[];
    float* st   = sh1;               // [128][68] LN'd rows (tf32)
    float* sW   = sh1 + 128*68;      // [64][136] combined [Wmv|Wmg] (tf32)
    float* sout = sh1;               // [128][132] overlays st+sW after GEMM

    int tid = threadIdx.x, wid = tid >> 5, lane = tid & 31;
    int group = lane >> 2, tg = lane & 3;
    int wm = wid >> 2, wn = wid & 3;
    float gm0 = lng[lane], gm1 = lng[lane+32];
    float bt0 = lnb[lane], bt1 = lnb[lane+32];

    int rbase = blockIdx.x*128;
    int ss = rbase >> 9, ii0 = rbase & 511;

    // ---- weights -> smem (tf32) ----
    {
        int wk = tid >> 2, wq = tid & 3;
        #pragma unroll
        for (int u = 0; u < 4; u++) {
            float4 a4 = *(const float4*)&Wmv[(size_t)wk*64 + wq*16 + u*4];
            float4 b4 = *(const float4*)&Wmg[(size_t)wk*64 + wq*16 + u*4];
            *(float4*)&sW[wk*136 + wq*16 + u*4] =
                make_float4(tf32r(a4.x),tf32r(a4.y),tf32r(a4.z),tf32r(a4.w));
            *(float4*)&sW[wk*136 + 64 + wq*16 + u*4] =
                make_float4(tf32r(b4.x),tf32r(b4.y),tf32r(b4.z),tf32r(b4.w));
        }
    }
    // ---- load m rows + LN -> st ----
    #pragma unroll 1
    for (int rr = 0; rr < 16; rr += 4) {
        float xs0[4], xs1[4], s[4], q[4];
        #pragma unroll
        for (int u = 0; u < 4; u++) {
            int row = wid*16 + rr + u;
            xs0[u] = m[(size_t)(rbase+row)*64 + lane];
            xs1[u] = m[(size_t)(rbase+row)*64 + 32 + lane];
            s[u] = xs0[u] + xs1[u];
            q[u] = xs0[u]*xs0[u] + xs1[u]*xs1[u];
        }
        #pragma unroll
        for (int o = 16; o > 0; o >>= 1) {
            #pragma unroll
            for (int u = 0; u < 4; u++) {
                s[u] += __shfl_xor_sync(0xffffffffu, s[u], o);
                q[u] += __shfl_xor_sync(0xffffffffu, q[u], o);
            }
        }
        #pragma unroll
        for (int u = 0; u < 4; u++) {
            int row = wid*16 + rr + u;
            float mean = s[u]*(1.0f/64.0f);
            float var  = q[u]*(1.0f/64.0f) - mean*mean;
            float rs = rsqrtf(var + 1e-5f);
            st[row*68 + lane]      = tf32r((xs0[u]-mean)*rs*gm0 + bt0);
            st[row*68 + 32 + lane] = tf32r((xs1[u]-mean)*rs*gm1 + bt1);
        }
    }
    __syncthreads();

    // ---- GEMM: st[128x64] @ sW[64x128] ----
    float acc[4][4][4] = {};
    #pragma unroll
    for (int ks = 0; ks < 8; ks++) {
        uint32_t af[4][4], bf[4][2];
        #pragma unroll
        for (int mt = 0; mt < 4; mt++) {
            const float* ap = st + (wm*64 + mt*16 + group)*68 + ks*8 + tg;
            af[mt][0] = __float_as_uint(ap[0]);
            af[mt][1] = __float_as_uint(ap[8*68]);
            af[mt][2] = __float_as_uint(ap[4]);
            af[mt][3] = __float_as_uint(ap[8*68 + 4]);
        }
        #pragma unroll
        for (int nt = 0; nt < 4; nt++) {
            const float* bp = sW + (ks*8 + tg)*136 + wn*32 + nt*8 + group;
            bf[nt][0] = __float_as_uint(bp[0]);
            bf[nt][1] = __float_as_uint(bp[4*136]);
        }
        #pragma unroll
        for (int mt = 0; mt < 4; mt++)
            #pragma unroll
            for (int nt = 0; nt < 4; nt++)
                mma16n8k8(acc[mt][nt], af[mt], bf[nt]);
    }
    __syncthreads();   // st/sW dead; sout overlays them
    // ---- stage output to smem ----
    #pragma unroll
    for (int mt = 0; mt < 4; mt++) {
        int r1 = wm*64 + mt*16 + group;
        #pragma unroll
        for (int nt = 0; nt < 4; nt++) {
            int col = wn*32 + nt*8 + tg*2;
            *(float2*)&sout[r1*132 + col]     = make_float2(acc[mt][nt][0], acc[mt][nt][1]);
            *(float2*)&sout[(r1+8)*132 + col] = make_float2(acc[mt][nt][2], acc[mt][nt][3]);
        }
    }
    __syncthreads();

    // ---- gate: sigmoid(cols 64..127) -> g_G ----
    #pragma unroll
    for (int u = 0; u < 8; u++) {
        int flat = u*256 + tid;
        int row = flat >> 4, c4 = (flat & 15)*4;
        float4 v = *(const float4*)&sout[row*132 + 64 + c4];
        float4 gv;
        gv.x = __fdividef(1.0f, 1.0f + __expf(-v.x));
        gv.y = __fdividef(1.0f, 1.0f + __expf(-v.y));
        gv.z = __fdividef(1.0f, 1.0f + __expf(-v.z));
        gv.w = __fdividef(1.0f, 1.0f + __expf(-v.w));
        *(float4*)&g_G[(size_t)(rbase+row)*64 + c4] = gv;
    }
    // ---- v: cols 0..63, tf32 -> g_Vt[h][ii0+row][ss*8..+7] ----
    #pragma unroll
    for (int u = 0; u < 4; u++) {
        int pidx = u*256 + tid;
        int h = pidx >> 7, row = pidx & 127;
        float4 v0 = *(const float4*)&sout[row*132 + h*8];
        float4 v1 = *(const float4*)&sout[row*132 + h*8 + 4];
        size_t off = ((size_t)h*N_DIM + ii0 + row)*PDIM + ss*8;
        *(float4*)&g_Vt[off]     = make_float4(tf32r(v0.x),tf32r(v0.y),tf32r(v0.z),tf32r(v0.w));
        *(float4*)&g_Vt[off + 4] = make_float4(tf32r(v1.x),tf32r(v1.y),tf32r(v1.z),tf32r(v1.w));
    }
}

// ============================================================
// K2a: bias[h][i][j] = LN(z[i,j,:]) @ W_z
// ============================================================
__global__ void __launch_bounds__(256) k2a_bias(
    const float* __restrict__ z, const float* __restrict__ lng, const float* __restrict__ lnb,
    const float* __restrict__ Wz)
{
    int w = (blockIdx.x * 256 + threadIdx.x) >> 5;
    int lane = threadIdx.x & 31;
    if (w >= N_DIM*N_DIM) return;
    int i = w >> 9, j = w & 511;
    const float* zp = z + ((size_t)i*N_DIM + j)*CZ;
    float x0 = zp[lane], x1 = zp[lane+32], x2 = zp[lane+64], x3 = zp[lane+96];
    float s = x0+x1+x2+x3;
    float q = x0*x0 + x1*x1 + x2*x2 + x3*x3;
    #pragma unroll
    for (int o = 16; o > 0; o >>= 1) {
        s += __shfl_xor_sync(0xffffffffu, s, o);
        q += __shfl_xor_sync(0xffffffffu, q, o);
    }
    float mean = s * (1.0f/128.0f);
    float var  = q * (1.0f/128.0f) - mean*mean;
    float rs = rsqrtf(var + 1e-5f);
    float n0 = (x0-mean)*rs*lng[lane]    + lnb[lane];
    float n1 = (x1-mean)*rs*lng[lane+32] + lnb[lane+32];
    float n2 = (x2-mean)*rs*lng[lane+64] + lnb[lane+64];
    float n3 = (x3-mean)*rs*lng[lane+96] + lnb[lane+96];
    float ph[8];
    #pragma unroll
    for (int h = 0; h < 8; h++) {
        float pp = n0*Wz[lane*8+h] + n1*Wz[(lane+32)*8+h]
                 + n2*Wz[(lane+64)*8+h] + n3*Wz[(lane+96)*8+h];
        #pragma unroll
        for (int o = 16; o > 0; o >>= 1) pp += __shfl_xor_sync(0xffffffffu, pp, o);
        ph[h] = pp;
    }
    if (lane == 0) {
        #pragma unroll
        for (int h = 0; h < 8; h++)
            g_Wsm[(size_t)h*N_DIM*N_DIM + (size_t)i*N_DIM + j] = ph[h];
    }
}

// ============================================================
// K2b: softmax over j, tf32-rounded output
// ============================================================
__global__ void __launch_bounds__(256) k2b_softmax()
{
    float* p = g_Wsm + (size_t)blockIdx.x * N_DIM;
    __shared__ float red[256];
    int t = threadIdx.x;
    float v0 = p[t], v1 = p[t+256];
    red[t] = fmaxf(v0, v1);
    __syncthreads();
    for (int s2 = 128; s2 > 0; s2 >>= 1) {
        if (t < s2) red[t] = fmaxf(red[t], red[t+s2]);
        __syncthreads();
    }
    float mx = red[0];
    __syncthreads();
    float e0 = __expf(v0-mx), e1 = __expf(v1-mx);
    red[t] = e0+e1;
    __syncthreads();
    for (int s2 = 128; s2 > 0; s2 >>= 1) {
        if (t < s2) red[t] += red[t+s2];
        __syncthreads();
    }
    float inv = __fdividef(1.0f, red[0]);
    p[t] = tf32r(e0*inv); p[t+256] = tf32r(e1*inv);
}

// ============================================================
// K3: mma.sync tf32 GEMM per head; cp.async, 2 CTAs/SM. (unchanged)
// ============================================================
__global__ void __launch_bounds__(256,2) k3_mma()
{
    extern __shared__ float sh3[];
    float* sAs = sh3;                 // 2 x [128][36]
    float* sBs = sh3 + 2*128*36;      // 2 x [32][136]
    uint32_t aS = smem_u32(sAs), bS = smem_u32(sBs);

    int tid = threadIdx.x, wid = tid >> 5, lane = tid & 31;
    int group = lane >> 2, tg = lane & 3;
    int wm = wid >> 2, wn = wid & 3;
    int h  = blockIdx.z;
    int i0 = blockIdx.y * 128;
    int p0 = blockIdx.x * 128;
    const float* A = g_Wsm + (size_t)h*N_DIM*N_DIM;
    const float* B = g_Vt  + (size_t)h*N_DIM*PDIM;
    float*       C = g_WV  + (size_t)h*N_DIM*PDIM;

    int lr = tid >> 3, lc = (tid & 7)*4;

    #pragma unroll
    for (int u = 0; u < 4; u++)
        cpasync16(aS + (uint32_t)((lr + u*32)*36 + lc)*4, &A[(size_t)(i0+lr+u*32)*N_DIM + lc]);
    #pragma unroll
    for (int u = 0; u < 4; u++)
        cpasync16(bS + (uint32_t)(lr*136 + lc + u*32)*4, &B[(size_t)lr*PDIM + p0 + lc + u*32]);
    asm volatile("cp.async.commit_group;");

    float acc[4][4][4] = {};
    for (int it = 0; it < 16; it++) {
        if (it < 15) {
            int k0 = (it+1)*32;
            uint32_t ao = aS + (uint32_t)(((it+1)&1)*4608*4);
            uint32_t bo = bS + (uint32_t)(((it+1)&1)*4352*4);
            #pragma unroll
            for (int u = 0; u < 4; u++)
                cpasync16(ao + (uint32_t)((lr + u*32)*36 + lc)*4, &A[(size_t)(i0+lr+u*32)*N_DIM + k0 + lc]);
            #pragma unroll
            for (int u = 0; u < 4; u++)
                cpasync16(bo + (uint32_t)(lr*136 + lc + u*32)*4, &B[(size_t)(k0+lr)*PDIM + p0 + lc + u*32]);
            asm volatile("cp.async.commit_group;");
            asm volatile("cp.async.wait_group 1;");
        } else {
            asm volatile("cp.async.wait_group 0;");
        }
        __syncthreads();
        const float* as = sAs + (it&1)*4608;
        const float* bs = sBs + (it&1)*4352;
        #pragma unroll
        for (int ks = 0; ks < 4; ks++) {
            uint32_t af[4][4], bf[4][2];
            #pragma unroll
            for (int mt = 0; mt < 4; mt++) {
                const float* ap = as + (wm*64 + mt*16 + group)*36 + ks*8 + tg;
                af[mt][0] = __float_as_uint(ap[0]);
                af[mt][1] = __float_as_uint(ap[8*36]);
                af[mt][2] = __float_as_uint(ap[4]);
                af[mt][3] = __float_as_uint(ap[8*36 + 4]);
            }
            #pragma unroll
            for (int nt = 0; nt < 4; nt++) {
                const float* bp = bs + (ks*8 + tg)*136 + wn*32 + nt*8 + group;
                bf[nt][0] = __float_as_uint(bp[0]);
                bf[nt][1] = __float_as_uint(bp[4*136]);
            }
            #pragma unroll
            for (int mt = 0; mt < 4; mt++)
                #pragma unroll
                for (int nt = 0; nt < 4; nt++)
                    mma16n8k8(acc[mt][nt], af[mt], bf[nt]);
        }
        __syncthreads();
    }

    #pragma unroll
    for (int mt = 0; mt < 4; mt++) {
        int row = i0 + wm*64 + mt*16 + group;
        #pragma unroll
        for (int nt = 0; nt < 4; nt++) {
            int col = p0 + wn*32 + nt*8 + tg*2;
            *(float2*)&C[(size_t)row*PDIM + col]     = make_float2(acc[mt][nt][0], acc[mt][nt][1]);
            *(float2*)&C[(size_t)(row+8)*PDIM + col] = make_float2(acc[mt][nt][2], acc[mt][nt][3]);
        }
    }
}

// ============================================================
// K4: mma.sync. Per 128-row tile: st = tf32(g*wv); out = m + st @ Wout. (unchanged)
// ============================================================
__global__ void __launch_bounds__(256) k4_mma(
    const float* __restrict__ m, const float* __restrict__ Wout, float* __restrict__ out)
{
    extern __shared__ float sh4[];
    float* st = sh4;             // [128][68] gated product (tf32)
    float* sW = st + 128*68;     // [64][72]  Wout (tf32)

    int tid = threadIdx.x, wid = tid >> 5, lane = tid & 31;
    int group = lane >> 2, tg = lane & 3;
    int wm2 = wid >> 1, wn2 = wid & 1;
    int rbase = blockIdx.x*128;
    int ss = rbase >> 9, ii0 = rbase & 511;

    {
        int wk = tid >> 2, wq = tid & 3;
        #pragma unroll
        for (int u = 0; u < 4; u++) {
            float4 w4 = *(const float4*)&Wout[(size_t)wk*64 + wq*16 + u*4];
            *(float4*)&sW[wk*72 + wq*16 + u*4] =
                make_float4(tf32r(w4.x),tf32r(w4.y),tf32r(w4.z),tf32r(w4.w));
        }
    }
    #pragma unroll
    for (int i = 0; i < 8; i++) {
        int flat4 = i*256 + tid;
        int row = flat4 >> 4, c4 = flat4 & 15;
        int k0 = c4*4; int hh = k0 >> 3, cc = k0 & 7;
        float4 g4 = *(const float4*)&g_G[(size_t)(rbase+row)*64 + k0];
        float4 w4 = *(const float4*)&g_WV[((size_t)hh*N_DIM + ii0 + row)*PDIM + ss*8 + cc];
        *(float4*)&st[row*68 + k0] = make_float4(
            tf32r(g4.x*w4.x), tf32r(g4.y*w4.y), tf32r(g4.z*w4.z), tf32r(g4.w*w4.w));
    }
    __syncthreads();

    float acc[2][4][4] = {};
    #pragma unroll
    for (int ks = 0; ks < 8; ks++) {
        uint32_t af[2][4], bf[4][2];
        #pragma unroll
        for (int mt = 0; mt < 2; mt++) {
            const float* ap = st + (wm2*32 + mt*16 + group)*68 + ks*8 + tg;
            af[mt][0] = __float_as_uint(ap[0]);
            af[mt][1] = __float_as_uint(ap[8*68]);
            af[mt][2] = __float_as_uint(ap[4]);
            af[mt][3] = __float_as_uint(ap[8*68 + 4]);
        }
        #pragma unroll
        for (int nt = 0; nt < 4; nt++) {
            const float* bp = sW + (ks*8 + tg)*72 + wn2*32 + nt*8 + group;
            bf[nt][0] = __float_as_uint(bp[0]);
            bf[nt][1] = __float_as_uint(bp[4*72]);
        }
        #pragma unroll
        for (int mt = 0; mt < 2; mt++)
            #pragma unroll
            for (int nt = 0; nt < 4; nt++)
                mma16n8k8(acc[mt][nt], af[mt], bf[nt]);
    }
    #pragma unroll
    for (int mt = 0; mt < 2; mt++) {
        int row = rbase + wm2*32 + mt*16 + group;
        #pragma unroll
        for (int nt = 0; nt < 4; nt++) {
            int col = wn2*32 + nt*8 + tg*2;
            float2 m0 = *(const float2*)&m[(size_t)row*64 + col];
            *(float2*)&out[(size_t)row*64 + col] =
                make_float2(m0.x + acc[mt][nt][0], m0.y + acc[mt][nt][1]);
            float2 m1 = *(const float2*)&m[(size_t)(row+8)*64 + col];
            *(float2*)&out[(size_t)(row+8)*64 + col] =
                make_float2(m1.x + acc[mt][nt][2], m1.y + acc[mt][nt][3]);
        }
    }
}

// ============================================================
// K5: SwiGLU via mma.sync tf32; 32-hidden-col weight chunks (8 chunks),
// shh [128][36] (32 data cols), smem 80.9KB -> 2 CTAs/SM.
// ============================================================
__global__ void __launch_bounds__(256,2) k5_mma(
    float* __restrict__ out, const float* __restrict__ lng, const float* __restrict__ lnb,
    const float* __restrict__ Wa, const float* __restrict__ Wb, const float* __restrict__ Wo)
{
    extern __shared__ float sh5[];
    float* st   = sh5;               // [128][68] LN'd rows
    float* shh  = st  + 128*68;      // [128][36] hidden chunk (32 cols)
    float* swab = shh + 128*36;      // [64][72]  interleaved Wa|Wb chunk (32 hidden)
    float* swo  = swab + 64*72;      // [32][72]  Wo chunk

    int tid = threadIdx.x, wid = tid >> 5, lane = tid & 31;
    int group = lane >> 2, tg = lane & 3;
    int wm = wid >> 2, wn = wid & 3;       // GEMM1: 2(M) x 4(N)
    int wm2 = wid >> 1, wn2 = wid & 1;     // GEMM2: 4(M) x 2(N)
    float gm0 = lng[lane], gm1 = lng[lane+32];
    float bt0 = lnb[lane], bt1 = lnb[lane+32];
    int wk = tid >> 2, wq = tid & 3;       // Wa/Wb loader: 64 rows x 4 col-groups
    int wk2 = tid >> 3, wq2 = tid & 7;     // Wo loader: 32 rows x 8 col-groups

    for (int tile = blockIdx.x; tile < NROWS/128; tile += gridDim.x) {
        int rbase = tile*128;
        // ---- load + LN -> st ----
        #pragma unroll 1
        for (int rr = 0; rr < 16; rr += 4) {
            float xs0[4], xs1[4], s[4], q[4];
            #pragma unroll
            for (int u = 0; u < 4; u++) {
                int row = wid*16 + rr + u;
                xs0[u] = out[(size_t)(rbase+row)*64 + lane];
                xs1[u] = out[(size_t)(rbase+row)*64 + 32 + lane];
                s[u] = xs0[u] + xs1[u];
                q[u] = xs0[u]*xs0[u] + xs1[u]*xs1[u];
            }
            #pragma unroll
            for (int o = 16; o > 0; o >>= 1) {
                #pragma unroll
                for (int u = 0; u < 4; u++) {
                    s[u] += __shfl_xor_sync(0xffffffffu, s[u], o);
                    q[u] += __shfl_xor_sync(0xffffffffu, q[u], o);
                }
            }
            #pragma unroll
            for (int u = 0; u < 4; u++) {
                int row = wid*16 + rr + u;
                float mean = s[u]*(1.0f/64.0f);
                float var  = q[u]*(1.0f/64.0f) - mean*mean;
                float rs = rsqrtf(var + 1e-5f);
                st[row*68 + lane]      = tf32r((xs0[u]-mean)*rs*gm0 + bt0);
                st[row*68 + 32 + lane] = tf32r((xs1[u]-mean)*rs*gm1 + bt1);
            }
        }

        float acc2[2][4][4] = {};
        #pragma unroll 1
        for (int hc = 0; hc < 8; hc++) {
            __syncthreads();  // st ready / prev GEMM2 done with shh+weights
            // ---- stream 32-hidden-col weight chunk ----
            #pragma unroll
            for (int u = 0; u < 2; u++) {
                float4 a4 = *(const float4*)&Wa[(size_t)wk*256 + hc*32 + wq*8 + u*4];
                float4 b4 = *(const float4*)&Wb[(size_t)wk*256 + hc*32 + wq*8 + u*4];
                int base = wk*72 + wq*16 + u*8;
                swab[base+0] = tf32r(a4.x); swab[base+1] = tf32r(b4.x);
                swab[base+2] = tf32r(a4.y); swab[base+3] = tf32r(b4.y);
                swab[base+4] = tf32r(a4.z); swab[base+5] = tf32r(b4.z);
                swab[base+6] = tf32r(a4.w); swab[base+7] = tf32r(b4.w);
                float4 o4 = *(const float4*)&Wo[(size_t)(hc*32 + wk2)*64 + wq2*8 + u*4];
                *(float4*)&swo[wk2*72 + wq2*8 + u*4] =
                    make_float4(tf32r(o4.x), tf32r(o4.y), tf32r(o4.z), tf32r(o4.w));
            }
            __syncthreads();
            // ---- GEMM1: st[128x64] @ wab[64x64] (32 hidden, interleaved) ----
            float acc1[4][2][4] = {};
            #pragma unroll
            for (int ks = 0; ks < 8; ks++) {
                uint32_t af[4][4], bf[2][2];
                #pragma unroll
                for (int mt = 0; mt < 4; mt++) {
                    const float* ap = st + (wm*64 + mt*16 + group)*68 + ks*8 + tg;
                    af[mt][0] = __float_as_uint(ap[0]);
                    af[mt][1] = __float_as_uint(ap[8*68]);
                    af[mt][2] = __float_as_uint(ap[4]);
                    af[mt][3] = __float_as_uint(ap[8*68 + 4]);
                }
                #pragma unroll
                for (int nt = 0; nt < 2; nt++) {
                    const float* bp = swab + (ks*8 + tg)*72 + wn*16 + nt*8 + group;
                    bf[nt][0] = __float_as_uint(bp[0]);
                    bf[nt][1] = __float_as_uint(bp[4*72]);
                }
                #pragma unroll
                for (int mt = 0; mt < 4; mt++)
                    #pragma unroll
                    for (int nt = 0; nt < 2; nt++)
                        mma16n8k8(acc1[mt][nt], af[mt], bf[nt]);
            }
            // ---- SiLU(a)*b in-register (c0=A, c1=B), h -> shh (32 cols) ----
            #pragma unroll
            for (int mt = 0; mt < 4; mt++) {
                int r1 = wm*64 + mt*16 + group;
                #pragma unroll
                for (int nt = 0; nt < 2; nt++) {
                    int hcol = wn*8 + nt*4 + tg;
                    float a0 = acc1[mt][nt][0], b0v = acc1[mt][nt][1];
                    float a1 = acc1[mt][nt][2], b1v = acc1[mt][nt][3];
                    float h0 = __fdividef(a0, 1.0f + __expf(-a0)) * b0v;
                    float h1 = __fdividef(a1, 1.0f + __expf(-a1)) * b1v;
                    shh[r1*36 + hcol]      = tf32r(h0);
                    shh[(r1+8)*36 + hcol]  = tf32r(h1);
                }
            }
            __syncthreads();
            // ---- GEMM2: shh[128x32] @ swo[32x64], accumulate ----
            #pragma unroll
            for (int ks = 0; ks < 4; ks++) {
                uint32_t af[2][4], bf[4][2];
                #pragma unroll
                for (int mt = 0; mt < 2; mt++) {
                    const float* ap = shh + (wm2*32 + mt*16 + group)*36 + ks*8 + tg;
                    af[mt][0] = __float_as_uint(ap[0]);
                    af[mt][1] = __float_as_uint(ap[8*36]);
                    af[mt][2] = __float_as_uint(ap[4]);
                    af[mt][3] = __float_as_uint(ap[8*36 + 4]);
                }
                #pragma unroll
                for (int nt = 0; nt < 4; nt++) {
                    const float* bp = swo + (ks*8 + tg)*72 + wn2*32 + nt*8 + group;
                    bf[nt][0] = __float_as_uint(bp[0]);
                    bf[nt][1] = __float_as_uint(bp[4*72]);
                }
                #pragma unroll
                for (int mt = 0; mt < 2; mt++)
                    #pragma unroll
                    for (int nt = 0; nt < 4; nt++)
                        mma16n8k8(acc2[mt][nt], af[mt], bf[nt]);
            }
        }
        // ---- residual add + store ----
        #pragma unroll
        for (int mt = 0; mt < 2; mt++) {
            int row = rbase + wm2*32 + mt*16 + group;
            #pragma unroll
            for (int nt = 0; nt < 4; nt++) {
                int col = wn2*32 + nt*8 + tg*2;
                float2 o0 = *(float2*)&out[(size_t)row*64 + col];
                o0.x += acc2[mt][nt][0]; o0.y += acc2[mt][nt][1];
                *(float2*)&out[(size_t)row*64 + col] = o0;
                float2 o1 = *(float2*)&out[(size_t)(row+8)*64 + col];
                o1.x += acc2[mt][nt][2]; o1.y += acc2[mt][nt][3];
                *(float2*)&out[(size_t)(row+8)*64 + col] = o1;
            }
        }
        __syncthreads();
    }
}

// ============================================================
extern "C" void kernel_launch(void* const* d_in, const int* in_sizes, int n_in,
                              void* d_out, int out_size) {
    const float* m    = (const float*)d_in[0];
    const float* z    = (const float*)d_in[1];
    const float* lnmg = (const float*)d_in[2];
    const float* lnmb = (const float*)d_in[3];
    const float* Wmv  = (const float*)d_in[4];
    const float* lnzg = (const float*)d_in[5];
    const float* lnzb = (const float*)d_in[6];
    const float* Wz   = (const float*)d_in[7];
    const float* Wmg  = (const float*)d_in[8];
    const float* Wout = (const float*)d_in[9];
    const float* lntg = (const float*)d_in[10];
    const float* lntb = (const float*)d_in[11];
    const float* Wa   = (const float*)d_in[12];
    const float* Wb   = (const float*)d_in[13];
    const float* Wo   = (const float*)d_in[14];
    float* out = (float*)d_out;

    const int k1_smem = (128*68 + 64*136) * 4;       // 69,632 B (sout overlays)
    cudaFuncSetAttribute(k1_mma, cudaFuncAttributeMaxDynamicSharedMemorySize, k1_smem);
    k1_mma<<<NROWS/128, 256, k1_smem>>>(m, lnmg, lnmb, Wmv, Wmg);

    k2a_bias<<<(N_DIM*N_DIM)/8, 256>>>(z, lnzg, lnzb, Wz);
    k2b_softmax<<<HH*N_DIM, 256>>>();

    const int k3_smem = (2*128*36 + 2*32*136) * 4;   // 71,680 B
    cudaFuncSetAttribute(k3_mma, cudaFuncAttributeMaxDynamicSharedMemorySize, k3_smem);
    k3_mma<<<dim3(PDIM/128, N_DIM/128, HH), 256, k3_smem>>>();

    const int k4_smem = (128*68 + 64*72) * 4;        // 53,248 B
    cudaFuncSetAttribute(k4_mma, cudaFuncAttributeMaxDynamicSharedMemorySize, k4_smem);
    k4_mma<<<NROWS/128, 256, k4_smem>>>(m, Wout, out);

    const int k5_smem = (128*68 + 128*36 + 64*72 + 32*72) * 4;   // 80,896 B
    cudaFuncSetAttribute(k5_mma, cudaFuncAttributeMaxDynamicSharedMemorySize, k5_smem);
    k5_mma<<<296, 256, k5_smem>>>(out, lntg, lntb, Wa, Wb, Wo);
    (void)in_sizes; (void)n_in; (void)out_size;
}

// round 13
// speedup vs baseline: 2.8580x; 1.0326x over previous
#include <cuda_runtime.h>
#include <math.h>
#include <stdint.h>

#define S_DIM 1024
#define N_DIM 512
#define CM 64
#define CC 8
#define CZ 128
#define HH 8
#define NROWS (S_DIM*N_DIM)        // 524288
#define PDIM (S_DIM*CC)            // 8192

// ---- scratch ----
__device__ float g_G [(size_t)NROWS*CM];                 // gate, [s*N+i][hc]
__device__ float g_Vt[(size_t)HH*N_DIM*PDIM];            // v^T,  [h][j][p=s*8+c]  (tf32-rounded)
__device__ float g_WV[(size_t)HH*N_DIM*PDIM];            // wv,   [h][i][p]
__device__ float g_Wsm[(size_t)HH*N_DIM*N_DIM];          // softmax w [h][i][j] (tf32-rounded)

__device__ __forceinline__ float tf32r(float x){
    uint32_t u; asm("cvt.rna.tf32.f32 %0, %1;" : "=r"(u) : "f"(x)); return __uint_as_float(u);
}
__device__ __forceinline__ void mma16n8k8(float* c, const uint32_t* a, const uint32_t* b){
    asm volatile("mma.sync.aligned.m16n8k8.row.col.f32.tf32.tf32.f32 "
        "{%0,%1,%2,%3}, {%4,%5,%6,%7}, {%8,%9}, {%0,%1,%2,%3};"
        : "+f"(c[0]), "+f"(c[1]), "+f"(c[2]), "+f"(c[3])
        : "r"(a[0]), "r"(a[1]), "r"(a[2]), "r"(a[3]), "r"(b[0]), "r"(b[1]));
}
__device__ __forceinline__ uint32_t smem_u32(const void* p){
    uint32_t a; asm("{ .reg .u64 t; cvta.to.shared.u64 t, %1; cvt.u32.u64 %0, t; }" : "=r"(a) : "l"(p)); return a;
}
__device__ __forceinline__ void cpasync16(uint32_t saddr, const void* g){
    asm volatile("cp.async.ca.shared.global [%0], [%1], 16;" :: "r"(saddr), "l"(g));
}

// ============================================================
// K1: per 128-row tile: LN -> st; GEMM st @ [Wmv|Wmg] (mma tf32);
//     sigmoid gate -> g_G; v half tf32 -> g_Vt. (unchanged, 2 CTAs/SM)
// ============================================================
__global__ void __launch_bounds__(256,2) k1_mma(
    const float* __restrict__ m, const float* __restrict__ lng, const float* __restrict__ lnb,
    const float* __restrict__ Wmv, const float* __restrict__ Wmg)
{
    extern __shared__ float sh1[];
    float* st   = sh1;               // [128][68]
    float* sW   = sh1 + 128*68;      // [64][136]
    float* sout = sh1;               // [128][132] overlays after GEMM

    int tid = threadIdx.x, wid = tid >> 5, lane = tid & 31;
    int group = lane >> 2, tg = lane & 3;
    int wm = wid >> 2, wn = wid & 3;
    float gm0 = lng[lane], gm1 = lng[lane+32];
    float bt0 = lnb[lane], bt1 = lnb[lane+32];

    int rbase = blockIdx.x*128;
    int ss = rbase >> 9, ii0 = rbase & 511;

    {
        int wk = tid >> 2, wq = tid & 3;
        #pragma unroll
        for (int u = 0; u < 4; u++) {
            float4 a4 = *(const float4*)&Wmv[(size_t)wk*64 + wq*16 + u*4];
            float4 b4 = *(const float4*)&Wmg[(size_t)wk*64 + wq*16 + u*4];
            *(float4*)&sW[wk*136 + wq*16 + u*4] =
                make_float4(tf32r(a4.x),tf32r(a4.y),tf32r(a4.z),tf32r(a4.w));
            *(float4*)&sW[wk*136 + 64 + wq*16 + u*4] =
                make_float4(tf32r(b4.x),tf32r(b4.y),tf32r(b4.z),tf32r(b4.w));
        }
    }
    #pragma unroll 1
    for (int rr = 0; rr < 16; rr += 4) {
        float xs0[4], xs1[4], s[4], q[4];
        #pragma unroll
        for (int u = 0; u < 4; u++) {
            int row = wid*16 + rr + u;
            xs0[u] = m[(size_t)(rbase+row)*64 + lane];
            xs1[u] = m[(size_t)(rbase+row)*64 + 32 + lane];
            s[u] = xs0[u] + xs1[u];
            q[u] = xs0[u]*xs0[u] + xs1[u]*xs1[u];
        }
        #pragma unroll
        for (int o = 16; o > 0; o >>= 1) {
            #pragma unroll
            for (int u = 0; u < 4; u++) {
                s[u] += __shfl_xor_sync(0xffffffffu, s[u], o);
                q[u] += __shfl_xor_sync(0xffffffffu, q[u], o);
            }
        }
        #pragma unroll
        for (int u = 0; u < 4; u++) {
            int row = wid*16 + rr + u;
            float mean = s[u]*(1.0f/64.0f);
            float var  = q[u]*(1.0f/64.0f) - mean*mean;
            float rs = rsqrtf(var + 1e-5f);
            st[row*68 + lane]      = tf32r((xs0[u]-mean)*rs*gm0 + bt0);
            st[row*68 + 32 + lane] = tf32r((xs1[u]-mean)*rs*gm1 + bt1);
        }
    }
    __syncthreads();

    float acc[4][4][4] = {};
    #pragma unroll
    for (int ks = 0; ks < 8; ks++) {
        uint32_t af[4][4], bf[4][2];
        #pragma unroll
        for (int mt = 0; mt < 4; mt++) {
            const float* ap = st + (wm*64 + mt*16 + group)*68 + ks*8 + tg;
            af[mt][0] = __float_as_uint(ap[0]);
            af[mt][1] = __float_as_uint(ap[8*68]);
            af[mt][2] = __float_as_uint(ap[4]);
            af[mt][3] = __float_as_uint(ap[8*68 + 4]);
        }
        #pragma unroll
        for (int nt = 0; nt < 4; nt++) {
            const float* bp = sW + (ks*8 + tg)*136 + wn*32 + nt*8 + group;
            bf[nt][0] = __float_as_uint(bp[0]);
            bf[nt][1] = __float_as_uint(bp[4*136]);
        }
        #pragma unroll
        for (int mt = 0; mt < 4; mt++)
            #pragma unroll
            for (int nt = 0; nt < 4; nt++)
                mma16n8k8(acc[mt][nt], af[mt], bf[nt]);
    }
    __syncthreads();
    #pragma unroll
    for (int mt = 0; mt < 4; mt++) {
        int r1 = wm*64 + mt*16 + group;
        #pragma unroll
        for (int nt = 0; nt < 4; nt++) {
            int col = wn*32 + nt*8 + tg*2;
            *(float2*)&sout[r1*132 + col]     = make_float2(acc[mt][nt][0], acc[mt][nt][1]);
            *(float2*)&sout[(r1+8)*132 + col] = make_float2(acc[mt][nt][2], acc[mt][nt][3]);
        }
    }
    __syncthreads();

    #pragma unroll
    for (int u = 0; u < 8; u++) {
        int flat = u*256 + tid;
        int row = flat >> 4, c4 = (flat & 15)*4;
        float4 v = *(const float4*)&sout[row*132 + 64 + c4];
        float4 gv;
        gv.x = __fdividef(1.0f, 1.0f + __expf(-v.x));
        gv.y = __fdividef(1.0f, 1.0f + __expf(-v.y));
        gv.z = __fdividef(1.0f, 1.0f + __expf(-v.z));
        gv.w = __fdividef(1.0f, 1.0f + __expf(-v.w));
        *(float4*)&g_G[(size_t)(rbase+row)*64 + c4] = gv;
    }
    #pragma unroll
    for (int u = 0; u < 4; u++) {
        int pidx = u*256 + tid;
        int h = pidx >> 7, row = pidx & 127;
        float4 v0 = *(const float4*)&sout[row*132 + h*8];
        float4 v1 = *(const float4*)&sout[row*132 + h*8 + 4];
        size_t off = ((size_t)h*N_DIM + ii0 + row)*PDIM + ss*8;
        *(float4*)&g_Vt[off]     = make_float4(tf32r(v0.x),tf32r(v0.y),tf32r(v0.z),tf32r(v0.w));
        *(float4*)&g_Vt[off + 4] = make_float4(tf32r(v1.x),tf32r(v1.y),tf32r(v1.z),tf32r(v1.w));
    }
}

// ============================================================
// K2a: bias[h][i][j] = LN(z[i,j,:]) @ W_z  (unchanged)
// ============================================================
__global__ void __launch_bounds__(256) k2a_bias(
    const float* __restrict__ z, const float* __restrict__ lng, const float* __restrict__ lnb,
    const float* __restrict__ Wz)
{
    int w = (blockIdx.x * 256 + threadIdx.x) >> 5;
    int lane = threadIdx.x & 31;
    if (w >= N_DIM*N_DIM) return;
    int i = w >> 9, j = w & 511;
    const float* zp = z + ((size_t)i*N_DIM + j)*CZ;
    float x0 = zp[lane], x1 = zp[lane+32], x2 = zp[lane+64], x3 = zp[lane+96];
    float s = x0+x1+x2+x3;
    float q = x0*x0 + x1*x1 + x2*x2 + x3*x3;
    #pragma unroll
    for (int o = 16; o > 0; o >>= 1) {
        s += __shfl_xor_sync(0xffffffffu, s, o);
        q += __shfl_xor_sync(0xffffffffu, q, o);
    }
    float mean = s * (1.0f/128.0f);
    float var  = q * (1.0f/128.0f) - mean*mean;
    float rs = rsqrtf(var + 1e-5f);
    float n0 = (x0-mean)*rs*lng[lane]    + lnb[lane];
    float n1 = (x1-mean)*rs*lng[lane+32] + lnb[lane+32];
    float n2 = (x2-mean)*rs*lng[lane+64] + lnb[lane+64];
    float n3 = (x3-mean)*rs*lng[lane+96] + lnb[lane+96];
    float ph[8];
    #pragma unroll
    for (int h = 0; h < 8; h++) {
        float pp = n0*Wz[lane*8+h] + n1*Wz[(lane+32)*8+h]
                 + n2*Wz[(lane+64)*8+h] + n3*Wz[(lane+96)*8+h];
        #pragma unroll
        for (int o = 16; o > 0; o >>= 1) pp += __shfl_xor_sync(0xffffffffu, pp, o);
        ph[h] = pp;
    }
    if (lane == 0) {
        #pragma unroll
        for (int h = 0; h < 8; h++)
            g_Wsm[(size_t)h*N_DIM*N_DIM + (size_t)i*N_DIM + j] = ph[h];
    }
}

// ============================================================
// K2b: softmax over j, tf32-rounded output  (unchanged)
// ============================================================
__global__ void __launch_bounds__(256) k2b_softmax()
{
    float* p = g_Wsm + (size_t)blockIdx.x * N_DIM;
    __shared__ float red[256];
    int t = threadIdx.x;
    float v0 = p[t], v1 = p[t+256];
    red[t] = fmaxf(v0, v1);
    __syncthreads();
    for (int s2 = 128; s2 > 0; s2 >>= 1) {
        if (t < s2) red[t] = fmaxf(red[t], red[t+s2]);
        __syncthreads();
    }
    float mx = red[0];
    __syncthreads();
    float e0 = __expf(v0-mx), e1 = __expf(v1-mx);
    red[t] = e0+e1;
    __syncthreads();
    for (int s2 = 128; s2 > 0; s2 >>= 1) {
        if (t < s2) red[t] += red[t+s2];
        __syncthreads();
    }
    float inv = __fdividef(1.0f, red[0]);
    p[t] = tf32r(e0*inv); p[t+256] = tf32r(e1*inv);
}

// ============================================================
// K3: mma.sync tf32 GEMM per head; cp.async, 2 CTAs/SM. (unchanged)
// ============================================================
__global__ void __launch_bounds__(256,2) k3_mma()
{
    extern __shared__ float sh3[];
    float* sAs = sh3;                 // 2 x [128][36]
    float* sBs = sh3 + 2*128*36;      // 2 x [32][136]
    uint32_t aS = smem_u32(sAs), bS = smem_u32(sBs);

    int tid = threadIdx.x, wid = tid >> 5, lane = tid & 31;
    int group = lane >> 2, tg = lane & 3;
    int wm = wid >> 2, wn = wid & 3;
    int h  = blockIdx.z;
    int i0 = blockIdx.y * 128;
    int p0 = blockIdx.x * 128;
    const float* A = g_Wsm + (size_t)h*N_DIM*N_DIM;
    const float* B = g_Vt  + (size_t)h*N_DIM*PDIM;
    float*       C = g_WV  + (size_t)h*N_DIM*PDIM;

    int lr = tid >> 3, lc = (tid & 7)*4;

    #pragma unroll
    for (int u = 0; u < 4; u++)
        cpasync16(aS + (uint32_t)((lr + u*32)*36 + lc)*4, &A[(size_t)(i0+lr+u*32)*N_DIM + lc]);
    #pragma unroll
    for (int u = 0; u < 4; u++)
        cpasync16(bS + (uint32_t)(lr*136 + lc + u*32)*4, &B[(size_t)lr*PDIM + p0 + lc + u*32]);
    asm volatile("cp.async.commit_group;");

    float acc[4][4][4] = {};
    for (int it = 0; it < 16; it++) {
        if (it < 15) {
            int k0 = (it+1)*32;
            uint32_t ao = aS + (uint32_t)(((it+1)&1)*4608*4);
            uint32_t bo = bS + (uint32_t)(((it+1)&1)*4352*4);
            #pragma unroll
            for (int u = 0; u < 4; u++)
                cpasync16(ao + (uint32_t)((lr + u*32)*36 + lc)*4, &A[(size_t)(i0+lr+u*32)*N_DIM + k0 + lc]);
            #pragma unroll
            for (int u = 0; u < 4; u++)
                cpasync16(bo + (uint32_t)(lr*136 + lc + u*32)*4, &B[(size_t)(k0+lr)*PDIM + p0 + lc + u*32]);
            asm volatile("cp.async.commit_group;");
            asm volatile("cp.async.wait_group 1;");
        } else {
            asm volatile("cp.async.wait_group 0;");
        }
        __syncthreads();
        const float* as = sAs + (it&1)*4608;
        const float* bs = sBs + (it&1)*4352;
        #pragma unroll
        for (int ks = 0; ks < 4; ks++) {
            uint32_t af[4][4], bf[4][2];
            #pragma unroll
            for (int mt = 0; mt < 4; mt++) {
                const float* ap = as + (wm*64 + mt*16 + group)*36 + ks*8 + tg;
                af[mt][0] = __float_as_uint(ap[0]);
                af[mt][1] = __float_as_uint(ap[8*36]);
                af[mt][2] = __float_as_uint(ap[4]);
                af[mt][3] = __float_as_uint(ap[8*36 + 4]);
            }
            #pragma unroll
            for (int nt = 0; nt < 4; nt++) {
                const float* bp = bs + (ks*8 + tg)*136 + wn*32 + nt*8 + group;
                bf[nt][0] = __float_as_uint(bp[0]);
                bf[nt][1] = __float_as_uint(bp[4*136]);
            }
            #pragma unroll
            for (int mt = 0; mt < 4; mt++)
                #pragma unroll
                for (int nt = 0; nt < 4; nt++)
                    mma16n8k8(acc[mt][nt], af[mt], bf[nt]);
        }
        __syncthreads();
    }

    #pragma unroll
    for (int mt = 0; mt < 4; mt++) {
        int row = i0 + wm*64 + mt*16 + group;
        #pragma unroll
        for (int nt = 0; nt < 4; nt++) {
            int col = p0 + wn*32 + nt*8 + tg*2;
            *(float2*)&C[(size_t)row*PDIM + col]     = make_float2(acc[mt][nt][0], acc[mt][nt][1]);
            *(float2*)&C[(size_t)(row+8)*PDIM + col] = make_float2(acc[mt][nt][2], acc[mt][nt][3]);
        }
    }
}

// ============================================================
// K45: fused gate/out-projection + SwiGLU transition.
// Per 128-row tile: stA = tf32(g*wv); acc2 = stA@Wout + m  (= out, in regs,
// layout identical to transition's acc2); acc2 -> sx for LN; LN -> stA;
// 8x 32-hidden-chunk transition accumulates into acc2; single global store.
// sx overlays shh+swab. smem 99.3KB -> 2 CTAs/SM.
// ============================================================
__global__ void __launch_bounds__(256,2) k45_mma(
    const float* __restrict__ m, const float* __restrict__ Wout,
    const float* __restrict__ lng, const float* __restrict__ lnb,
    const float* __restrict__ Wa, const float* __restrict__ Wb, const float* __restrict__ Wo,
    float* __restrict__ out)
{
    extern __shared__ float sh45[];
    float* stA  = sh45;              // [128][68] gated (tf32), then LN'd (tf32)
    float* ovl  = sh45 + 128*68;     // overlay region: 11520 floats
    float* sx   = ovl;               // [128][68] out staging for LN (dies after LN)
    float* shh  = ovl;               // [128][36] hidden chunk
    float* swab = ovl + 128*36;      // [64][72]  interleaved Wa|Wb chunk
    float* swo  = ovl + 128*36 + 64*72;  // [32][72] Wo chunk
    float* sWout= sh45 + 128*68 + 11520; // [64][72] Wout (persistent)

    int tid = threadIdx.x, wid = tid >> 5, lane = tid & 31;
    int group = lane >> 2, tg = lane & 3;
    int wm = wid >> 2, wn = wid & 3;       // GEMM1: 2(M) x 4(N)
    int wm2 = wid >> 1, wn2 = wid & 1;     // out-GEMM / GEMM2: 4(M) x 2(N)
    float gm0 = lng[lane], gm1 = lng[lane+32];
    float bt0 = lnb[lane], bt1 = lnb[lane+32];
    int wk = tid >> 2, wq = tid & 3;
    int wk2 = tid >> 3, wq2 = tid & 7;

    // ---- Wout -> sWout once (tf32) ----
    #pragma unroll
    for (int u = 0; u < 4; u++) {
        float4 w4 = *(const float4*)&Wout[(size_t)wk*64 + wq*16 + u*4];
        *(float4*)&sWout[wk*72 + wq*16 + u*4] =
            make_float4(tf32r(w4.x),tf32r(w4.y),tf32r(w4.z),tf32r(w4.w));
    }

    for (int tile = blockIdx.x; tile < NROWS/128; tile += gridDim.x) {
        int rbase = tile*128;
        int ss = rbase >> 9, ii0 = rbase & 511;

        // ---- 1. gated product -> stA (tf32) ----
        #pragma unroll
        for (int i = 0; i < 8; i++) {
            int flat4 = i*256 + tid;
            int row = flat4 >> 4, c4 = flat4 & 15;
            int k0 = c4*4; int hh = k0 >> 3, cc = k0 & 7;
            float4 g4 = *(const float4*)&g_G[(size_t)(rbase+row)*64 + k0];
            float4 w4 = *(const float4*)&g_WV[((size_t)hh*N_DIM + ii0 + row)*PDIM + ss*8 + cc];
            *(float4*)&stA[row*68 + k0] = make_float4(
                tf32r(g4.x*w4.x), tf32r(g4.y*w4.y), tf32r(g4.z*w4.z), tf32r(g4.w*w4.w));
        }
        __syncthreads();

        // ---- 2. acc2 = stA @ Wout + m  (= out) ----
        float acc2[2][4][4] = {};
        #pragma unroll
        for (int ks = 0; ks < 8; ks++) {
            uint32_t af[2][4], bf[4][2];
            #pragma unroll
            for (int mt = 0; mt < 2; mt++) {
                const float* ap = stA + (wm2*32 + mt*16 + group)*68 + ks*8 + tg;
                af[mt][0] = __float_as_uint(ap[0]);
                af[mt][1] = __float_as_uint(ap[8*68]);
                af[mt][2] = __float_as_uint(ap[4]);
                af[mt][3] = __float_as_uint(ap[8*68 + 4]);
            }
            #pragma unroll
            for (int nt = 0; nt < 4; nt++) {
                const float* bp = sWout + (ks*8 + tg)*72 + wn2*32 + nt*8 + group;
                bf[nt][0] = __float_as_uint(bp[0]);
                bf[nt][1] = __float_as_uint(bp[4*72]);
            }
            #pragma unroll
            for (int mt = 0; mt < 2; mt++)
                #pragma unroll
                for (int nt = 0; nt < 4; nt++)
                    mma16n8k8(acc2[mt][nt], af[mt], bf[nt]);
        }
        #pragma unroll
        for (int mt = 0; mt < 2; mt++) {
            int row = rbase + wm2*32 + mt*16 + group;
            #pragma unroll
            for (int nt = 0; nt < 4; nt++) {
                int col = wn2*32 + nt*8 + tg*2;
                float2 m0 = *(const float2*)&m[(size_t)row*64 + col];
                acc2[mt][nt][0] += m0.x; acc2[mt][nt][1] += m0.y;
                float2 m1 = *(const float2*)&m[(size_t)(row+8)*64 + col];
                acc2[mt][nt][2] += m1.x; acc2[mt][nt][3] += m1.y;
            }
        }

        // ---- 3. stage acc2 -> sx for LN ----
        #pragma unroll
        for (int mt = 0; mt < 2; mt++) {
            int r1 = wm2*32 + mt*16 + group;
            #pragma unroll
            for (int nt = 0; nt < 4; nt++) {
                int col = wn2*32 + nt*8 + tg*2;
                *(float2*)&sx[r1*68 + col]     = make_float2(acc2[mt][nt][0], acc2[mt][nt][1]);
                *(float2*)&sx[(r1+8)*68 + col] = make_float2(acc2[mt][nt][2], acc2[mt][nt][3]);
            }
        }
        __syncthreads();

        // ---- 4. LN(sx) -> stA (tf32) ----
        #pragma unroll 1
        for (int rr = 0; rr < 16; rr += 4) {
            float xs0[4], xs1[4], s[4], q[4];
            #pragma unroll
            for (int u = 0; u < 4; u++) {
                int row = wid*16 + rr + u;
                xs0[u] = sx[row*68 + lane];
                xs1[u] = sx[row*68 + 32 + lane];
                s[u] = xs0[u] + xs1[u];
                q[u] = xs0[u]*xs0[u] + xs1[u]*xs1[u];
            }
            #pragma unroll
            for (int o = 16; o > 0; o >>= 1) {
                #pragma unroll
                for (int u = 0; u < 4; u++) {
                    s[u] += __shfl_xor_sync(0xffffffffu, s[u], o);
                    q[u] += __shfl_xor_sync(0xffffffffu, q[u], o);
                }
            }
            #pragma unroll
            for (int u = 0; u < 4; u++) {
                int row = wid*16 + rr + u;
                float mean = s[u]*(1.0f/64.0f);
                float var  = q[u]*(1.0f/64.0f) - mean*mean;
                float rs = rsqrtf(var + 1e-5f);
                stA[row*68 + lane]      = tf32r((xs0[u]-mean)*rs*gm0 + bt0);
                stA[row*68 + 32 + lane] = tf32r((xs1[u]-mean)*rs*gm1 + bt1);
            }
        }

        // ---- 5. transition: 8 chunks of 32 hidden, accumulate into acc2 ----
        #pragma unroll 1
        for (int hc = 0; hc < 8; hc++) {
            __syncthreads();  // LN/sx reads done; prev GEMM2 done with shh+weights
            #pragma unroll
            for (int u = 0; u < 2; u++) {
                float4 a4 = *(const float4*)&Wa[(size_t)wk*256 + hc*32 + wq*8 + u*4];
                float4 b4 = *(const float4*)&Wb[(size_t)wk*256 + hc*32 + wq*8 + u*4];
                int base = wk*72 + wq*16 + u*8;
                swab[base+0] = tf32r(a4.x); swab[base+1] = tf32r(b4.x);
                swab[base+2] = tf32r(a4.y); swab[base+3] = tf32r(b4.y);
                swab[base+4] = tf32r(a4.z); swab[base+5] = tf32r(b4.z);
                swab[base+6] = tf32r(a4.w); swab[base+7] = tf32r(b4.w);
                float4 o4 = *(const float4*)&Wo[(size_t)(hc*32 + wk2)*64 + wq2*8 + u*4];
                *(float4*)&swo[wk2*72 + wq2*8 + u*4] =
                    make_float4(tf32r(o4.x), tf32r(o4.y), tf32r(o4.z), tf32r(o4.w));
            }
            __syncthreads();
            // GEMM1: stA[128x64] @ wab[64x64-interleaved] (32 hidden)
            float acc1[4][2][4] = {};
            #pragma unroll
            for (int ks = 0; ks < 8; ks++) {
                uint32_t af[4][4], bf[2][2];
                #pragma unroll
                for (int mt = 0; mt < 4; mt++) {
                    const float* ap = stA + (wm*64 + mt*16 + group)*68 + ks*8 + tg;
                    af[mt][0] = __float_as_uint(ap[0]);
                    af[mt][1] = __float_as_uint(ap[8*68]);
                    af[mt][2] = __float_as_uint(ap[4]);
                    af[mt][3] = __float_as_uint(ap[8*68 + 4]);
                }
                #pragma unroll
                for (int nt = 0; nt < 2; nt++) {
                    const float* bp = swab + (ks*8 + tg)*72 + wn*16 + nt*8 + group;
                    bf[nt][0] = __float_as_uint(bp[0]);
                    bf[nt][1] = __float_as_uint(bp[4*72]);
                }
                #pragma unroll
                for (int mt = 0; mt < 4; mt++)
                    #pragma unroll
                    for (int nt = 0; nt < 2; nt++)
                        mma16n8k8(acc1[mt][nt], af[mt], bf[nt]);
            }
            // SiLU(a)*b in-register, h -> shh (32 cols)
            #pragma unroll
            for (int mt = 0; mt < 4; mt++) {
                int r1 = wm*64 + mt*16 + group;
                #pragma unroll
                for (int nt = 0; nt < 2; nt++) {
                    int hcol = wn*8 + nt*4 + tg;
                    float a0 = acc1[mt][nt][0], b0v = acc1[mt][nt][1];
                    float a1 = acc1[mt][nt][2], b1v = acc1[mt][nt][3];
                    float h0 = __fdividef(a0, 1.0f + __expf(-a0)) * b0v;
                    float h1 = __fdividef(a1, 1.0f + __expf(-a1)) * b1v;
                    shh[r1*36 + hcol]      = tf32r(h0);
                    shh[(r1+8)*36 + hcol]  = tf32r(h1);
                }
            }
            __syncthreads();
            // GEMM2: shh[128x32] @ swo[32x64] -> acc2
            #pragma unroll
            for (int ks = 0; ks < 4; ks++) {
                uint32_t af[2][4], bf[4][2];
                #pragma unroll
                for (int mt = 0; mt < 2; mt++) {
                    const float* ap = shh + (wm2*32 + mt*16 + group)*36 + ks*8 + tg;
                    af[mt][0] = __float_as_uint(ap[0]);
                    af[mt][1] = __float_as_uint(ap[8*36]);
                    af[mt][2] = __float_as_uint(ap[4]);
                    af[mt][3] = __float_as_uint(ap[8*36 + 4]);
                }
                #pragma unroll
                for (int nt = 0; nt < 4; nt++) {
                    const float* bp = swo + (ks*8 + tg)*72 + wn2*32 + nt*8 + group;
                    bf[nt][0] = __float_as_uint(bp[0]);
                    bf[nt][1] = __float_as_uint(bp[4*72]);
                }
                #pragma unroll
                for (int mt = 0; mt < 2; mt++)
                    #pragma unroll
                    for (int nt = 0; nt < 4; nt++)
                        mma16n8k8(acc2[mt][nt], af[mt], bf[nt]);
            }
        }
        // ---- 6. final store (residual already inside acc2) ----
        #pragma unroll
        for (int mt = 0; mt < 2; mt++) {
            int row = rbase + wm2*32 + mt*16 + group;
            #pragma unroll
            for (int nt = 0; nt < 4; nt++) {
                int col = wn2*32 + nt*8 + tg*2;
                *(float2*)&out[(size_t)row*64 + col] =
                    make_float2(acc2[mt][nt][0], acc2[mt][nt][1]);
                *(float2*)&out[(size_t)(row+8)*64 + col] =
                    make_float2(acc2[mt][nt][2], acc2[mt][nt][3]);
            }
        }
        __syncthreads();  // protect stA/shh before next tile overwrites
    }
}

// ============================================================
extern "C" void kernel_launch(void* const* d_in, const int* in_sizes, int n_in,
                              void* d_out, int out_size) {
    const float* m    = (const float*)d_in[0];
    const float* z    = (const float*)d_in[1];
    const float* lnmg = (const float*)d_in[2];
    const float* lnmb = (const float*)d_in[3];
    const float* Wmv  = (const float*)d_in[4];
    const float* lnzg = (const float*)d_in[5];
    const float* lnzb = (const float*)d_in[6];
    const float* Wz   = (const float*)d_in[7];
    const float* Wmg  = (const float*)d_in[8];
    const float* Wout = (const float*)d_in[9];
    const float* lntg = (const float*)d_in[10];
    const float* lntb = (const float*)d_in[11];
    const float* Wa   = (const float*)d_in[12];
    const float* Wb   = (const float*)d_in[13];
    const float* Wo   = (const float*)d_in[14];
    float* out = (float*)d_out;

    const int k1_smem = (128*68 + 64*136) * 4;       // 69,632 B
    cudaFuncSetAttribute(k1_mma, cudaFuncAttributeMaxDynamicSharedMemorySize, k1_smem);
    k1_mma<<<NROWS/128, 256, k1_smem>>>(m, lnmg, lnmb, Wmv, Wmg);

    k2a_bias<<<(N_DIM*N_DIM)/8, 256>>>(z, lnzg, lnzb, Wz);
    k2b_softmax<<<HH*N_DIM, 256>>>();

    const int k3_smem = (2*128*36 + 2*32*136) * 4;   // 71,680 B
    cudaFuncSetAttribute(k3_mma, cudaFuncAttributeMaxDynamicSharedMemorySize, k3_smem);
    k3_mma<<<dim3(PDIM/128, N_DIM/128, HH), 256, k3_smem>>>();

    const int k45_smem = (128*68 + 11520 + 64*72) * 4;   // 99,328 B
    cudaFuncSetAttribute(k45_mma, cudaFuncAttributeMaxDynamicSharedMemorySize, k45_smem);
    k45_mma<<<296, 256, k45_smem>>>(m, Wout, lntg, lntb, Wa, Wb, Wo, out);
    (void)in_sizes; (void)n_in; (void)out_size;
}

// round 14
// speedup vs baseline: 3.3202x; 1.1617x over previous
#include <cuda_runtime.h>
#include <math.h>
#include <stdint.h>

#define S_DIM 1024
#define N_DIM 512
#define CM 64
#define CC 8
#define CZ 128
#define HH 8
#define NROWS (S_DIM*N_DIM)        // 524288
#define PDIM (S_DIM*CC)            // 8192

// ---- scratch ----
__device__ float g_G [(size_t)NROWS*CM];                 // gate, [s*N+i][hc]
__device__ float g_Vt[(size_t)HH*N_DIM*PDIM];            // v^T,  [h][j][p=s*8+c]  (tf32-rounded)
__device__ float g_WV[(size_t)HH*N_DIM*PDIM];            // wv,   [h][i][p]
__device__ float g_Wsm[(size_t)HH*N_DIM*N_DIM];          // softmax w [h][i][j] (tf32-rounded)

__device__ __forceinline__ float tf32r(float x){
    uint32_t u; asm("cvt.rna.tf32.f32 %0, %1;" : "=r"(u) : "f"(x)); return __uint_as_float(u);
}
__device__ __forceinline__ void mma16n8k8(float* c, const uint32_t* a, const uint32_t* b){
    asm volatile("mma.sync.aligned.m16n8k8.row.col.f32.tf32.tf32.f32 "
        "{%0,%1,%2,%3}, {%4,%5,%6,%7}, {%8,%9}, {%0,%1,%2,%3};"
        : "+f"(c[0]), "+f"(c[1]), "+f"(c[2]), "+f"(c[3])
        : "r"(a[0]), "r"(a[1]), "r"(a[2]), "r"(a[3]), "r"(b[0]), "r"(b[1]));
}
__device__ __forceinline__ uint32_t smem_u32(const void* p){
    uint32_t a; asm("{ .reg .u64 t; cvta.to.shared.u64 t, %1; cvt.u32.u64 %0, t; }" : "=r"(a) : "l"(p)); return a;
}
__device__ __forceinline__ void cpasync16(uint32_t saddr, const void* g){
    asm volatile("cp.async.ca.shared.global [%0], [%1], 16;" :: "r"(saddr), "l"(g));
}

// ============================================================
// K1: per 128-row tile: LN -> st; GEMM st @ [Wmv|Wmg] (mma tf32);
//     sigmoid gate -> g_G; v half tf32 -> g_Vt. (unchanged, 2 CTAs/SM)
// ============================================================
__global__ void __launch_bounds__(256,2) k1_mma(
    const float* __restrict__ m, const float* __restrict__ lng, const float* __restrict__ lnb,
    const float* __restrict__ Wmv, const float* __restrict__ Wmg)
{
    extern __shared__ float sh1[];
    float* st   = sh1;               // [128][68]
    float* sW   = sh1 + 128*68;      // [64][136]
    float* sout = sh1;               // [128][132] overlays after GEMM

    int tid = threadIdx.x, wid = tid >> 5, lane = tid & 31;
    int group = lane >> 2, tg = lane & 3;
    int wm = wid >> 2, wn = wid & 3;
    float gm0 = lng[lane], gm1 = lng[lane+32];
    float bt0 = lnb[lane], bt1 = lnb[lane+32];

    int rbase = blockIdx.x*128;
    int ss = rbase >> 9, ii0 = rbase & 511;

    {
        int wk = tid >> 2, wq = tid & 3;
        #pragma unroll
        for (int u = 0; u < 4; u++) {
            float4 a4 = *(const float4*)&Wmv[(size_t)wk*64 + wq*16 + u*4];
            float4 b4 = *(const float4*)&Wmg[(size_t)wk*64 + wq*16 + u*4];
            *(float4*)&sW[wk*136 + wq*16 + u*4] =
                make_float4(tf32r(a4.x),tf32r(a4.y),tf32r(a4.z),tf32r(a4.w));
            *(float4*)&sW[wk*136 + 64 + wq*16 + u*4] =
                make_float4(tf32r(b4.x),tf32r(b4.y),tf32r(b4.z),tf32r(b4.w));
        }
    }
    #pragma unroll 1
    for (int rr = 0; rr < 16; rr += 4) {
        float xs0[4], xs1[4], s[4], q[4];
        #pragma unroll
        for (int u = 0; u < 4; u++) {
            int row = wid*16 + rr + u;
            xs0[u] = m[(size_t)(rbase+row)*64 + lane];
            xs1[u] = m[(size_t)(rbase+row)*64 + 32 + lane];
            s[u] = xs0[u] + xs1[u];
            q[u] = xs0[u]*xs0[u] + xs1[u]*xs1[u];
        }
        #pragma unroll
        for (int o = 16; o > 0; o >>= 1) {
            #pragma unroll
            for (int u = 0; u < 4; u++) {
                s[u] += __shfl_xor_sync(0xffffffffu, s[u], o);
                q[u] += __shfl_xor_sync(0xffffffffu, q[u], o);
            }
        }
        #pragma unroll
        for (int u = 0; u < 4; u++) {
            int row = wid*16 + rr + u;
            float mean = s[u]*(1.0f/64.0f);
            float var  = q[u]*(1.0f/64.0f) - mean*mean;
            float rs = rsqrtf(var + 1e-5f);
            st[row*68 + lane]      = tf32r((xs0[u]-mean)*rs*gm0 + bt0);
            st[row*68 + 32 + lane] = tf32r((xs1[u]-mean)*rs*gm1 + bt1);
        }
    }
    __syncthreads();

    float acc[4][4][4] = {};
    #pragma unroll
    for (int ks = 0; ks < 8; ks++) {
        uint32_t af[4][4], bf[4][2];
        #pragma unroll
        for (int mt = 0; mt < 4; mt++) {
            const float* ap = st + (wm*64 + mt*16 + group)*68 + ks*8 + tg;
            af[mt][0] = __float_as_uint(ap[0]);
            af[mt][1] = __float_as_uint(ap[8*68]);
            af[mt][2] = __float_as_uint(ap[4]);
            af[mt][3] = __float_as_uint(ap[8*68 + 4]);
        }
        #pragma unroll
        for (int nt = 0; nt < 4; nt++) {
            const float* bp = sW + (ks*8 + tg)*136 + wn*32 + nt*8 + group;
            bf[nt][0] = __float_as_uint(bp[0]);
            bf[nt][1] = __float_as_uint(bp[4*136]);
        }
        #pragma unroll
        for (int mt = 0; mt < 4; mt++)
            #pragma unroll
            for (int nt = 0; nt < 4; nt++)
                mma16n8k8(acc[mt][nt], af[mt], bf[nt]);
    }
    __syncthreads();
    #pragma unroll
    for (int mt = 0; mt < 4; mt++) {
        int r1 = wm*64 + mt*16 + group;
        #pragma unroll
        for (int nt = 0; nt < 4; nt++) {
            int col = wn*32 + nt*8 + tg*2;
            *(float2*)&sout[r1*132 + col]     = make_float2(acc[mt][nt][0], acc[mt][nt][1]);
            *(float2*)&sout[(r1+8)*132 + col] = make_float2(acc[mt][nt][2], acc[mt][nt][3]);
        }
    }
    __syncthreads();

    #pragma unroll
    for (int u = 0; u < 8; u++) {
        int flat = u*256 + tid;
        int row = flat >> 4, c4 = (flat & 15)*4;
        float4 v = *(const float4*)&sout[row*132 + 64 + c4];
        float4 gv;
        gv.x = __fdividef(1.0f, 1.0f + __expf(-v.x));
        gv.y = __fdividef(1.0f, 1.0f + __expf(-v.y));
        gv.z = __fdividef(1.0f, 1.0f + __expf(-v.z));
        gv.w = __fdividef(1.0f, 1.0f + __expf(-v.w));
        *(float4*)&g_G[(size_t)(rbase+row)*64 + c4] = gv;
    }
    #pragma unroll
    for (int u = 0; u < 4; u++) {
        int pidx = u*256 + tid;
        int h = pidx >> 7, row = pidx & 127;
        float4 v0 = *(const float4*)&sout[row*132 + h*8];
        float4 v1 = *(const float4*)&sout[row*132 + h*8 + 4];
        size_t off = ((size_t)h*N_DIM + ii0 + row)*PDIM + ss*8;
        *(float4*)&g_Vt[off]     = make_float4(tf32r(v0.x),tf32r(v0.y),tf32r(v0.z),tf32r(v0.w));
        *(float4*)&g_Vt[off + 4] = make_float4(tf32r(v1.x),tf32r(v1.y),tf32r(v1.z),tf32r(v1.w));
    }
}

// ============================================================
// K2a: bias[h][i][j] = LN(z[i,j,:]) @ W_z
// FIX: Wz staged in smem with stride 9 (coprime w/ 32) -> the
// lane*9+h gather is a bank permutation (1 wavefront, was 8-way
// line-replay against global Wz).
// ============================================================
__global__ void __launch_bounds__(256) k2a_bias(
    const float* __restrict__ z, const float* __restrict__ lng, const float* __restrict__ lnb,
    const float* __restrict__ Wz)
{
    __shared__ float sWz[CZ*9];
    int tid = threadIdx.x;
    for (int idx = tid; idx < CZ*8; idx += 256) {
        int k = idx >> 3, h = idx & 7;
        sWz[k*9 + h] = Wz[idx];
    }
    __syncthreads();

    int w = (blockIdx.x * 256 + tid) >> 5;
    int lane = tid & 31;
    if (w >= N_DIM*N_DIM) return;
    int i = w >> 9, j = w & 511;
    const float* zp = z + ((size_t)i*N_DIM + j)*CZ;
    float x0 = zp[lane], x1 = zp[lane+32], x2 = zp[lane+64], x3 = zp[lane+96];
    float s = x0+x1+x2+x3;
    float q = x0*x0 + x1*x1 + x2*x2 + x3*x3;
    #pragma unroll
    for (int o = 16; o > 0; o >>= 1) {
        s += __shfl_xor_sync(0xffffffffu, s, o);
        q += __shfl_xor_sync(0xffffffffu, q, o);
    }
    float mean = s * (1.0f/128.0f);
    float var  = q * (1.0f/128.0f) - mean*mean;
    float rs = rsqrtf(var + 1e-5f);
    float n0 = (x0-mean)*rs*lng[lane]    + lnb[lane];
    float n1 = (x1-mean)*rs*lng[lane+32] + lnb[lane+32];
    float n2 = (x2-mean)*rs*lng[lane+64] + lnb[lane+64];
    float n3 = (x3-mean)*rs*lng[lane+96] + lnb[lane+96];
    float ph[8];
    #pragma unroll
    for (int h = 0; h < 8; h++) {
        float pp = n0*sWz[lane*9+h] + n1*sWz[(lane+32)*9+h]
                 + n2*sWz[(lane+64)*9+h] + n3*sWz[(lane+96)*9+h];
        #pragma unroll
        for (int o = 16; o > 0; o >>= 1) pp += __shfl_xor_sync(0xffffffffu, pp, o);
        ph[h] = pp;
    }
    if (lane == 0) {
        #pragma unroll
        for (int h = 0; h < 8; h++)
            g_Wsm[(size_t)h*N_DIM*N_DIM + (size_t)i*N_DIM + j] = ph[h];
    }
}

// ============================================================
// K2b: softmax over j, tf32 output. Warp-shuffle reductions (2 barriers).
// ============================================================
__global__ void __launch_bounds__(256) k2b_softmax()
{
    float* p = g_Wsm + (size_t)blockIdx.x * N_DIM;
    __shared__ float red[8];
    __shared__ float red2[8];
    int t = threadIdx.x, lane = t & 31, w = t >> 5;
    float v0 = p[t], v1 = p[t+256];
    float mx = fmaxf(v0, v1);
    #pragma unroll
    for (int o = 16; o > 0; o >>= 1) mx = fmaxf(mx, __shfl_xor_sync(0xffffffffu, mx, o));
    if (lane == 0) red[w] = mx;
    __syncthreads();
    float m0 = red[0];
    #pragma unroll
    for (int i = 1; i < 8; i++) m0 = fmaxf(m0, red[i]);
    float e0 = __expf(v0-m0), e1 = __expf(v1-m0);
    float sm = e0+e1;
    #pragma unroll
    for (int o = 16; o > 0; o >>= 1) sm += __shfl_xor_sync(0xffffffffu, sm, o);
    if (lane == 0) red2[w] = sm;
    __syncthreads();
    float tot = red2[0]+red2[1]+red2[2]+red2[3]+red2[4]+red2[5]+red2[6]+red2[7];
    float inv = __fdividef(1.0f, tot);
    p[t] = tf32r(e0*inv); p[t+256] = tf32r(e1*inv);
}

// ============================================================
// K3: mma.sync tf32 GEMM per head; cp.async, 2 CTAs/SM. (unchanged)
// ============================================================
__global__ void __launch_bounds__(256,2) k3_mma()
{
    extern __shared__ float sh3[];
    float* sAs = sh3;                 // 2 x [128][36]
    float* sBs = sh3 + 2*128*36;      // 2 x [32][136]
    uint32_t aS = smem_u32(sAs), bS = smem_u32(sBs);

    int tid = threadIdx.x, wid = tid >> 5, lane = tid & 31;
    int group = lane >> 2, tg = lane & 3;
    int wm = wid >> 2, wn = wid & 3;
    int h  = blockIdx.z;
    int i0 = blockIdx.y * 128;
    int p0 = blockIdx.x * 128;
    const float* A = g_Wsm + (size_t)h*N_DIM*N_DIM;
    const float* B = g_Vt  + (size_t)h*N_DIM*PDIM;
    float*       C = g_WV  + (size_t)h*N_DIM*PDIM;

    int lr = tid >> 3, lc = (tid & 7)*4;

    #pragma unroll
    for (int u = 0; u < 4; u++)
        cpasync16(aS + (uint32_t)((lr + u*32)*36 + lc)*4, &A[(size_t)(i0+lr+u*32)*N_DIM + lc]);
    #pragma unroll
    for (int u = 0; u < 4; u++)
        cpasync16(bS + (uint32_t)(lr*136 + lc + u*32)*4, &B[(size_t)lr*PDIM + p0 + lc + u*32]);
    asm volatile("cp.async.commit_group;");

    float acc[4][4][4] = {};
    for (int it = 0; it < 16; it++) {
        if (it < 15) {
            int k0 = (it+1)*32;
            uint32_t ao = aS + (uint32_t)(((it+1)&1)*4608*4);
            uint32_t bo = bS + (uint32_t)(((it+1)&1)*4352*4);
            #pragma unroll
            for (int u = 0; u < 4; u++)
                cpasync16(ao + (uint32_t)((lr + u*32)*36 + lc)*4, &A[(size_t)(i0+lr+u*32)*N_DIM + k0 + lc]);
            #pragma unroll
            for (int u = 0; u < 4; u++)
                cpasync16(bo + (uint32_t)(lr*136 + lc + u*32)*4, &B[(size_t)(k0+lr)*PDIM + p0 + lc + u*32]);
            asm volatile("cp.async.commit_group;");
            asm volatile("cp.async.wait_group 1;");
        } else {
            asm volatile("cp.async.wait_group 0;");
        }
        __syncthreads();
        const float* as = sAs + (it&1)*4608;
        const float* bs = sBs + (it&1)*4352;
        #pragma unroll
        for (int ks = 0; ks < 4; ks++) {
            uint32_t af[4][4], bf[4][2];
            #pragma unroll
            for (int mt = 0; mt < 4; mt++) {
                const float* ap = as + (wm*64 + mt*16 + group)*36 + ks*8 + tg;
                af[mt][0] = __float_as_uint(ap[0]);
                af[mt][1] = __float_as_uint(ap[8*36]);
                af[mt][2] = __float_as_uint(ap[4]);
                af[mt][3] = __float_as_uint(ap[8*36 + 4]);
            }
            #pragma unroll
            for (int nt = 0; nt < 4; nt++) {
                const float* bp = bs + (ks*8 + tg)*136 + wn*32 + nt*8 + group;
                bf[nt][0] = __float_as_uint(bp[0]);
                bf[nt][1] = __float_as_uint(bp[4*136]);
            }
            #pragma unroll
            for (int mt = 0; mt < 4; mt++)
                #pragma unroll
                for (int nt = 0; nt < 4; nt++)
                    mma16n8k8(acc[mt][nt], af[mt], bf[nt]);
        }
        __syncthreads();
    }

    #pragma unroll
    for (int mt = 0; mt < 4; mt++) {
        int row = i0 + wm*64 + mt*16 + group;
        #pragma unroll
        for (int nt = 0; nt < 4; nt++) {
            int col = p0 + wn*32 + nt*8 + tg*2;
            *(float2*)&C[(size_t)row*PDIM + col]     = make_float2(acc[mt][nt][0], acc[mt][nt][1]);
            *(float2*)&C[(size_t)(row+8)*PDIM + col] = make_float2(acc[mt][nt][2], acc[mt][nt][3]);
        }
    }
}

// ============================================================
// K45: fused gate/out-projection + SwiGLU transition. (unchanged)
// ============================================================
__global__ void __launch_bounds__(256,2) k45_mma(
    const float* __restrict__ m, const float* __restrict__ Wout,
    const float* __restrict__ lng, const float* __restrict__ lnb,
    const float* __restrict__ Wa, const float* __restrict__ Wb, const float* __restrict__ Wo,
    float* __restrict__ out)
{
    extern __shared__ float sh45[];
    float* stA  = sh45;              // [128][68]
    float* ovl  = sh45 + 128*68;     // overlay region: 11520 floats
    float* sx   = ovl;               // [128][68]
    float* shh  = ovl;               // [128][36]
    float* swab = ovl + 128*36;      // [64][72]
    float* swo  = ovl + 128*36 + 64*72;  // [32][72]
    float* sWout= sh45 + 128*68 + 11520; // [64][72]

    int tid = threadIdx.x, wid = tid >> 5, lane = tid & 31;
    int group = lane >> 2, tg = lane & 3;
    int wm = wid >> 2, wn = wid & 3;
    int wm2 = wid >> 1, wn2 = wid & 1;
    float gm0 = lng[lane], gm1 = lng[lane+32];
    float bt0 = lnb[lane], bt1 = lnb[lane+32];
    int wk = tid >> 2, wq = tid & 3;
    int wk2 = tid >> 3, wq2 = tid & 7;

    #pragma unroll
    for (int u = 0; u < 4; u++) {
        float4 w4 = *(const float4*)&Wout[(size_t)wk*64 + wq*16 + u*4];
        *(float4*)&sWout[wk*72 + wq*16 + u*4] =
            make_float4(tf32r(w4.x),tf32r(w4.y),tf32r(w4.z),tf32r(w4.w));
    }

    for (int tile = blockIdx.x; tile < NROWS/128; tile += gridDim.x) {
        int rbase = tile*128;
        int ss = rbase >> 9, ii0 = rbase & 511;

        #pragma unroll
        for (int i = 0; i < 8; i++) {
            int flat4 = i*256 + tid;
            int row = flat4 >> 4, c4 = flat4 & 15;
            int k0 = c4*4; int hh = k0 >> 3, cc = k0 & 7;
            float4 g4 = *(const float4*)&g_G[(size_t)(rbase+row)*64 + k0];
            float4 w4 = *(const float4*)&g_WV[((size_t)hh*N_DIM + ii0 + row)*PDIM + ss*8 + cc];
            *(float4*)&stA[row*68 + k0] = make_float4(
                tf32r(g4.x*w4.x), tf32r(g4.y*w4.y), tf32r(g4.z*w4.z), tf32r(g4.w*w4.w));
        }
        __syncthreads();

        float acc2[2][4][4] = {};
        #pragma unroll
        for (int ks = 0; ks < 8; ks++) {
            uint32_t af[2][4], bf[4][2];
            #pragma unroll
            for (int mt = 0; mt < 2; mt++) {
                const float* ap = stA + (wm2*32 + mt*16 + group)*68 + ks*8 + tg;
                af[mt][0] = __float_as_uint(ap[0]);
                af[mt][1] = __float_as_uint(ap[8*68]);
                af[mt][2] = __float_as_uint(ap[4]);
                af[mt][3] = __float_as_uint(ap[8*68 + 4]);
            }
            #pragma unroll
            for (int nt = 0; nt < 4; nt++) {
                const float* bp = sWout + (ks*8 + tg)*72 + wn2*32 + nt*8 + group;
                bf[nt][0] = __float_as_uint(bp[0]);
                bf[nt][1] = __float_as_uint(bp[4*72]);
            }
            #pragma unroll
            for (int mt = 0; mt < 2; mt++)
                #pragma unroll
                for (int nt = 0; nt < 4; nt++)
                    mma16n8k8(acc2[mt][nt], af[mt], bf[nt]);
        }
        #pragma unroll
        for (int mt = 0; mt < 2; mt++) {
            int row = rbase + wm2*32 + mt*16 + group;
            #pragma unroll
            for (int nt = 0; nt < 4; nt++) {
                int col = wn2*32 + nt*8 + tg*2;
                float2 m0 = *(const float2*)&m[(size_t)row*64 + col];
                acc2[mt][nt][0] += m0.x; acc2[mt][nt][1] += m0.y;
                float2 m1 = *(const float2*)&m[(size_t)(row+8)*64 + col];
                acc2[mt][nt][2] += m1.x; acc2[mt][nt][3] += m1.y;
            }
        }

        #pragma unroll
        for (int mt = 0; mt < 2; mt++) {
            int r1 = wm2*32 + mt*16 + group;
            #pragma unroll
            for (int nt = 0; nt < 4; nt++) {
                int col = wn2*32 + nt*8 + tg*2;
                *(float2*)&sx[r1*68 + col]     = make_float2(acc2[mt][nt][0], acc2[mt][nt][1]);
                *(float2*)&sx[(r1+8)*68 + col] = make_float2(acc2[mt][nt][2], acc2[mt][nt][3]);
            }
        }
        __syncthreads();

        #pragma unroll 1
        for (int rr = 0; rr < 16; rr += 4) {
            float xs0[4], xs1[4], s[4], q[4];
            #pragma unroll
            for (int u = 0; u < 4; u++) {
                int row = wid*16 + rr + u;
                xs0[u] = sx[row*68 + lane];
                xs1[u] = sx[row*68 + 32 + lane];
                s[u] = xs0[u] + xs1[u];
                q[u] = xs0[u]*xs0[u] + xs1[u]*xs1[u];
            }
            #pragma unroll
            for (int o = 16; o > 0; o >>= 1) {
                #pragma unroll
                for (int u = 0; u < 4; u++) {
                    s[u] += __shfl_xor_sync(0xffffffffu, s[u], o);
                    q[u] += __shfl_xor_sync(0xffffffffu, q[u], o);
                }
            }
            #pragma unroll
            for (int u = 0; u < 4; u++) {
                int row = wid*16 + rr + u;
                float mean = s[u]*(1.0f/64.0f);
                float var  = q[u]*(1.0f/64.0f) - mean*mean;
                float rs = rsqrtf(var + 1e-5f);
                stA[row*68 + lane]      = tf32r((xs0[u]-mean)*rs*gm0 + bt0);
                stA[row*68 + 32 + lane] = tf32r((xs1[u]-mean)*rs*gm1 + bt1);
            }
        }

        #pragma unroll 1
        for (int hc = 0; hc < 8; hc++) {
            __syncthreads();
            #pragma unroll
            for (int u = 0; u < 2; u++) {
                float4 a4 = *(const float4*)&Wa[(size_t)wk*256 + hc*32 + wq*8 + u*4];
                float4 b4 = *(const float4*)&Wb[(size_t)wk*256 + hc*32 + wq*8 + u*4];
                int base = wk*72 + wq*16 + u*8;
                swab[base+0] = tf32r(a4.x); swab[base+1] = tf32r(b4.x);
                swab[base+2] = tf32r(a4.y); swab[base+3] = tf32r(b4.y);
                swab[base+4] = tf32r(a4.z); swab[base+5] = tf32r(b4.z);
                swab[base+6] = tf32r(a4.w); swab[base+7] = tf32r(b4.w);
                float4 o4 = *(const float4*)&Wo[(size_t)(hc*32 + wk2)*64 + wq2*8 + u*4];
                *(float4*)&swo[wk2*72 + wq2*8 + u*4] =
                    make_float4(tf32r(o4.x), tf32r(o4.y), tf32r(o4.z), tf32r(o4.w));
            }
            __syncthreads();
            float acc1[4][2][4] = {};
            #pragma unroll
            for (int ks = 0; ks < 8; ks++) {
                uint32_t af[4][4], bf[2][2];
                #pragma unroll
                for (int mt = 0; mt < 4; mt++) {
                    const float* ap = stA + (wm*64 + mt*16 + group)*68 + ks*8 + tg;
                    af[mt][0] = __float_as_uint(ap[0]);
                    af[mt][1] = __float_as_uint(ap[8*68]);
                    af[mt][2] = __float_as_uint(ap[4]);
                    af[mt][3] = __float_as_uint(ap[8*68 + 4]);
                }
                #pragma unroll
                for (int nt = 0; nt < 2; nt++) {
                    const float* bp = swab + (ks*8 + tg)*72 + wn*16 + nt*8 + group;
                    bf[nt][0] = __float_as_uint(bp[0]);
                    bf[nt][1] = __float_as_uint(bp[4*72]);
                }
                #pragma unroll
                for (int mt = 0; mt < 4; mt++)
                    #pragma unroll
                    for (int nt = 0; nt < 2; nt++)
                        mma16n8k8(acc1[mt][nt], af[mt], bf[nt]);
            }
            #pragma unroll
            for (int mt = 0; mt < 4; mt++) {
                int r1 = wm*64 + mt*16 + group;
                #pragma unroll
                for (int nt = 0; nt < 2; nt++) {
                    int hcol = wn*8 + nt*4 + tg;
                    float a0 = acc1[mt][nt][0], b0v = acc1[mt][nt][1];
                    float a1 = acc1[mt][nt][2], b1v = acc1[mt][nt][3];
                    float h0 = __fdividef(a0, 1.0f + __expf(-a0)) * b0v;
                    float h1 = __fdividef(a1, 1.0f + __expf(-a1)) * b1v;
                    shh[r1*36 + hcol]      = tf32r(h0);
                    shh[(r1+8)*36 + hcol]  = tf32r(h1);
                }
            }
            __syncthreads();
            #pragma unroll
            for (int ks = 0; ks < 4; ks++) {
                uint32_t af[2][4], bf[4][2];
                #pragma unroll
                for (int mt = 0; mt < 2; mt++) {
                    const float* ap = shh + (wm2*32 + mt*16 + group)*36 + ks*8 + tg;
                    af[mt][0] = __float_as_uint(ap[0]);
                    af[mt][1] = __float_as_uint(ap[8*36]);
                    af[mt][2] = __float_as_uint(ap[4]);
                    af[mt][3] = __float_as_uint(ap[8*36 + 4]);
                }
                #pragma unroll
                for (int nt = 0; nt < 4; nt++) {
                    const float* bp = swo + (ks*8 + tg)*72 + wn2*32 + nt*8 + group;
                    bf[nt][0] = __float_as_uint(bp[0]);
                    bf[nt][1] = __float_as_uint(bp[4*72]);
                }
                #pragma unroll
                for (int mt = 0; mt < 2; mt++)
                    #pragma unroll
                    for (int nt = 0; nt < 4; nt++)
                        mma16n8k8(acc2[mt][nt], af[mt], bf[nt]);
            }
        }
        #pragma unroll
        for (int mt = 0; mt < 2; mt++) {
            int row = rbase + wm2*32 + mt*16 + group;
            #pragma unroll
            for (int nt = 0; nt < 4; nt++) {
                int col = wn2*32 + nt*8 + tg*2;
                *(float2*)&out[(size_t)row*64 + col] =
                    make_float2(acc2[mt][nt][0], acc2[mt][nt][1]);
                *(float2*)&out[(size_t)(row+8)*64 + col] =
                    make_float2(acc2[mt][nt][2], acc2[mt][nt][3]);
            }
        }
        __syncthreads();
    }
}

// ============================================================
extern "C" void kernel_launch(void* const* d_in, const int* in_sizes, int n_in,
                              void* d_out, int out_size) {
    const float* m    = (const float*)d_in[0];
    const float* z    = (const float*)d_in[1];
    const float* lnmg = (const float*)d_in[2];
    const float* lnmb = (const float*)d_in[3];
    const float* Wmv  = (const float*)d_in[4];
    const float* lnzg = (const float*)d_in[5];
    const float* lnzb = (const float*)d_in[6];
    const float* Wz   = (const float*)d_in[7];
    const float* Wmg  = (const float*)d_in[8];
    const float* Wout = (const float*)d_in[9];
    const float* lntg = (const float*)d_in[10];
    const float* lntb = (const float*)d_in[11];
    const float* Wa   = (const float*)d_in[12];
    const float* Wb   = (const float*)d_in[13];
    const float* Wo   = (const float*)d_in[14];
    float* out = (float*)d_out;

    const int k1_smem = (128*68 + 64*136) * 4;       // 69,632 B
    cudaFuncSetAttribute(k1_mma, cudaFuncAttributeMaxDynamicSharedMemorySize, k1_smem);
    k1_mma<<<NROWS/128, 256, k1_smem>>>(m, lnmg, lnmb, Wmv, Wmg);

    k2a_bias<<<(N_DIM*N_DIM)/8, 256>>>(z, lnzg, lnzb, Wz);
    k2b_softmax<<<HH*N_DIM, 256>>>();

    const int k3_smem = (2*128*36 + 2*32*136) * 4;   // 71,680 B
    cudaFuncSetAttribute(k3_mma, cudaFuncAttributeMaxDynamicSharedMemorySize, k3_smem);
    k3_mma<<<dim3(PDIM/128, N_DIM/128, HH), 256, k3_smem>>>();

    const int k45_smem = (128*68 + 11520 + 64*72) * 4;   // 99,328 B
    cudaFuncSetAttribute(k45_mma, cudaFuncAttributeMaxDynamicSharedMemorySize, k45_smem);
    k45_mma<<<296, 256, k45_smem>>>(m, Wout, lntg, lntb, Wa, Wb, Wo, out);
    (void)in_sizes; (void)n_in; (void)out_size;
}